// round 12
// baseline (speedup 1.0000x reference)
#include <cuda_runtime.h>
#include <cuda_bf16.h>
#include <math.h>
#include <stdint.h>

#define L 2048
#define DM 512
#define NH 8
#define DH 64
#define MF 128
#define CHK 64
#define NC (L/CHK)   // 32

#define SCALE_QK 0.2102241038134287f
#define NC_COEF  0.08838834764831845f
#define KEPS 1e-4f
#define DEPS 1e-6f

// ---------------- device scratch ----------------
__device__ float g_hk[NH*L];
__device__ unsigned g_kstab;
__device__ float g_S[NH*NC*MF*DH];
__device__ float g_z[NH*NC*MF];

__device__ __nv_bfloat16 g_bhi_in[3][L*DM];
__device__ __nv_bfloat16 g_blo_in[3][L*DM];
__device__ __nv_bfloat16 g_bhi_w[4][DM*DM];
__device__ __nv_bfloat16 g_blo_w[4][DM*DM];
__device__ __nv_bfloat16 g_bhi_ctx[L*DM];
__device__ __nv_bfloat16 g_blo_ctx[L*DM];
__device__ __nv_bfloat16 g_qhi[L*DM];
__device__ __nv_bfloat16 g_qlo[L*DM];
__device__ __nv_bfloat16 g_khi[L*DM];
__device__ __nv_bfloat16 g_klo[L*DM];
__device__ __nv_bfloat16 g_rfthi[MF*DH];
__device__ __nv_bfloat16 g_rftlo[MF*DH];
__device__ __nv_bfloat16 g_pqhi[NH*L*MF];
__device__ __nv_bfloat16 g_pqlo[NH*L*MF];
__device__ __nv_bfloat16 g_pkhi[NH*L*MF];
__device__ __nv_bfloat16 g_pklo[NH*L*MF];
__device__ __nv_bfloat16 g_vhi[L*DM];
__device__ __nv_bfloat16 g_vlo[L*DM];
__device__ __nv_bfloat16 g_Shi[NH*NC*MF*DH];
__device__ __nv_bfloat16 g_Slo[NH*NC*MF*DH];

__device__ __forceinline__ unsigned enc_f(float f){
    unsigned u = __float_as_uint(f);
    return (u & 0x80000000u) ? ~u : (u | 0x80000000u);
}
__device__ __forceinline__ float dec_f(unsigned k){
    unsigned u = (k & 0x80000000u) ? (k ^ 0x80000000u) : ~k;
    return __uint_as_float(u);
}

__device__ __forceinline__ uint32_t smem_u32(const void* p) {
    uint32_t a;
    asm("{ .reg .u64 t; cvta.to.shared.u64 t, %1; cvt.u32.u64 %0, t; }" : "=r"(a) : "l"(p));
    return a;
}

#define CP_ASYNC16(sa, gp) asm volatile("cp.async.cg.shared.global [%0], [%1], 16;" :: "r"(sa), "l"(gp))
#define CP_COMMIT()        asm volatile("cp.async.commit_group;")
#define CP_WAIT1()         asm volatile("cp.async.wait_group 1;")
#define CP_WAIT0()         asm volatile("cp.async.wait_group 0;")

#define LDSM4(r0,r1,r2,r3,a) \
    asm volatile("ldmatrix.sync.aligned.m8n8.x4.shared.b16 {%0,%1,%2,%3}, [%4];" \
        : "=r"(r0),"=r"(r1),"=r"(r2),"=r"(r3) : "r"(a))
#define LDSM4T(r0,r1,r2,r3,a) \
    asm volatile("ldmatrix.sync.aligned.m8n8.x4.trans.shared.b16 {%0,%1,%2,%3}, [%4];" \
        : "=r"(r0),"=r"(r1),"=r"(r2),"=r"(r3) : "r"(a))

#define MMA16816(d,a,b0,b1) \
    asm volatile("mma.sync.aligned.m16n8k16.row.col.f32.bf16.bf16.f32 " \
        "{%0,%1,%2,%3},{%4,%5,%6,%7},{%8,%9},{%0,%1,%2,%3};" \
        : "+f"((d)[0]),"+f"((d)[1]),"+f"((d)[2]),"+f"((d)[3]) \
        : "r"((a)[0]),"r"((a)[1]),"r"((a)[2]),"r"((a)[3]),"r"(b0),"r"(b1))

__device__ __forceinline__ void split2(float x, float y, __nv_bfloat162& hv, __nv_bfloat162& lv){
    __nv_bfloat16 hx = __float2bfloat16(x);
    __nv_bfloat16 hy = __float2bfloat16(y);
    hv.x = hx; hv.y = hy;
    lv.x = __float2bfloat16(x - __bfloat162float(hx));
    lv.y = __float2bfloat16(y - __bfloat162float(hy));
}

// ---------------- fp32 -> (bf16 hi, bf16 lo) converter (+rf transpose, +kstab reset) ----------------
struct CV { const float* src[8]; __nv_bfloat16* hi[8]; __nv_bfloat16* lo[8]; int n[8]; int cnt; };
__global__ void convert_split(CV cv, const float* __restrict__ rf){
    int t = blockIdx.y;
    if (t == cv.cnt) {
        // rf transpose + split (only first few blocks do work) + kstab reset
        if (blockIdx.x == 0 && threadIdx.x == 0) g_kstab = 0u;
        int i0 = blockIdx.x * 1024 + threadIdx.x;
#pragma unroll
        for (int j = 0; j < 4; j++) {
            int i = i0 + j * 256;
            if (i < MF * DH) {
                int m = i >> 6, d = i & 63;
                float x = rf[(size_t)d * MF + m];
                __nv_bfloat16 h = __float2bfloat16(x);
                g_rfthi[(size_t)m * DH + d] = h;
                g_rftlo[(size_t)m * DH + d] = __float2bfloat16(x - __bfloat162float(h));
            }
        }
        return;
    }
    int n = cv.n[t];
    const float* s = cv.src[t];
    __nv_bfloat16* ph = cv.hi[t];
    __nv_bfloat16* pl = cv.lo[t];
    int i0 = blockIdx.x * 1024 + threadIdx.x;
#pragma unroll
    for (int j = 0; j < 4; j++) {
        int i = i0 + j * 256;
        if (i < n) {
            float x = s[i];
            __nv_bfloat16 h = __float2bfloat16(x);
            ph[i] = h;
            pl[i] = __float2bfloat16(x - __bfloat162float(h));
        }
    }
}

// ---------------- split-bf16 HMMA GEMM (tile 64x128, BK=32, 3-stage pipeline) ----------------
#define PITCH_B 80
#define A_TILE (64*PITCH_B)          // 5120
#define B_TILE (128*PITCH_B)         // 10240
#define STAGE_BYTES (2*A_TILE + 2*B_TILE)  // 30720
#define HG_SMEM (3*STAGE_BYTES)      // 92160
#define NKC 16

struct MMArgs {
    const __nv_bfloat16* Ahi[3]; const __nv_bfloat16* Alo[3];
    const __nv_bfloat16* Whi[3]; const __nv_bfloat16* Wlo[3];
    const float* bias[3]; float* C[3];
    __nv_bfloat16* Chi[3]; __nv_bfloat16* Clo[3];
    float alpha[3];
};

__global__ __launch_bounds__(256, 2) void hmma_gemm(MMArgs ga, int do_hk)
{
    extern __shared__ char smem[];
    uint32_t sb = smem_u32(smem);
    int tid = threadIdx.x;
    int lane = tid & 31, wid = tid >> 5;
    int warp_m = wid & 1, warp_n = wid >> 1;      // 2M x 4N, warp tile 32x32
    int z = blockIdx.z;
    int m0 = blockIdx.y * 64, n0 = blockIdx.x * 128;

    const __nv_bfloat16* Ahi = ga.Ahi[z] + (size_t)m0 * DM;
    const __nv_bfloat16* Alo = ga.Alo[z] + (size_t)m0 * DM;
    const __nv_bfloat16* Whi = ga.Whi[z] + (size_t)n0 * DM;
    const __nv_bfloat16* Wlo = ga.Wlo[z] + (size_t)n0 * DM;
    const float* bias = ga.bias[z];
    float alpha = ga.alpha[z];

    uint32_t a_off = (uint32_t)(warp_m*32 + (lane & 15)) * PITCH_B + (lane >> 4) * 16;
    uint32_t b_off = (uint32_t)(warp_n*32 + (lane & 7) + (lane >> 4) * 8) * PITCH_B + ((lane >> 3) & 1) * 16;

    // per-thread load slice (6 x 16B per stage)
    int li_t2[6], li_r[6], li_c[6], li_isA[6];
#pragma unroll
    for (int j = 0; j < 6; j++) {
        int idx = tid + j * 256;
        if (idx < 512) {
            li_isA[j] = 1; li_t2[j] = idx >> 8;
            int w = idx & 255;
            li_r[j] = w >> 2; li_c[j] = w & 3;
        } else {
            li_isA[j] = 0;
            int w = idx - 512;
            li_t2[j] = w >> 9; w &= 511;
            li_r[j] = w >> 2; li_c[j] = w & 3;
        }
    }

    float acc[2][4][4];
#pragma unroll
    for (int i = 0; i < 2; i++)
#pragma unroll
        for (int j = 0; j < 4; j++)
#pragma unroll
            for (int r = 0; r < 4; r++) acc[i][j][r] = 0.f;

    // prologue: stages for kc=0,1
#pragma unroll
    for (int s = 0; s < 2; s++) {
        uint32_t stb = sb + s * STAGE_BYTES;
        int k0 = s * 32;
#pragma unroll
        for (int j = 0; j < 6; j++) {
            const __nv_bfloat16* gp = li_isA[j]
                ? ((li_t2[j] ? Alo : Ahi) + (size_t)li_r[j] * DM + k0 + li_c[j]*8)
                : ((li_t2[j] ? Wlo : Whi) + (size_t)li_r[j] * DM + k0 + li_c[j]*8);
            uint32_t sp = stb + (li_isA[j] ? li_t2[j]*A_TILE : 2*A_TILE + li_t2[j]*B_TILE)
                        + (uint32_t)li_r[j] * PITCH_B + li_c[j] * 16;
            CP_ASYNC16(sp, gp);
        }
        CP_COMMIT();
    }

    for (int kc = 0; kc < NKC; kc++) {
        CP_WAIT1();
        __syncthreads();

        // issue stage kc+2 (buffer last read at kc-1; sync above guarantees drained)
        if (kc + 2 < NKC) {
            int k0 = (kc + 2) * 32;
            uint32_t stb = sb + ((kc + 2) % 3) * STAGE_BYTES;
#pragma unroll
            for (int j = 0; j < 6; j++) {
                const __nv_bfloat16* gp = li_isA[j]
                    ? ((li_t2[j] ? Alo : Ahi) + (size_t)li_r[j] * DM + k0 + li_c[j]*8)
                    : ((li_t2[j] ? Wlo : Whi) + (size_t)li_r[j] * DM + k0 + li_c[j]*8);
                uint32_t sp = stb + (li_isA[j] ? li_t2[j]*A_TILE : 2*A_TILE + li_t2[j]*B_TILE)
                            + (uint32_t)li_r[j] * PITCH_B + li_c[j] * 16;
                CP_ASYNC16(sp, gp);
            }
        }
        CP_COMMIT();

        uint32_t st = sb + (kc % 3) * STAGE_BYTES;
        uint32_t sAhi = st + a_off;
        uint32_t sAlo = st + A_TILE + a_off;
        uint32_t sBhi = st + 2*A_TILE + b_off;
        uint32_t sBlo = st + 2*A_TILE + B_TILE + b_off;

#pragma unroll
        for (int ks = 0; ks < 2; ks++) {
            uint32_t ah[2][4], al[2][4], bh[2][4], bl[2][4];
#pragma unroll
            for (int mi = 0; mi < 2; mi++) {
                LDSM4(ah[mi][0], ah[mi][1], ah[mi][2], ah[mi][3], sAhi + mi*16*PITCH_B + ks*32);
                LDSM4(al[mi][0], al[mi][1], al[mi][2], al[mi][3], sAlo + mi*16*PITCH_B + ks*32);
            }
#pragma unroll
            for (int nb = 0; nb < 2; nb++) {
                LDSM4(bh[nb][0], bh[nb][1], bh[nb][2], bh[nb][3], sBhi + nb*16*PITCH_B + ks*32);
                LDSM4(bl[nb][0], bl[nb][1], bl[nb][2], bl[nb][3], sBlo + nb*16*PITCH_B + ks*32);
            }
#pragma unroll
            for (int mi = 0; mi < 2; mi++)
#pragma unroll
                for (int nb = 0; nb < 2; nb++) {
                    MMA16816(acc[mi][nb*2+0], ah[mi], bh[nb][0], bh[nb][1]);
                    MMA16816(acc[mi][nb*2+1], ah[mi], bh[nb][2], bh[nb][3]);
                    MMA16816(acc[mi][nb*2+0], ah[mi], bl[nb][0], bl[nb][1]);
                    MMA16816(acc[mi][nb*2+1], ah[mi], bl[nb][2], bl[nb][3]);
                    MMA16816(acc[mi][nb*2+0], al[mi], bh[nb][0], bh[nb][1]);
                    MMA16816(acc[mi][nb*2+1], al[mi], bh[nb][2], bh[nb][3]);
                }
        }
    }
    __syncthreads();   // protect epilogue smem reuse (stage 0 aliases pr/red)

    int g = lane >> 2, t = lane & 3;
    __nv_bfloat16* Chi = ga.Chi[z];
    float* C = ga.C[z];
    bool hk = (do_hk && z == 1);
    float* pr = (float*)smem;
    float* red = (float*)smem + 256;

#pragma unroll
    for (int mi = 0; mi < 2; mi++) {
#pragma unroll
        for (int half = 0; half < 2; half++) {
            int row = m0 + warp_m*32 + mi*16 + g + half*8;
            float ss = 0.f;
#pragma unroll
            for (int nj = 0; nj < 4; nj++) {
                int col = n0 + warp_n*32 + nj*8 + t*2;
                float2 bb = *(const float2*)(bias + col);
                float ox = alpha * (acc[mi][nj][half*2+0] + bb.x);
                float oy = alpha * (acc[mi][nj][half*2+1] + bb.y);
                ss += ox*ox + oy*oy;
                if (C) *(float2*)(C + (size_t)row * DM + col) = make_float2(ox, oy);
                if (Chi) {
                    __nv_bfloat162 hv, lv;
                    split2(ox, oy, hv, lv);
                    *(__nv_bfloat162*)(Chi + (size_t)row * DM + col) = hv;
                    *(__nv_bfloat162*)(ga.Clo[z] + (size_t)row * DM + col) = lv;
                }
            }
            if (hk) {
                ss += __shfl_xor_sync(0xffffffffu, ss, 1);
                ss += __shfl_xor_sync(0xffffffffu, ss, 2);
                if (t == 0) pr[(warp_m*32 + mi*16 + g + half*8)*4 + warp_n] = ss;
            }
        }
    }
    if (hk) {
        __syncthreads();
        float hmax = -1e30f;
        if (tid < 128) {
            int row = tid >> 1, hd2 = tid & 1;
            float ss = pr[row*4 + hd2*2] + pr[row*4 + hd2*2 + 1];
            float hv = -0.5f * ss;
            g_hk[(size_t)((n0 >> 6) + hd2) * L + m0 + row] = hv;
            hmax = hv;
        }
#pragma unroll
        for (int o = 16; o; o >>= 1) hmax = fmaxf(hmax, __shfl_xor_sync(0xffffffffu, hmax, o));
        if (lane == 0) red[wid] = hmax;
        __syncthreads();
        if (tid == 0) {
            float mx = red[0];
#pragma unroll
            for (int i = 1; i < 8; i++) mx = fmaxf(mx, red[i]);
            atomicMax(&g_kstab, enc_f(mx));
        }
    }
}

// ---------------- rf projection + featurize (HMMA split-bf16) ----------------
#define PITCH2 144
#define TILE2 (128*PITCH2)
#define RF_SMEM (4*TILE2)

__global__ __launch_bounds__(256) void rf_proj_hmma()
{
    extern __shared__ char smem[];
    uint32_t sb = smem_u32(smem);
    int tid = threadIdx.x;
    int lane = tid & 31, wid = tid >> 5;
    int warp_m = wid & 1, warp_n = wid >> 1;
    int z = blockIdx.z;
    int h = z & 7;
    bool isq = z < 8;
    int m0 = blockIdx.y * 128;

    const __nv_bfloat16* Ahi = (isq ? g_qhi : g_khi) + (size_t)m0 * DM + h * DH;
    const __nv_bfloat16* Alo = (isq ? g_qlo : g_klo) + (size_t)m0 * DM + h * DH;

#pragma unroll
    for (int j = 0; j < 16; j++) {
        int idx = tid + j * 256;
        int tile = idx >> 10;
        int w = idx & 1023;
        int r = w >> 3, c = w & 7;
        const __nv_bfloat16* gp =
            (tile == 0) ? (Ahi + (size_t)r * DM + c*8) :
            (tile == 1) ? (Alo + (size_t)r * DM + c*8) :
            (tile == 2) ? (g_rfthi + (size_t)r * DH + c*8) :
                          (g_rftlo + (size_t)r * DH + c*8);
        uint32_t sp = sb + tile * TILE2 + (uint32_t)r * PITCH2 + c * 16;
        CP_ASYNC16(sp, gp);
    }
    CP_COMMIT();
    CP_WAIT0();
    __syncthreads();

    uint32_t a_off = (uint32_t)(warp_m*64 + (lane & 15)) * PITCH2 + (lane >> 4) * 16;
    uint32_t b_off = (uint32_t)(warp_n*32 + (lane & 7) + (lane >> 4) * 8) * PITCH2 + ((lane >> 3) & 1) * 16;
    uint32_t sAhi = sb + a_off;
    uint32_t sAlo = sb + TILE2 + a_off;
    uint32_t sBhi = sb + 2*TILE2 + b_off;
    uint32_t sBlo = sb + 3*TILE2 + b_off;

    float acc[4][4][4];
#pragma unroll
    for (int i = 0; i < 4; i++)
#pragma unroll
        for (int j = 0; j < 4; j++)
#pragma unroll
            for (int r = 0; r < 4; r++) acc[i][j][r] = 0.f;

#pragma unroll
    for (int ks = 0; ks < 4; ks++) {
        uint32_t ah[4][4], al[4][4], bh[2][4], bl[2][4];
#pragma unroll
        for (int mi = 0; mi < 4; mi++) {
            LDSM4(ah[mi][0], ah[mi][1], ah[mi][2], ah[mi][3], sAhi + mi*16*PITCH2 + ks*32);
            LDSM4(al[mi][0], al[mi][1], al[mi][2], al[mi][3], sAlo + mi*16*PITCH2 + ks*32);
        }
#pragma unroll
        for (int nb = 0; nb < 2; nb++) {
            LDSM4(bh[nb][0], bh[nb][1], bh[nb][2], bh[nb][3], sBhi + nb*16*PITCH2 + ks*32);
            LDSM4(bl[nb][0], bl[nb][1], bl[nb][2], bl[nb][3], sBlo + nb*16*PITCH2 + ks*32);
        }
#pragma unroll
        for (int mi = 0; mi < 4; mi++)
#pragma unroll
            for (int nb = 0; nb < 2; nb++) {
                MMA16816(acc[mi][nb*2+0], ah[mi], bh[nb][0], bh[nb][1]);
                MMA16816(acc[mi][nb*2+1], ah[mi], bh[nb][2], bh[nb][3]);
                MMA16816(acc[mi][nb*2+0], ah[mi], bl[nb][0], bl[nb][1]);
                MMA16816(acc[mi][nb*2+1], ah[mi], bl[nb][2], bl[nb][3]);
                MMA16816(acc[mi][nb*2+0], al[mi], bh[nb][0], bh[nb][1]);
                MMA16816(acc[mi][nb*2+1], al[mi], bh[nb][2], bh[nb][3]);
            }
    }

    float kst = isq ? 0.f : dec_f(g_kstab);
    int g = lane >> 2, t = lane & 3;
    __nv_bfloat16* Ph = (isq ? g_pqhi : g_pkhi) + (size_t)h * L * MF;
    __nv_bfloat16* Pl = (isq ? g_pqlo : g_pklo) + (size_t)h * L * MF;
#pragma unroll
    for (int mi = 0; mi < 4; mi++) {
#pragma unroll
        for (int half = 0; half < 2; half++) {
            int row = m0 + warp_m*64 + mi*16 + g + half*8;
            float off = isq ? 0.f : (g_hk[(size_t)h * L + row] - kst);
#pragma unroll
            for (int nj = 0; nj < 4; nj++) {
                int col = warp_n*32 + nj*8 + t*2;
                float ox = NC_COEF * (__expf(acc[mi][nj][half*2+0] + off) + KEPS);
                float oy = NC_COEF * (__expf(acc[mi][nj][half*2+1] + off) + KEPS);
                __nv_bfloat162 hv, lv;
                split2(ox, oy, hv, lv);
                *(__nv_bfloat162*)(Ph + (size_t)row * MF + col) = hv;
                *(__nv_bfloat162*)(Pl + (size_t)row * MF + col) = lv;
            }
        }
    }
}

// ---------------- chunk_state via HMMA ----------------
#define CSP_K 272
#define CSP_V 208
#define CS_KH 0
#define CS_KL (CS_KH + 64*CSP_K)
#define CS_VH (CS_KL + 64*CSP_K)
#define CS_VL (CS_VH + 64*CSP_V)
#define CS_TOTAL (CS_VL + 64*CSP_V)

__global__ __launch_bounds__(256) void chunk_state_hmma(){
    extern __shared__ char smc[];
    uint32_t sb = smem_u32(smc);
    int c = blockIdx.x, h = blockIdx.y;
    int tid = threadIdx.x, lane = tid & 31, wid = tid >> 5;
    int warp_m = wid >> 1, warp_n = wid & 1;
    int l0 = c * CHK;

    const __nv_bfloat16* kh = g_pkhi + ((size_t)h * L + l0) * MF;
    const __nv_bfloat16* kl = g_pklo + ((size_t)h * L + l0) * MF;
    for (int i = tid; i < 1024; i += 256) {
        int r = i >> 4, cc = i & 15;
        CP_ASYNC16(sb + CS_KH + (uint32_t)r*CSP_K + cc*16, kh + (size_t)r*MF + cc*8);
        CP_ASYNC16(sb + CS_KL + (uint32_t)r*CSP_K + cc*16, kl + (size_t)r*MF + cc*8);
    }
    for (int i = tid; i < 512; i += 256) {
        int r = i >> 3, cc = i & 7;
        CP_ASYNC16(sb + CS_VH + (uint32_t)r*CSP_V + cc*16, g_vhi + (size_t)(l0+r)*DM + h*DH + cc*8);
        CP_ASYNC16(sb + CS_VL + (uint32_t)r*CSP_V + cc*16, g_vlo + (size_t)(l0+r)*DM + h*DH + cc*8);
    }
    if (tid < 64) {
        uint4 zz = make_uint4(0u,0u,0u,0u);
#pragma unroll
        for (int q = 0; q < 4; q++) {
            *(uint4*)(smc + CS_VH + tid*CSP_V + 128 + q*16) = zz;
            *(uint4*)(smc + CS_VL + tid*CSP_V + 128 + q*16) = zz;
        }
        *((__nv_bfloat16*)(smc + CS_VH + tid*CSP_V) + 64) = __float2bfloat16(1.0f);
    }
    CP_COMMIT(); CP_WAIT0();
    __syncthreads();

    float acc[2][6][4];
#pragma unroll
    for (int i = 0; i < 2; i++)
#pragma unroll
        for (int j = 0; j < 6; j++)
#pragma unroll
            for (int r = 0; r < 4; r++) acc[i][j][r] = 0.f;

#pragma unroll
    for (int ks = 0; ks < 4; ks++) {
        uint32_t ah[2][4], al[2][4], bh[3][4], bl[3][4];
#pragma unroll
        for (int mi = 0; mi < 2; mi++) {
            uint32_t aoff = (uint32_t)(ks*16 + ((lane >> 4) & 1)*8 + (lane & 7)) * CSP_K
                          + (uint32_t)(warp_m*32 + mi*16 + ((lane >> 3) & 1)*8) * 2;
            LDSM4T(ah[mi][0], ah[mi][1], ah[mi][2], ah[mi][3], sb + CS_KH + aoff);
            LDSM4T(al[mi][0], al[mi][1], al[mi][2], al[mi][3], sb + CS_KL + aoff);
        }
#pragma unroll
        for (int nb = 0; nb < 3; nb++) {
            uint32_t boff = (uint32_t)(ks*16 + (lane & 15)) * CSP_V
                          + (uint32_t)(warp_n*48 + nb*16 + (lane >> 4)*8) * 2;
            LDSM4T(bh[nb][0], bh[nb][1], bh[nb][2], bh[nb][3], sb + CS_VH + boff);
            LDSM4T(bl[nb][0], bl[nb][1], bl[nb][2], bl[nb][3], sb + CS_VL + boff);
        }
#pragma unroll
        for (int mi = 0; mi < 2; mi++)
#pragma unroll
            for (int nb = 0; nb < 3; nb++) {
                MMA16816(acc[mi][nb*2+0], ah[mi], bh[nb][0], bh[nb][1]);
                MMA16816(acc[mi][nb*2+1], ah[mi], bh[nb][2], bh[nb][3]);
                MMA16816(acc[mi][nb*2+0], ah[mi], bl[nb][0], bl[nb][1]);
                MMA16816(acc[mi][nb*2+1], ah[mi], bl[nb][2], bl[nb][3]);
                MMA16816(acc[mi][nb*2+0], al[mi], bh[nb][0], bh[nb][1]);
                MMA16816(acc[mi][nb*2+1], al[mi], bh[nb][2], bh[nb][3]);
            }
    }

    int g = lane >> 2, t = lane & 3;
    float* Sdst = g_S + (size_t)(h*NC + c) * MF * DH;
    float* zdst = g_z + (size_t)(h*NC + c) * MF;
#pragma unroll
    for (int mi = 0; mi < 2; mi++) {
#pragma unroll
        for (int half = 0; half < 2; half++) {
            int m = warp_m*32 + mi*16 + g + half*8;
#pragma unroll
            for (int nj = 0; nj < 6; nj++) {
                int col = warp_n*48 + nj*8 + t*2;
                float x = acc[mi][nj][half*2+0];
                float y = acc[mi][nj][half*2+1];
                if (col < 64) {
                    *(float2*)(Sdst + (size_t)m * DH + col) = make_float2(x, y);
                } else if (col == 64) {
                    zdst[m] = x;
                }
            }
        }
    }
}

// ---------------- exclusive prefix over chunks (batched loads, MLP=32) ----------------
__global__ void prefix_scan(){
    int h = blockIdx.y;
    int idx = blockIdx.x * 256 + threadIdx.x;
    if (idx < MF * DH) {
        const float* p = g_S + (size_t)h * NC * MF * DH + idx;
        float v[NC];
#pragma unroll
        for (int c = 0; c < NC; c++) v[c] = p[(size_t)c * MF * DH];
        __nv_bfloat16* ph = g_Shi + (size_t)h * NC * MF * DH + idx;
        __nv_bfloat16* pl = g_Slo + (size_t)h * NC * MF * DH + idx;
        float prev = 0.f;
#pragma unroll
        for (int c = 0; c < NC; c++) {
            __nv_bfloat16 hh = __float2bfloat16(prev);
            ph[(size_t)c * MF * DH] = hh;
            pl[(size_t)c * MF * DH] = __float2bfloat16(prev - __bfloat162float(hh));
            prev += v[c];
        }
    } else if (idx < MF * DH + MF) {
        int m = idx - MF * DH;
        float* p = g_z + (size_t)h * NC * MF + m;
        float v[NC];
#pragma unroll
        for (int c = 0; c < NC; c++) v[c] = p[c * MF];
        float prev = 0.f;
#pragma unroll
        for (int c = 0; c < NC; c++) {
            p[c * MF] = prev;
            prev += v[c];
        }
    }
}

// ---------------- chunk_out via HMMA ----------------
#define PQ 272
#define PV 144
#define CO_QH 0
#define CO_QL (CO_QH + 64*PQ)
#define CO_KH (CO_QL + 64*PQ)
#define CO_KL (CO_KH + 64*PQ)
#define CO_VH (CO_KL + 64*PQ)
#define CO_VL (CO_VH + 64*PV)
#define CO_SH (CO_VL + 64*PV)
#define CO_SL (CO_SH + 128*PV)
#define CO_AH (CO_SL + 128*PV)
#define CO_AL (CO_AH + 64*PV)
#define CO_ZB (CO_AL + 64*PV)
#define CO_PR (CO_ZB + 512)
#define CO_RS (CO_PR + 64*4*4)
#define CO_TOTAL (CO_RS + 256)

__global__ __launch_bounds__(256) void chunk_out_hmma(){
    extern __shared__ char smc[];
    uint32_t sb = smem_u32(smc);
    int c = blockIdx.x, h = blockIdx.y;
    int tid = threadIdx.x, lane = tid & 31, wid = tid >> 5;
    int warp_m = wid & 1, warp_n = wid >> 1;
    int l0 = c * CHK;

    {
        const __nv_bfloat16* pqh = g_pqhi + ((size_t)h * L + l0) * MF;
        const __nv_bfloat16* pql = g_pqlo + ((size_t)h * L + l0) * MF;
        const __nv_bfloat16* pkh = g_pkhi + ((size_t)h * L + l0) * MF;
        const __nv_bfloat16* pkl = g_pklo + ((size_t)h * L + l0) * MF;
        for (int i = tid; i < 1024; i += 256) {
            int r = i >> 4, cc = i & 15;
            CP_ASYNC16(sb + CO_QH + r*PQ + cc*16, pqh + (size_t)r*MF + cc*8);
            CP_ASYNC16(sb + CO_QL + r*PQ + cc*16, pql + (size_t)r*MF + cc*8);
            CP_ASYNC16(sb + CO_KH + r*PQ + cc*16, pkh + (size_t)r*MF + cc*8);
            CP_ASYNC16(sb + CO_KL + r*PQ + cc*16, pkl + (size_t)r*MF + cc*8);
        }
        for (int i = tid; i < 512; i += 256) {
            int r = i >> 3, cc = i & 7;
            CP_ASYNC16(sb + CO_VH + r*PV + cc*16, g_vhi + (size_t)(l0 + r)*DM + h*DH + cc*8);
            CP_ASYNC16(sb + CO_VL + r*PV + cc*16, g_vlo + (size_t)(l0 + r)*DM + h*DH + cc*8);
        }
        const __nv_bfloat16* sh = g_Shi + (size_t)(h*NC + c)*MF*DH;
        const __nv_bfloat16* sl = g_Slo + (size_t)(h*NC + c)*MF*DH;
        for (int i = tid; i < 1024; i += 256) {
            int r = i >> 3, cc = i & 7;
            CP_ASYNC16(sb + CO_SH + r*PV + cc*16, sh + (size_t)r*DH + cc*8);
            CP_ASYNC16(sb + CO_SL + r*PV + cc*16, sl + (size_t)r*DH + cc*8);
        }
        if (tid < 32) CP_ASYNC16(sb + CO_ZB + tid*16, g_z + (size_t)(h*NC + c)*MF + tid*4);
        CP_COMMIT(); CP_WAIT0();
    }
    __syncthreads();

    uint32_t a_off = (uint32_t)(warp_m*32 + (lane & 15)) * PQ + (lane >> 4) * 16;
    uint32_t b_off = (uint32_t)(warp_n*16 + (lane & 7) + (lane >> 4) * 8) * PQ + ((lane >> 3) & 1) * 16;

    float acc[2][2][4];
#pragma unroll
    for (int i = 0; i < 2; i++)
#pragma unroll
        for (int j = 0; j < 2; j++)
#pragma unroll
            for (int r = 0; r < 4; r++) acc[i][j][r] = 0.f;

#pragma unroll
    for (int ks = 0; ks < 8; ks++) {
        uint32_t ah[2][4], al[2][4], bh[4], bl[4];
#pragma unroll
        for (int mi = 0; mi < 2; mi++) {
            LDSM4(ah[mi][0], ah[mi][1], ah[mi][2], ah[mi][3], sb + CO_QH + a_off + mi*16*PQ + ks*32);
            LDSM4(al[mi][0], al[mi][1], al[mi][2], al[mi][3], sb + CO_QL + a_off + mi*16*PQ + ks*32);
        }
        LDSM4(bh[0], bh[1], bh[2], bh[3], sb + CO_KH + b_off + ks*32);
        LDSM4(bl[0], bl[1], bl[2], bl[3], sb + CO_KL + b_off + ks*32);
#pragma unroll
        for (int mi = 0; mi < 2; mi++) {
            MMA16816(acc[mi][0], ah[mi], bh[0], bh[1]);
            MMA16816(acc[mi][1], ah[mi], bh[2], bh[3]);
            MMA16816(acc[mi][0], ah[mi], bl[0], bl[1]);
            MMA16816(acc[mi][1], ah[mi], bl[2], bl[3]);
            MMA16816(acc[mi][0], al[mi], bh[0], bh[1]);
            MMA16816(acc[mi][1], al[mi], bh[2], bh[3]);
        }
    }

    int g = lane >> 2, t = lane & 3;
    float* pr = (float*)(smc + CO_PR);
#pragma unroll
    for (int mi = 0; mi < 2; mi++) {
#pragma unroll
        for (int half = 0; half < 2; half++) {
            int row = warp_m*32 + mi*16 + g + half*8;
            float rsum = 0.f;
#pragma unroll
            for (int nj = 0; nj < 2; nj++) {
                int col = warp_n*16 + nj*8 + t*2;
                float x = (col     <= row) ? acc[mi][nj][half*2+0] : 0.f;
                float y = (col + 1 <= row) ? acc[mi][nj][half*2+1] : 0.f;
                rsum += x + y;
                __nv_bfloat162 hv, lv;
                split2(x, y, hv, lv);
                *(__nv_bfloat162*)(smc + CO_AH + row*PV + col*2) = hv;
                *(__nv_bfloat162*)(smc + CO_AL + row*PV + col*2) = lv;
            }
            rsum += __shfl_xor_sync(0xffffffffu, rsum, 1);
            rsum += __shfl_xor_sync(0xffffffffu, rsum, 2);
            if (t == 0) pr[row*4 + warp_n] = rsum;
        }
    }
    __syncthreads();

    if (tid < 64) {
        float s = pr[tid*4+0] + pr[tid*4+1] + pr[tid*4+2] + pr[tid*4+3];
        const float* zf = (const float*)(smc + CO_ZB);
#pragma unroll 8
        for (int m2 = 0; m2 < 64; m2++) {
            __nv_bfloat162 qh2 = *(const __nv_bfloat162*)(smc + CO_QH + tid*PQ + m2*4);
            __nv_bfloat162 ql2 = *(const __nv_bfloat162*)(smc + CO_QL + tid*PQ + m2*4);
            float2 z2 = *(const float2*)(zf + m2*2);
            s += (__bfloat162float(qh2.x) + __bfloat162float(ql2.x)) * z2.x
               + (__bfloat162float(qh2.y) + __bfloat162float(ql2.y)) * z2.y;
        }
        ((float*)(smc + CO_RS))[tid] = s + DEPS;
    }

    float o[2][2][4];
#pragma unroll
    for (int i = 0; i < 2; i++)
#pragma unroll
        for (int j = 0; j < 2; j++)
#pragma unroll
            for (int r = 0; r < 4; r++) o[i][j][r] = 0.f;

    uint32_t a2_off = (uint32_t)(warp_m*32 + (lane & 15)) * PV + (lane >> 4) * 16;
    uint32_t bt_off = (uint32_t)(lane & 15) * PV + (warp_n*16 + (lane >> 4) * 8) * 2;

#pragma unroll
    for (int ks = 0; ks < 4; ks++) {
        uint32_t ah[2][4], al[2][4], bh[4], bl[4];
#pragma unroll
        for (int mi = 0; mi < 2; mi++) {
            LDSM4(ah[mi][0], ah[mi][1], ah[mi][2], ah[mi][3], sb + CO_AH + a2_off + mi*16*PV + ks*32);
            LDSM4(al[mi][0], al[mi][1], al[mi][2], al[mi][3], sb + CO_AL + a2_off + mi*16*PV + ks*32);
        }
        LDSM4T(bh[0], bh[1], bh[2], bh[3], sb + CO_VH + bt_off + ks*16*PV);
        LDSM4T(bl[0], bl[1], bl[2], bl[3], sb + CO_VL + bt_off + ks*16*PV);
#pragma unroll
        for (int mi = 0; mi < 2; mi++) {
            MMA16816(o[mi][0], ah[mi], bh[0], bh[1]);
            MMA16816(o[mi][1], ah[mi], bh[2], bh[3]);
            MMA16816(o[mi][0], ah[mi], bl[0], bl[1]);
            MMA16816(o[mi][1], ah[mi], bl[2], bl[3]);
            MMA16816(o[mi][0], al[mi], bh[0], bh[1]);
            MMA16816(o[mi][1], al[mi], bh[2], bh[3]);
        }
    }
#pragma unroll
    for (int ks = 0; ks < 8; ks++) {
        uint32_t ah[2][4], al[2][4], bh[4], bl[4];
#pragma unroll
        for (int mi = 0; mi < 2; mi++) {
            LDSM4(ah[mi][0], ah[mi][1], ah[mi][2], ah[mi][3], sb + CO_QH + a_off + mi*16*PQ + ks*32);
            LDSM4(al[mi][0], al[mi][1], al[mi][2], al[mi][3], sb + CO_QL + a_off + mi*16*PQ + ks*32);
        }
        LDSM4T(bh[0], bh[1], bh[2], bh[3], sb + CO_SH + bt_off + ks*16*PV);
        LDSM4T(bl[0], bl[1], bl[2], bl[3], sb + CO_SL + bt_off + ks*16*PV);
#pragma unroll
        for (int mi = 0; mi < 2; mi++) {
            MMA16816(o[mi][0], ah[mi], bh[0], bh[1]);
            MMA16816(o[mi][1], ah[mi], bh[2], bh[3]);
            MMA16816(o[mi][0], ah[mi], bl[0], bl[1]);
            MMA16816(o[mi][1], ah[mi], bl[2], bl[3]);
            MMA16816(o[mi][0], al[mi], bh[0], bh[1]);
            MMA16816(o[mi][1], al[mi], bh[2], bh[3]);
        }
    }
    __syncthreads();

    const float* rs = (const float*)(smc + CO_RS);
#pragma unroll
    for (int mi = 0; mi < 2; mi++) {
#pragma unroll
        for (int half = 0; half < 2; half++) {
            int row = warp_m*32 + mi*16 + g + half*8;
            float inv = 1.0f / rs[row];
#pragma unroll
            for (int nj = 0; nj < 2; nj++) {
                int col = warp_n*16 + nj*8 + t*2;
                float ox = o[mi][nj][half*2+0] * inv;
                float oy = o[mi][nj][half*2+1] * inv;
                __nv_bfloat162 hv, lv;
                split2(ox, oy, hv, lv);
                size_t off = (size_t)(l0 + row) * DM + h*DH + col;
                *(__nv_bfloat162*)(g_bhi_ctx + off) = hv;
                *(__nv_bfloat162*)(g_blo_ctx + off) = lv;
            }
        }
    }
}

// ---------------- launcher ----------------
extern "C" void kernel_launch(void* const* d_in, const int* in_sizes, int n_in,
                              void* d_out, int out_size)
{
    const float* query = (const float*)d_in[0];
    const float* key_i = (const float*)d_in[1];
    const float* value = (const float*)d_in[2];
    const float* Wq = (const float*)d_in[3];
    const float* bq = (const float*)d_in[4];
    const float* Wk = (const float*)d_in[5];
    const float* bk = (const float*)d_in[6];
    const float* Wv = (const float*)d_in[7];
    const float* bv = (const float*)d_in[8];
    const float* Wo = (const float*)d_in[9];
    const float* bo = (const float*)d_in[10];
    const float* rf = (const float*)d_in[11];
    float* out = (float*)d_out;

    void* p;
    cudaGetSymbolAddress(&p, g_bhi_in);  __nv_bfloat16* bhi_in = (__nv_bfloat16*)p;
    cudaGetSymbolAddress(&p, g_blo_in);  __nv_bfloat16* blo_in = (__nv_bfloat16*)p;
    cudaGetSymbolAddress(&p, g_bhi_w);   __nv_bfloat16* bhi_w  = (__nv_bfloat16*)p;
    cudaGetSymbolAddress(&p, g_blo_w);   __nv_bfloat16* blo_w  = (__nv_bfloat16*)p;
    cudaGetSymbolAddress(&p, g_bhi_ctx); __nv_bfloat16* bhi_c  = (__nv_bfloat16*)p;
    cudaGetSymbolAddress(&p, g_blo_ctx); __nv_bfloat16* blo_c  = (__nv_bfloat16*)p;
    cudaGetSymbolAddress(&p, g_qhi);     __nv_bfloat16* qhi    = (__nv_bfloat16*)p;
    cudaGetSymbolAddress(&p, g_qlo);     __nv_bfloat16* qlo    = (__nv_bfloat16*)p;
    cudaGetSymbolAddress(&p, g_khi);     __nv_bfloat16* khi    = (__nv_bfloat16*)p;
    cudaGetSymbolAddress(&p, g_klo);     __nv_bfloat16* klo    = (__nv_bfloat16*)p;
    cudaGetSymbolAddress(&p, g_vhi);     __nv_bfloat16* vhi    = (__nv_bfloat16*)p;
    cudaGetSymbolAddress(&p, g_vlo);     __nv_bfloat16* vlo    = (__nv_bfloat16*)p;

    CV cv;
    cv.src[0]=query; cv.hi[0]=bhi_in;          cv.lo[0]=blo_in;          cv.n[0]=L*DM;
    cv.src[1]=key_i; cv.hi[1]=bhi_in+L*DM;     cv.lo[1]=blo_in+L*DM;     cv.n[1]=L*DM;
    cv.src[2]=value; cv.hi[2]=bhi_in+2*L*DM;   cv.lo[2]=blo_in+2*L*DM;   cv.n[2]=L*DM;
    cv.src[3]=Wq;    cv.hi[3]=bhi_w;           cv.lo[3]=blo_w;           cv.n[3]=DM*DM;
    cv.src[4]=Wk;    cv.hi[4]=bhi_w+DM*DM;     cv.lo[4]=blo_w+DM*DM;     cv.n[4]=DM*DM;
    cv.src[5]=Wv;    cv.hi[5]=bhi_w+2*DM*DM;   cv.lo[5]=blo_w+2*DM*DM;   cv.n[5]=DM*DM;
    cv.src[6]=Wo;    cv.hi[6]=bhi_w+3*DM*DM;   cv.lo[6]=blo_w+3*DM*DM;   cv.n[6]=DM*DM;
    cv.cnt = 7;
    // y-slice 7 handles rf transpose + kstab reset
    convert_split<<<dim3((L*DM)/1024, 8), 256>>>(cv, rf);

    cudaFuncSetAttribute(hmma_gemm, cudaFuncAttributeMaxDynamicSharedMemorySize, HG_SMEM);
    cudaFuncSetAttribute(rf_proj_hmma, cudaFuncAttributeMaxDynamicSharedMemorySize, RF_SMEM);
    cudaFuncSetAttribute(chunk_state_hmma, cudaFuncAttributeMaxDynamicSharedMemorySize, CS_TOTAL);
    cudaFuncSetAttribute(chunk_out_hmma, cudaFuncAttributeMaxDynamicSharedMemorySize, CO_TOTAL);

    // QKV projections (hk fused into z==1 epilogue)
    MMArgs mq;
    mq.Ahi[0]=bhi_in;        mq.Alo[0]=blo_in;        mq.Whi[0]=bhi_w;        mq.Wlo[0]=blo_w;        mq.bias[0]=bq; mq.C[0]=nullptr; mq.Chi[0]=qhi; mq.Clo[0]=qlo; mq.alpha[0]=SCALE_QK;
    mq.Ahi[1]=bhi_in+L*DM;   mq.Alo[1]=blo_in+L*DM;   mq.Whi[1]=bhi_w+DM*DM;  mq.Wlo[1]=blo_w+DM*DM;  mq.bias[1]=bk; mq.C[1]=nullptr; mq.Chi[1]=khi; mq.Clo[1]=klo; mq.alpha[1]=SCALE_QK;
    mq.Ahi[2]=bhi_in+2*L*DM; mq.Alo[2]=blo_in+2*L*DM; mq.Whi[2]=bhi_w+2*DM*DM;mq.Wlo[2]=blo_w+2*DM*DM;mq.bias[2]=bv; mq.C[2]=nullptr; mq.Chi[2]=vhi; mq.Clo[2]=vlo; mq.alpha[2]=1.0f;
    hmma_gemm<<<dim3(DM/128, L/64, 3), 256, HG_SMEM>>>(mq, 1);

    rf_proj_hmma<<<dim3(1, L/128, 16), 256, RF_SMEM>>>();

    chunk_state_hmma<<<dim3(NC, NH), 256, CS_TOTAL>>>();
    prefix_scan<<<dim3((MF*DH + MF + 255)/256, NH), 256>>>();
    chunk_out_hmma<<<dim3(NC, NH), 256, CO_TOTAL>>>();

    // output projection
    MMArgs mo;
    mo.Ahi[0]=bhi_c; mo.Alo[0]=blo_c; mo.Whi[0]=bhi_w+3*DM*DM; mo.Wlo[0]=blo_w+3*DM*DM; mo.bias[0]=bo; mo.C[0]=out; mo.Chi[0]=nullptr; mo.Clo[0]=nullptr; mo.alpha[0]=1.0f;
    mo.Ahi[1]=mo.Ahi[0]; mo.Alo[1]=mo.Alo[0]; mo.Whi[1]=mo.Whi[0]; mo.Wlo[1]=mo.Wlo[0]; mo.bias[1]=bo; mo.C[1]=out; mo.Chi[1]=nullptr; mo.Clo[1]=nullptr; mo.alpha[1]=1.0f;
    mo.Ahi[2]=mo.Ahi[0]; mo.Alo[2]=mo.Alo[0]; mo.Whi[2]=mo.Whi[0]; mo.Wlo[2]=mo.Wlo[0]; mo.bias[2]=bo; mo.C[2]=out; mo.Chi[2]=nullptr; mo.Clo[2]=nullptr; mo.alpha[2]=1.0f;
    hmma_gemm<<<dim3(DM/128, L/64, 1), 256, HG_SMEM>>>(mo, 0);
}

// round 13
// speedup vs baseline: 1.0336x; 1.0336x over previous
#include <cuda_runtime.h>
#include <cuda_bf16.h>
#include <math.h>
#include <stdint.h>

#define L 2048
#define DM 512
#define NH 8
#define DH 64
#define MF 128
#define CHK 64
#define NC (L/CHK)   // 32

#define SCALE_QK 0.2102241038134287f
#define NC_COEF  0.08838834764831845f
#define KEPS 1e-4f
#define DEPS 1e-6f

// ---------------- device scratch ----------------
__device__ float g_hk[NH*L];
__device__ unsigned g_kstab;
__device__ float g_S[NH*NC*MF*DH];
__device__ float g_z[NH*NC*MF];

__device__ __nv_bfloat16 g_bhi_in[3][L*DM];
__device__ __nv_bfloat16 g_blo_in[3][L*DM];
__device__ __nv_bfloat16 g_bhi_w[4][DM*DM];
__device__ __nv_bfloat16 g_blo_w[4][DM*DM];
__device__ __nv_bfloat16 g_bhi_ctx[L*DM];
__device__ __nv_bfloat16 g_blo_ctx[L*DM];
__device__ __nv_bfloat16 g_qhi[L*DM];
__device__ __nv_bfloat16 g_qlo[L*DM];
__device__ __nv_bfloat16 g_khi[L*DM];
__device__ __nv_bfloat16 g_klo[L*DM];
__device__ __nv_bfloat16 g_rfthi[MF*DH];
__device__ __nv_bfloat16 g_rftlo[MF*DH];
__device__ __nv_bfloat16 g_pqhi[NH*L*MF];
__device__ __nv_bfloat16 g_pqlo[NH*L*MF];
__device__ __nv_bfloat16 g_pkhi[NH*L*MF];
__device__ __nv_bfloat16 g_pklo[NH*L*MF];
__device__ __nv_bfloat16 g_vhi[L*DM];
__device__ __nv_bfloat16 g_vlo[L*DM];
__device__ __nv_bfloat16 g_Shi[NH*NC*MF*DH];
__device__ __nv_bfloat16 g_Slo[NH*NC*MF*DH];

__device__ __forceinline__ unsigned enc_f(float f){
    unsigned u = __float_as_uint(f);
    return (u & 0x80000000u) ? ~u : (u | 0x80000000u);
}
__device__ __forceinline__ float dec_f(unsigned k){
    unsigned u = (k & 0x80000000u) ? (k ^ 0x80000000u) : ~k;
    return __uint_as_float(u);
}

__device__ __forceinline__ uint32_t smem_u32(const void* p) {
    uint32_t a;
    asm("{ .reg .u64 t; cvta.to.shared.u64 t, %1; cvt.u32.u64 %0, t; }" : "=r"(a) : "l"(p));
    return a;
}

#define CP_ASYNC16(sa, gp) asm volatile("cp.async.cg.shared.global [%0], [%1], 16;" :: "r"(sa), "l"(gp))
#define CP_COMMIT()        asm volatile("cp.async.commit_group;")
#define CP_WAIT1()         asm volatile("cp.async.wait_group 1;")
#define CP_WAIT0()         asm volatile("cp.async.wait_group 0;")

#define LDSM4(r0,r1,r2,r3,a) \
    asm volatile("ldmatrix.sync.aligned.m8n8.x4.shared.b16 {%0,%1,%2,%3}, [%4];" \
        : "=r"(r0),"=r"(r1),"=r"(r2),"=r"(r3) : "r"(a))
#define LDSM4T(r0,r1,r2,r3,a) \
    asm volatile("ldmatrix.sync.aligned.m8n8.x4.trans.shared.b16 {%0,%1,%2,%3}, [%4];" \
        : "=r"(r0),"=r"(r1),"=r"(r2),"=r"(r3) : "r"(a))

#define MMA16816(d,a,b0,b1) \
    asm volatile("mma.sync.aligned.m16n8k16.row.col.f32.bf16.bf16.f32 " \
        "{%0,%1,%2,%3},{%4,%5,%6,%7},{%8,%9},{%0,%1,%2,%3};" \
        : "+f"((d)[0]),"+f"((d)[1]),"+f"((d)[2]),"+f"((d)[3]) \
        : "r"((a)[0]),"r"((a)[1]),"r"((a)[2]),"r"((a)[3]),"r"(b0),"r"(b1))

__device__ __forceinline__ void split2(float x, float y, __nv_bfloat162& hv, __nv_bfloat162& lv){
    __nv_bfloat16 hx = __float2bfloat16(x);
    __nv_bfloat16 hy = __float2bfloat16(y);
    hv.x = hx; hv.y = hy;
    lv.x = __float2bfloat16(x - __bfloat162float(hx));
    lv.y = __float2bfloat16(y - __bfloat162float(hy));
}

// ---------------- fp32 -> (bf16 hi, bf16 lo) converter (+rf transpose, +kstab reset) ----------------
struct CV { const float* src[8]; __nv_bfloat16* hi[8]; __nv_bfloat16* lo[8]; int n[8]; int cnt; };
__global__ void convert_split(CV cv, const float* __restrict__ rf){
    int t = blockIdx.y;
    if (t == cv.cnt) {
        if (blockIdx.x == 0 && threadIdx.x == 0) g_kstab = 0u;
        int i0 = blockIdx.x * 1024 + threadIdx.x;
#pragma unroll
        for (int j = 0; j < 4; j++) {
            int i = i0 + j * 256;
            if (i < MF * DH) {
                int m = i >> 6, d = i & 63;
                float x = rf[(size_t)d * MF + m];
                __nv_bfloat16 h = __float2bfloat16(x);
                g_rfthi[(size_t)m * DH + d] = h;
                g_rftlo[(size_t)m * DH + d] = __float2bfloat16(x - __bfloat162float(h));
            }
        }
        return;
    }
    int n = cv.n[t];
    const float* s = cv.src[t];
    __nv_bfloat16* ph = cv.hi[t];
    __nv_bfloat16* pl = cv.lo[t];
    int i0 = blockIdx.x * 1024 + threadIdx.x;
#pragma unroll
    for (int j = 0; j < 4; j++) {
        int i = i0 + j * 256;
        if (i < n) {
            float x = s[i];
            __nv_bfloat16 h = __float2bfloat16(x);
            ph[i] = h;
            pl[i] = __float2bfloat16(x - __bfloat162float(h));
        }
    }
}

// ---------------- split-bf16 HMMA GEMM (tile 64x128, BK=64, 2-stage, 2 CTAs/SM) ----------------
#define PITCH_B 144
#define A_TILE (64*PITCH_B)          // 9216
#define B_TILE (128*PITCH_B)         // 18432
#define STAGE_BYTES (2*A_TILE + 2*B_TILE)  // 55296
#define HG_SMEM (2*STAGE_BYTES)      // 110592
#define NKC 8

struct MMArgs {
    const __nv_bfloat16* Ahi[3]; const __nv_bfloat16* Alo[3];
    const __nv_bfloat16* Whi[3]; const __nv_bfloat16* Wlo[3];
    const float* bias[3]; float* C[3];
    __nv_bfloat16* Chi[3]; __nv_bfloat16* Clo[3];
    float alpha[3];
};

__global__ __launch_bounds__(256, 2) void hmma_gemm(MMArgs ga, int do_hk)
{
    extern __shared__ char smem[];
    uint32_t sb = smem_u32(smem);
    int tid = threadIdx.x;
    int lane = tid & 31, wid = tid >> 5;
    int warp_m = wid & 1, warp_n = wid >> 1;      // 2M x 4N, warp tile 32x32
    int z = blockIdx.z;
    int m0 = blockIdx.y * 64, n0 = blockIdx.x * 128;

    const __nv_bfloat16* Ahi = ga.Ahi[z] + (size_t)m0 * DM;
    const __nv_bfloat16* Alo = ga.Alo[z] + (size_t)m0 * DM;
    const __nv_bfloat16* Whi = ga.Whi[z] + (size_t)n0 * DM;
    const __nv_bfloat16* Wlo = ga.Wlo[z] + (size_t)n0 * DM;
    const float* bias = ga.bias[z];
    float alpha = ga.alpha[z];

    uint32_t a_off = (uint32_t)(warp_m*32 + (lane & 15)) * PITCH_B + (lane >> 4) * 16;
    uint32_t b_off = (uint32_t)(warp_n*32 + (lane & 7) + (lane >> 4) * 8) * PITCH_B + ((lane >> 3) & 1) * 16;

    float acc[2][4][4];
#pragma unroll
    for (int i = 0; i < 2; i++)
#pragma unroll
        for (int j = 0; j < 4; j++)
#pragma unroll
            for (int r = 0; r < 4; r++) acc[i][j][r] = 0.f;

    // loads: 3072 16B chunks per stage = 12 per thread
    {
#pragma unroll
        for (int j = 0; j < 12; j++) {
            int idx = tid + j * 256;
            const __nv_bfloat16* gp;
            uint32_t sp;
            if (idx < 1024) {
                int t2 = idx >> 9;
                int w = idx & 511;
                int r = w >> 3, cc = w & 7;
                gp = (t2 ? Alo : Ahi) + (size_t)r * DM + cc*8;
                sp = sb + t2*A_TILE + (uint32_t)r * PITCH_B + cc*16;
            } else {
                int w = idx - 1024;
                int t2 = w >> 10;
                w &= 1023;
                int r = w >> 3, cc = w & 7;
                gp = (t2 ? Wlo : Whi) + (size_t)r * DM + cc*8;
                sp = sb + 2*A_TILE + t2*B_TILE + (uint32_t)r * PITCH_B + cc*16;
            }
            CP_ASYNC16(sp, gp);
        }
        CP_COMMIT();
    }

    for (int kc = 0; kc < NKC; kc++) {
        if (kc + 1 < NKC) {
            int k0 = (kc + 1) * 64;
            uint32_t stb = sb + ((kc + 1) & 1) * STAGE_BYTES;
#pragma unroll
            for (int j = 0; j < 12; j++) {
                int idx = tid + j * 256;
                const __nv_bfloat16* gp;
                uint32_t sp;
                if (idx < 1024) {
                    int t2 = idx >> 9;
                    int w = idx & 511;
                    int r = w >> 3, cc = w & 7;
                    gp = (t2 ? Alo : Ahi) + (size_t)r * DM + k0 + cc*8;
                    sp = stb + t2*A_TILE + (uint32_t)r * PITCH_B + cc*16;
                } else {
                    int w = idx - 1024;
                    int t2 = w >> 10;
                    w &= 1023;
                    int r = w >> 3, cc = w & 7;
                    gp = (t2 ? Wlo : Whi) + (size_t)r * DM + k0 + cc*8;
                    sp = stb + 2*A_TILE + t2*B_TILE + (uint32_t)r * PITCH_B + cc*16;
                }
                CP_ASYNC16(sp, gp);
            }
            CP_COMMIT();
            CP_WAIT1();
        } else {
            CP_WAIT0();
        }
        __syncthreads();

        uint32_t st = sb + (kc & 1) * STAGE_BYTES;
        uint32_t sAhi = st + a_off;
        uint32_t sAlo = st + A_TILE + a_off;
        uint32_t sBhi = st + 2*A_TILE + b_off;
        uint32_t sBlo = st + 2*A_TILE + B_TILE + b_off;

#pragma unroll
        for (int ks = 0; ks < 4; ks++) {
            uint32_t ah[2][4], al[2][4], bh[2][4], bl[2][4];
#pragma unroll
            for (int mi = 0; mi < 2; mi++) {
                LDSM4(ah[mi][0], ah[mi][1], ah[mi][2], ah[mi][3], sAhi + mi*16*PITCH_B + ks*32);
                LDSM4(al[mi][0], al[mi][1], al[mi][2], al[mi][3], sAlo + mi*16*PITCH_B + ks*32);
            }
#pragma unroll
            for (int nb = 0; nb < 2; nb++) {
                LDSM4(bh[nb][0], bh[nb][1], bh[nb][2], bh[nb][3], sBhi + nb*16*PITCH_B + ks*32);
                LDSM4(bl[nb][0], bl[nb][1], bl[nb][2], bl[nb][3], sBlo + nb*16*PITCH_B + ks*32);
            }
#pragma unroll
            for (int mi = 0; mi < 2; mi++)
#pragma unroll
                for (int nb = 0; nb < 2; nb++) {
                    MMA16816(acc[mi][nb*2+0], ah[mi], bh[nb][0], bh[nb][1]);
                    MMA16816(acc[mi][nb*2+1], ah[mi], bh[nb][2], bh[nb][3]);
                    MMA16816(acc[mi][nb*2+0], ah[mi], bl[nb][0], bl[nb][1]);
                    MMA16816(acc[mi][nb*2+1], ah[mi], bl[nb][2], bl[nb][3]);
                    MMA16816(acc[mi][nb*2+0], al[mi], bh[nb][0], bh[nb][1]);
                    MMA16816(acc[mi][nb*2+1], al[mi], bh[nb][2], bh[nb][3]);
                }
        }
        __syncthreads();
    }

    int g = lane >> 2, t = lane & 3;
    __nv_bfloat16* Chi = ga.Chi[z];
    float* C = ga.C[z];
    bool hk = (do_hk && z == 1);
    float* pr = (float*)smem;
    float* red = (float*)smem + 256;

#pragma unroll
    for (int mi = 0; mi < 2; mi++) {
#pragma unroll
        for (int half = 0; half < 2; half++) {
            int row = m0 + warp_m*32 + mi*16 + g + half*8;
            float ss = 0.f;
#pragma unroll
            for (int nj = 0; nj < 4; nj++) {
                int col = n0 + warp_n*32 + nj*8 + t*2;
                float2 bb = *(const float2*)(bias + col);
                float ox = alpha * (acc[mi][nj][half*2+0] + bb.x);
                float oy = alpha * (acc[mi][nj][half*2+1] + bb.y);
                ss += ox*ox + oy*oy;
                if (C) *(float2*)(C + (size_t)row * DM + col) = make_float2(ox, oy);
                if (Chi) {
                    __nv_bfloat162 hv, lv;
                    split2(ox, oy, hv, lv);
                    *(__nv_bfloat162*)(Chi + (size_t)row * DM + col) = hv;
                    *(__nv_bfloat162*)(ga.Clo[z] + (size_t)row * DM + col) = lv;
                }
            }
            if (hk) {
                ss += __shfl_xor_sync(0xffffffffu, ss, 1);
                ss += __shfl_xor_sync(0xffffffffu, ss, 2);
                if (t == 0) pr[(warp_m*32 + mi*16 + g + half*8)*4 + warp_n] = ss;
            }
        }
    }
    if (hk) {
        __syncthreads();
        float hmax = -1e30f;
        if (tid < 128) {
            int row = tid >> 1, hd2 = tid & 1;
            float ss = pr[row*4 + hd2*2] + pr[row*4 + hd2*2 + 1];
            float hv = -0.5f * ss;
            g_hk[(size_t)((n0 >> 6) + hd2) * L + m0 + row] = hv;
            hmax = hv;
        }
#pragma unroll
        for (int o = 16; o; o >>= 1) hmax = fmaxf(hmax, __shfl_xor_sync(0xffffffffu, hmax, o));
        if (lane == 0) red[wid] = hmax;
        __syncthreads();
        if (tid == 0) {
            float mx = red[0];
#pragma unroll
            for (int i = 1; i < 8; i++) mx = fmaxf(mx, red[i]);
            atomicMax(&g_kstab, enc_f(mx));
        }
    }
}

// ---------------- rf projection + featurize (HMMA split-bf16) ----------------
#define PITCH2 144
#define TILE2 (128*PITCH2)
#define RF_SMEM (4*TILE2)

__global__ __launch_bounds__(256) void rf_proj_hmma()
{
    extern __shared__ char smem[];
    uint32_t sb = smem_u32(smem);
    int tid = threadIdx.x;
    int lane = tid & 31, wid = tid >> 5;
    int warp_m = wid & 1, warp_n = wid >> 1;
    int z = blockIdx.z;
    int h = z & 7;
    bool isq = z < 8;
    int m0 = blockIdx.y * 128;

    const __nv_bfloat16* Ahi = (isq ? g_qhi : g_khi) + (size_t)m0 * DM + h * DH;
    const __nv_bfloat16* Alo = (isq ? g_qlo : g_klo) + (size_t)m0 * DM + h * DH;

#pragma unroll
    for (int j = 0; j < 16; j++) {
        int idx = tid + j * 256;
        int tile = idx >> 10;
        int w = idx & 1023;
        int r = w >> 3, c = w & 7;
        const __nv_bfloat16* gp =
            (tile == 0) ? (Ahi + (size_t)r * DM + c*8) :
            (tile == 1) ? (Alo + (size_t)r * DM + c*8) :
            (tile == 2) ? (g_rfthi + (size_t)r * DH + c*8) :
                          (g_rftlo + (size_t)r * DH + c*8);
        uint32_t sp = sb + tile * TILE2 + (uint32_t)r * PITCH2 + c * 16;
        CP_ASYNC16(sp, gp);
    }
    CP_COMMIT();
    CP_WAIT0();
    __syncthreads();

    uint32_t a_off = (uint32_t)(warp_m*64 + (lane & 15)) * PITCH2 + (lane >> 4) * 16;
    uint32_t b_off = (uint32_t)(warp_n*32 + (lane & 7) + (lane >> 4) * 8) * PITCH2 + ((lane >> 3) & 1) * 16;
    uint32_t sAhi = sb + a_off;
    uint32_t sAlo = sb + TILE2 + a_off;
    uint32_t sBhi = sb + 2*TILE2 + b_off;
    uint32_t sBlo = sb + 3*TILE2 + b_off;

    float acc[4][4][4];
#pragma unroll
    for (int i = 0; i < 4; i++)
#pragma unroll
        for (int j = 0; j < 4; j++)
#pragma unroll
            for (int r = 0; r < 4; r++) acc[i][j][r] = 0.f;

#pragma unroll
    for (int ks = 0; ks < 4; ks++) {
        uint32_t ah[4][4], al[4][4], bh[2][4], bl[2][4];
#pragma unroll
        for (int mi = 0; mi < 4; mi++) {
            LDSM4(ah[mi][0], ah[mi][1], ah[mi][2], ah[mi][3], sAhi + mi*16*PITCH2 + ks*32);
            LDSM4(al[mi][0], al[mi][1], al[mi][2], al[mi][3], sAlo + mi*16*PITCH2 + ks*32);
        }
#pragma unroll
        for (int nb = 0; nb < 2; nb++) {
            LDSM4(bh[nb][0], bh[nb][1], bh[nb][2], bh[nb][3], sBhi + nb*16*PITCH2 + ks*32);
            LDSM4(bl[nb][0], bl[nb][1], bl[nb][2], bl[nb][3], sBlo + nb*16*PITCH2 + ks*32);
        }
#pragma unroll
        for (int mi = 0; mi < 4; mi++)
#pragma unroll
            for (int nb = 0; nb < 2; nb++) {
                MMA16816(acc[mi][nb*2+0], ah[mi], bh[nb][0], bh[nb][1]);
                MMA16816(acc[mi][nb*2+1], ah[mi], bh[nb][2], bh[nb][3]);
                MMA16816(acc[mi][nb*2+0], ah[mi], bl[nb][0], bl[nb][1]);
                MMA16816(acc[mi][nb*2+1], ah[mi], bl[nb][2], bl[nb][3]);
                MMA16816(acc[mi][nb*2+0], al[mi], bh[nb][0], bh[nb][1]);
                MMA16816(acc[mi][nb*2+1], al[mi], bh[nb][2], bh[nb][3]);
            }
    }

    float kst = isq ? 0.f : dec_f(g_kstab);
    int g = lane >> 2, t = lane & 3;
    __nv_bfloat16* Ph = (isq ? g_pqhi : g_pkhi) + (size_t)h * L * MF;
    __nv_bfloat16* Pl = (isq ? g_pqlo : g_pklo) + (size_t)h * L * MF;
#pragma unroll
    for (int mi = 0; mi < 4; mi++) {
#pragma unroll
        for (int half = 0; half < 2; half++) {
            int row = m0 + warp_m*64 + mi*16 + g + half*8;
            float off = isq ? 0.f : (g_hk[(size_t)h * L + row] - kst);
#pragma unroll
            for (int nj = 0; nj < 4; nj++) {
                int col = warp_n*32 + nj*8 + t*2;
                float ox = NC_COEF * (__expf(acc[mi][nj][half*2+0] + off) + KEPS);
                float oy = NC_COEF * (__expf(acc[mi][nj][half*2+1] + off) + KEPS);
                __nv_bfloat162 hv, lv;
                split2(ox, oy, hv, lv);
                *(__nv_bfloat162*)(Ph + (size_t)row * MF + col) = hv;
                *(__nv_bfloat162*)(Pl + (size_t)row * MF + col) = lv;
            }
        }
    }
}

// ---------------- chunk_state via HMMA ----------------
#define CSP_K 272
#define CSP_V 208
#define CS_KH 0
#define CS_KL (CS_KH + 64*CSP_K)
#define CS_VH (CS_KL + 64*CSP_K)
#define CS_VL (CS_VH + 64*CSP_V)
#define CS_TOTAL (CS_VL + 64*CSP_V)

__global__ __launch_bounds__(256) void chunk_state_hmma(){
    extern __shared__ char smc[];
    uint32_t sb = smem_u32(smc);
    int c = blockIdx.x, h = blockIdx.y;
    int tid = threadIdx.x, lane = tid & 31, wid = tid >> 5;
    int warp_m = wid >> 1, warp_n = wid & 1;
    int l0 = c * CHK;

    const __nv_bfloat16* kh = g_pkhi + ((size_t)h * L + l0) * MF;
    const __nv_bfloat16* kl = g_pklo + ((size_t)h * L + l0) * MF;
    for (int i = tid; i < 1024; i += 256) {
        int r = i >> 4, cc = i & 15;
        CP_ASYNC16(sb + CS_KH + (uint32_t)r*CSP_K + cc*16, kh + (size_t)r*MF + cc*8);
        CP_ASYNC16(sb + CS_KL + (uint32_t)r*CSP_K + cc*16, kl + (size_t)r*MF + cc*8);
    }
    for (int i = tid; i < 512; i += 256) {
        int r = i >> 3, cc = i & 7;
        CP_ASYNC16(sb + CS_VH + (uint32_t)r*CSP_V + cc*16, g_vhi + (size_t)(l0+r)*DM + h*DH + cc*8);
        CP_ASYNC16(sb + CS_VL + (uint32_t)r*CSP_V + cc*16, g_vlo + (size_t)(l0+r)*DM + h*DH + cc*8);
    }
    if (tid < 64) {
        uint4 zz = make_uint4(0u,0u,0u,0u);
#pragma unroll
        for (int q = 0; q < 4; q++) {
            *(uint4*)(smc + CS_VH + tid*CSP_V + 128 + q*16) = zz;
            *(uint4*)(smc + CS_VL + tid*CSP_V + 128 + q*16) = zz;
        }
        *((__nv_bfloat16*)(smc + CS_VH + tid*CSP_V) + 64) = __float2bfloat16(1.0f);
    }
    CP_COMMIT(); CP_WAIT0();
    __syncthreads();

    float acc[2][6][4];
#pragma unroll
    for (int i = 0; i < 2; i++)
#pragma unroll
        for (int j = 0; j < 6; j++)
#pragma unroll
            for (int r = 0; r < 4; r++) acc[i][j][r] = 0.f;

#pragma unroll
    for (int ks = 0; ks < 4; ks++) {
        uint32_t ah[2][4], al[2][4], bh[3][4], bl[3][4];
#pragma unroll
        for (int mi = 0; mi < 2; mi++) {
            uint32_t aoff = (uint32_t)(ks*16 + ((lane >> 4) & 1)*8 + (lane & 7)) * CSP_K
                          + (uint32_t)(warp_m*32 + mi*16 + ((lane >> 3) & 1)*8) * 2;
            LDSM4T(ah[mi][0], ah[mi][1], ah[mi][2], ah[mi][3], sb + CS_KH + aoff);
            LDSM4T(al[mi][0], al[mi][1], al[mi][2], al[mi][3], sb + CS_KL + aoff);
        }
#pragma unroll
        for (int nb = 0; nb < 3; nb++) {
            uint32_t boff = (uint32_t)(ks*16 + (lane & 15)) * CSP_V
                          + (uint32_t)(warp_n*48 + nb*16 + (lane >> 4)*8) * 2;
            LDSM4T(bh[nb][0], bh[nb][1], bh[nb][2], bh[nb][3], sb + CS_VH + boff);
            LDSM4T(bl[nb][0], bl[nb][1], bl[nb][2], bl[nb][3], sb + CS_VL + boff);
        }
#pragma unroll
        for (int mi = 0; mi < 2; mi++)
#pragma unroll
            for (int nb = 0; nb < 3; nb++) {
                MMA16816(acc[mi][nb*2+0], ah[mi], bh[nb][0], bh[nb][1]);
                MMA16816(acc[mi][nb*2+1], ah[mi], bh[nb][2], bh[nb][3]);
                MMA16816(acc[mi][nb*2+0], ah[mi], bl[nb][0], bl[nb][1]);
                MMA16816(acc[mi][nb*2+1], ah[mi], bl[nb][2], bl[nb][3]);
                MMA16816(acc[mi][nb*2+0], al[mi], bh[nb][0], bh[nb][1]);
                MMA16816(acc[mi][nb*2+1], al[mi], bh[nb][2], bh[nb][3]);
            }
    }

    int g = lane >> 2, t = lane & 3;
    float* Sdst = g_S + (size_t)(h*NC + c) * MF * DH;
    float* zdst = g_z + (size_t)(h*NC + c) * MF;
#pragma unroll
    for (int mi = 0; mi < 2; mi++) {
#pragma unroll
        for (int half = 0; half < 2; half++) {
            int m = warp_m*32 + mi*16 + g + half*8;
#pragma unroll
            for (int nj = 0; nj < 6; nj++) {
                int col = warp_n*48 + nj*8 + t*2;
                float x = acc[mi][nj][half*2+0];
                float y = acc[mi][nj][half*2+1];
                if (col < 64) {
                    *(float2*)(Sdst + (size_t)m * DH + col) = make_float2(x, y);
                } else if (col == 64) {
                    zdst[m] = x;
                }
            }
        }
    }
}

// ---------------- exclusive prefix over chunks (batched loads, MLP=32) ----------------
__global__ void prefix_scan(){
    int h = blockIdx.y;
    int idx = blockIdx.x * 256 + threadIdx.x;
    if (idx < MF * DH) {
        const float* p = g_S + (size_t)h * NC * MF * DH + idx;
        float v[NC];
#pragma unroll
        for (int c = 0; c < NC; c++) v[c] = p[(size_t)c * MF * DH];
        __nv_bfloat16* ph = g_Shi + (size_t)h * NC * MF * DH + idx;
        __nv_bfloat16* pl = g_Slo + (size_t)h * NC * MF * DH + idx;
        float prev = 0.f;
#pragma unroll
        for (int c = 0; c < NC; c++) {
            __nv_bfloat16 hh = __float2bfloat16(prev);
            ph[(size_t)c * MF * DH] = hh;
            pl[(size_t)c * MF * DH] = __float2bfloat16(prev - __bfloat162float(hh));
            prev += v[c];
        }
    } else if (idx < MF * DH + MF) {
        int m = idx - MF * DH;
        float* p = g_z + (size_t)h * NC * MF + m;
        float v[NC];
#pragma unroll
        for (int c = 0; c < NC; c++) v[c] = p[c * MF];
        float prev = 0.f;
#pragma unroll
        for (int c = 0; c < NC; c++) {
            p[c * MF] = prev;
            prev += v[c];
        }
    }
}

// ---------------- chunk_out via HMMA (split commit groups: Q/K first, V/S/z overlap phase 1) ----------------
#define PQ 272
#define PV 144
#define CO_QH 0
#define CO_QL (CO_QH + 64*PQ)
#define CO_KH (CO_QL + 64*PQ)
#define CO_KL (CO_KH + 64*PQ)
#define CO_VH (CO_KL + 64*PQ)
#define CO_VL (CO_VH + 64*PV)
#define CO_SH (CO_VL + 64*PV)
#define CO_SL (CO_SH + 128*PV)
#define CO_AH (CO_SL + 128*PV)
#define CO_AL (CO_AH + 64*PV)
#define CO_ZB (CO_AL + 64*PV)
#define CO_PR (CO_ZB + 512)
#define CO_RS (CO_PR + 64*4*4)
#define CO_TOTAL (CO_RS + 256)

__global__ __launch_bounds__(256) void chunk_out_hmma(){
    extern __shared__ char smc[];
    uint32_t sb = smem_u32(smc);
    int c = blockIdx.x, h = blockIdx.y;
    int tid = threadIdx.x, lane = tid & 31, wid = tid >> 5;
    int warp_m = wid & 1, warp_n = wid >> 1;
    int l0 = c * CHK;

    {
        const __nv_bfloat16* pqh = g_pqhi + ((size_t)h * L + l0) * MF;
        const __nv_bfloat16* pql = g_pqlo + ((size_t)h * L + l0) * MF;
        const __nv_bfloat16* pkh = g_pkhi + ((size_t)h * L + l0) * MF;
        const __nv_bfloat16* pkl = g_pklo + ((size_t)h * L + l0) * MF;
        // group A: Q/K (needed for phase 1)
        for (int i = tid; i < 1024; i += 256) {
            int r = i >> 4, cc = i & 15;
            CP_ASYNC16(sb + CO_QH + r*PQ + cc*16, pqh + (size_t)r*MF + cc*8);
            CP_ASYNC16(sb + CO_QL + r*PQ + cc*16, pql + (size_t)r*MF + cc*8);
            CP_ASYNC16(sb + CO_KH + r*PQ + cc*16, pkh + (size_t)r*MF + cc*8);
            CP_ASYNC16(sb + CO_KL + r*PQ + cc*16, pkl + (size_t)r*MF + cc*8);
        }
        CP_COMMIT();
        // group B: V/S/z (needed after phase 1)
        for (int i = tid; i < 512; i += 256) {
            int r = i >> 3, cc = i & 7;
            CP_ASYNC16(sb + CO_VH + r*PV + cc*16, g_vhi + (size_t)(l0 + r)*DM + h*DH + cc*8);
            CP_ASYNC16(sb + CO_VL + r*PV + cc*16, g_vlo + (size_t)(l0 + r)*DM + h*DH + cc*8);
        }
        const __nv_bfloat16* sh = g_Shi + (size_t)(h*NC + c)*MF*DH;
        const __nv_bfloat16* sl = g_Slo + (size_t)(h*NC + c)*MF*DH;
        for (int i = tid; i < 1024; i += 256) {
            int r = i >> 3, cc = i & 7;
            CP_ASYNC16(sb + CO_SH + r*PV + cc*16, sh + (size_t)r*DH + cc*8);
            CP_ASYNC16(sb + CO_SL + r*PV + cc*16, sl + (size_t)r*DH + cc*8);
        }
        if (tid < 32) CP_ASYNC16(sb + CO_ZB + tid*16, g_z + (size_t)(h*NC + c)*MF + tid*4);
        CP_COMMIT();
        CP_WAIT1();    // Q/K ready; V/S/z still in flight
    }
    __syncthreads();

    uint32_t a_off = (uint32_t)(warp_m*32 + (lane & 15)) * PQ + (lane >> 4) * 16;
    uint32_t b_off = (uint32_t)(warp_n*16 + (lane & 7) + (lane >> 4) * 8) * PQ + ((lane >> 3) & 1) * 16;

    float acc[2][2][4];
#pragma unroll
    for (int i = 0; i < 2; i++)
#pragma unroll
        for (int j = 0; j < 2; j++)
#pragma unroll
            for (int r = 0; r < 4; r++) acc[i][j][r] = 0.f;

#pragma unroll
    for (int ks = 0; ks < 8; ks++) {
        uint32_t ah[2][4], al[2][4], bh[4], bl[4];
#pragma unroll
        for (int mi = 0; mi < 2; mi++) {
            LDSM4(ah[mi][0], ah[mi][1], ah[mi][2], ah[mi][3], sb + CO_QH + a_off + mi*16*PQ + ks*32);
            LDSM4(al[mi][0], al[mi][1], al[mi][2], al[mi][3], sb + CO_QL + a_off + mi*16*PQ + ks*32);
        }
        LDSM4(bh[0], bh[1], bh[2], bh[3], sb + CO_KH + b_off + ks*32);
        LDSM4(bl[0], bl[1], bl[2], bl[3], sb + CO_KL + b_off + ks*32);
#pragma unroll
        for (int mi = 0; mi < 2; mi++) {
            MMA16816(acc[mi][0], ah[mi], bh[0], bh[1]);
            MMA16816(acc[mi][1], ah[mi], bh[2], bh[3]);
            MMA16816(acc[mi][0], ah[mi], bl[0], bl[1]);
            MMA16816(acc[mi][1], ah[mi], bl[2], bl[3]);
            MMA16816(acc[mi][0], al[mi], bh[0], bh[1]);
            MMA16816(acc[mi][1], al[mi], bh[2], bh[3]);
        }
    }
    CP_WAIT0();   // V/S/z now resident (visible to all after next __syncthreads)

    int g = lane >> 2, t = lane & 3;
    float* pr = (float*)(smc + CO_PR);
#pragma unroll
    for (int mi = 0; mi < 2; mi++) {
#pragma unroll
        for (int half = 0; half < 2; half++) {
            int row = warp_m*32 + mi*16 + g + half*8;
            float rsum = 0.f;
#pragma unroll
            for (int nj = 0; nj < 2; nj++) {
                int col = warp_n*16 + nj*8 + t*2;
                float x = (col     <= row) ? acc[mi][nj][half*2+0] : 0.f;
                float y = (col + 1 <= row) ? acc[mi][nj][half*2+1] : 0.f;
                rsum += x + y;
                __nv_bfloat162 hv, lv;
                split2(x, y, hv, lv);
                *(__nv_bfloat162*)(smc + CO_AH + row*PV + col*2) = hv;
                *(__nv_bfloat162*)(smc + CO_AL + row*PV + col*2) = lv;
            }
            rsum += __shfl_xor_sync(0xffffffffu, rsum, 1);
            rsum += __shfl_xor_sync(0xffffffffu, rsum, 2);
            if (t == 0) pr[row*4 + warp_n] = rsum;
        }
    }
    __syncthreads();

    if (tid < 64) {
        float s = pr[tid*4+0] + pr[tid*4+1] + pr[tid*4+2] + pr[tid*4+3];
        const float* zf = (const float*)(smc + CO_ZB);
#pragma unroll 8
        for (int m2 = 0; m2 < 64; m2++) {
            __nv_bfloat162 qh2 = *(const __nv_bfloat162*)(smc + CO_QH + tid*PQ + m2*4);
            __nv_bfloat162 ql2 = *(const __nv_bfloat162*)(smc + CO_QL + tid*PQ + m2*4);
            float2 z2 = *(const float2*)(zf + m2*2);
            s += (__bfloat162float(qh2.x) + __bfloat162float(ql2.x)) * z2.x
               + (__bfloat162float(qh2.y) + __bfloat162float(ql2.y)) * z2.y;
        }
        ((float*)(smc + CO_RS))[tid] = s + DEPS;
    }

    float o[2][2][4];
#pragma unroll
    for (int i = 0; i < 2; i++)
#pragma unroll
        for (int j = 0; j < 2; j++)
#pragma unroll
            for (int r = 0; r < 4; r++) o[i][j][r] = 0.f;

    uint32_t a2_off = (uint32_t)(warp_m*32 + (lane & 15)) * PV + (lane >> 4) * 16;
    uint32_t bt_off = (uint32_t)(lane & 15) * PV + (warp_n*16 + (lane >> 4) * 8) * 2;

#pragma unroll
    for (int ks = 0; ks < 4; ks++) {
        uint32_t ah[2][4], al[2][4], bh[4], bl[4];
#pragma unroll
        for (int mi = 0; mi < 2; mi++) {
            LDSM4(ah[mi][0], ah[mi][1], ah[mi][2], ah[mi][3], sb + CO_AH + a2_off + mi*16*PV + ks*32);
            LDSM4(al[mi][0], al[mi][1], al[mi][2], al[mi][3], sb + CO_AL + a2_off + mi*16*PV + ks*32);
        }
        LDSM4T(bh[0], bh[1], bh[2], bh[3], sb + CO_VH + bt_off + ks*16*PV);
        LDSM4T(bl[0], bl[1], bl[2], bl[3], sb + CO_VL + bt_off + ks*16*PV);
#pragma unroll
        for (int mi = 0; mi < 2; mi++) {
            MMA16816(o[mi][0], ah[mi], bh[0], bh[1]);
            MMA16816(o[mi][1], ah[mi], bh[2], bh[3]);
            MMA16816(o[mi][0], ah[mi], bl[0], bl[1]);
            MMA16816(o[mi][1], ah[mi], bl[2], bl[3]);
            MMA16816(o[mi][0], al[mi], bh[0], bh[1]);
            MMA16816(o[mi][1], al[mi], bh[2], bh[3]);
        }
    }
#pragma unroll
    for (int ks = 0; ks < 8; ks++) {
        uint32_t ah[2][4], al[2][4], bh[4], bl[4];
#pragma unroll
        for (int mi = 0; mi < 2; mi++) {
            LDSM4(ah[mi][0], ah[mi][1], ah[mi][2], ah[mi][3], sb + CO_QH + a_off + mi*16*PQ + ks*32);
            LDSM4(al[mi][0], al[mi][1], al[mi][2], al[mi][3], sb + CO_QL + a_off + mi*16*PQ + ks*32);
        }
        LDSM4T(bh[0], bh[1], bh[2], bh[3], sb + CO_SH + bt_off + ks*16*PV);
        LDSM4T(bl[0], bl[1], bl[2], bl[3], sb + CO_SL + bt_off + ks*16*PV);
#pragma unroll
        for (int mi = 0; mi < 2; mi++) {
            MMA16816(o[mi][0], ah[mi], bh[0], bh[1]);
            MMA16816(o[mi][1], ah[mi], bh[2], bh[3]);
            MMA16816(o[mi][0], ah[mi], bl[0], bl[1]);
            MMA16816(o[mi][1], ah[mi], bl[2], bl[3]);
            MMA16816(o[mi][0], al[mi], bh[0], bh[1]);
            MMA16816(o[mi][1], al[mi], bh[2], bh[3]);
        }
    }
    __syncthreads();

    const float* rs = (const float*)(smc + CO_RS);
#pragma unroll
    for (int mi = 0; mi < 2; mi++) {
#pragma unroll
        for (int half = 0; half < 2; half++) {
            int row = warp_m*32 + mi*16 + g + half*8;
            float inv = 1.0f / rs[row];
#pragma unroll
            for (int nj = 0; nj < 2; nj++) {
                int col = warp_n*16 + nj*8 + t*2;
                float ox = o[mi][nj][half*2+0] * inv;
                float oy = o[mi][nj][half*2+1] * inv;
                __nv_bfloat162 hv, lv;
                split2(ox, oy, hv, lv);
                size_t off = (size_t)(l0 + row) * DM + h*DH + col;
                *(__nv_bfloat162*)(g_bhi_ctx + off) = hv;
                *(__nv_bfloat162*)(g_blo_ctx + off) = lv;
            }
        }
    }
}

// ---------------- launcher ----------------
extern "C" void kernel_launch(void* const* d_in, const int* in_sizes, int n_in,
                              void* d_out, int out_size)
{
    const float* query = (const float*)d_in[0];
    const float* key_i = (const float*)d_in[1];
    const float* value = (const float*)d_in[2];
    const float* Wq = (const float*)d_in[3];
    const float* bq = (const float*)d_in[4];
    const float* Wk = (const float*)d_in[5];
    const float* bk = (const float*)d_in[6];
    const float* Wv = (const float*)d_in[7];
    const float* bv = (const float*)d_in[8];
    const float* Wo = (const float*)d_in[9];
    const float* bo = (const float*)d_in[10];
    const float* rf = (const float*)d_in[11];
    float* out = (float*)d_out;

    void* p;
    cudaGetSymbolAddress(&p, g_bhi_in);  __nv_bfloat16* bhi_in = (__nv_bfloat16*)p;
    cudaGetSymbolAddress(&p, g_blo_in);  __nv_bfloat16* blo_in = (__nv_bfloat16*)p;
    cudaGetSymbolAddress(&p, g_bhi_w);   __nv_bfloat16* bhi_w  = (__nv_bfloat16*)p;
    cudaGetSymbolAddress(&p, g_blo_w);   __nv_bfloat16* blo_w  = (__nv_bfloat16*)p;
    cudaGetSymbolAddress(&p, g_bhi_ctx); __nv_bfloat16* bhi_c  = (__nv_bfloat16*)p;
    cudaGetSymbolAddress(&p, g_blo_ctx); __nv_bfloat16* blo_c  = (__nv_bfloat16*)p;
    cudaGetSymbolAddress(&p, g_qhi);     __nv_bfloat16* qhi    = (__nv_bfloat16*)p;
    cudaGetSymbolAddress(&p, g_qlo);     __nv_bfloat16* qlo    = (__nv_bfloat16*)p;
    cudaGetSymbolAddress(&p, g_khi);     __nv_bfloat16* khi    = (__nv_bfloat16*)p;
    cudaGetSymbolAddress(&p, g_klo);     __nv_bfloat16* klo    = (__nv_bfloat16*)p;
    cudaGetSymbolAddress(&p, g_vhi);     __nv_bfloat16* vhi    = (__nv_bfloat16*)p;
    cudaGetSymbolAddress(&p, g_vlo);     __nv_bfloat16* vlo    = (__nv_bfloat16*)p;

    CV cv;
    cv.src[0]=query; cv.hi[0]=bhi_in;          cv.lo[0]=blo_in;          cv.n[0]=L*DM;
    cv.src[1]=key_i; cv.hi[1]=bhi_in+L*DM;     cv.lo[1]=blo_in+L*DM;     cv.n[1]=L*DM;
    cv.src[2]=value; cv.hi[2]=bhi_in+2*L*DM;   cv.lo[2]=blo_in+2*L*DM;   cv.n[2]=L*DM;
    cv.src[3]=Wq;    cv.hi[3]=bhi_w;           cv.lo[3]=blo_w;           cv.n[3]=DM*DM;
    cv.src[4]=Wk;    cv.hi[4]=bhi_w+DM*DM;     cv.lo[4]=blo_w+DM*DM;     cv.n[4]=DM*DM;
    cv.src[5]=Wv;    cv.hi[5]=bhi_w+2*DM*DM;   cv.lo[5]=blo_w+2*DM*DM;   cv.n[5]=DM*DM;
    cv.src[6]=Wo;    cv.hi[6]=bhi_w+3*DM*DM;   cv.lo[6]=blo_w+3*DM*DM;   cv.n[6]=DM*DM;
    cv.cnt = 7;
    convert_split<<<dim3((L*DM)/1024, 8), 256>>>(cv, rf);

    cudaFuncSetAttribute(hmma_gemm, cudaFuncAttributeMaxDynamicSharedMemorySize, HG_SMEM);
    cudaFuncSetAttribute(rf_proj_hmma, cudaFuncAttributeMaxDynamicSharedMemorySize, RF_SMEM);
    cudaFuncSetAttribute(chunk_state_hmma, cudaFuncAttributeMaxDynamicSharedMemorySize, CS_TOTAL);
    cudaFuncSetAttribute(chunk_out_hmma, cudaFuncAttributeMaxDynamicSharedMemorySize, CO_TOTAL);

    // QKV projections (hk fused into z==1 epilogue)
    MMArgs mq;
    mq.Ahi[0]=bhi_in;        mq.Alo[0]=blo_in;        mq.Whi[0]=bhi_w;        mq.Wlo[0]=blo_w;        mq.bias[0]=bq; mq.C[0]=nullptr; mq.Chi[0]=qhi; mq.Clo[0]=qlo; mq.alpha[0]=SCALE_QK;
    mq.Ahi[1]=bhi_in+L*DM;   mq.Alo[1]=blo_in+L*DM;   mq.Whi[1]=bhi_w+DM*DM;  mq.Wlo[1]=blo_w+DM*DM;  mq.bias[1]=bk; mq.C[1]=nullptr; mq.Chi[1]=khi; mq.Clo[1]=klo; mq.alpha[1]=SCALE_QK;
    mq.Ahi[2]=bhi_in+2*L*DM; mq.Alo[2]=blo_in+2*L*DM; mq.Whi[2]=bhi_w+2*DM*DM;mq.Wlo[2]=blo_w+2*DM*DM;mq.bias[2]=bv; mq.C[2]=nullptr; mq.Chi[2]=vhi; mq.Clo[2]=vlo; mq.alpha[2]=1.0f;
    hmma_gemm<<<dim3(DM/128, L/64, 3), 256, HG_SMEM>>>(mq, 1);

    rf_proj_hmma<<<dim3(1, L/128, 16), 256, RF_SMEM>>>();

    chunk_state_hmma<<<dim3(NC, NH), 256, CS_TOTAL>>>();
    prefix_scan<<<dim3((MF*DH + MF + 255)/256, NH), 256>>>();
    chunk_out_hmma<<<dim3(NC, NH), 256, CO_TOTAL>>>();

    // output projection
    MMArgs mo;
    mo.Ahi[0]=bhi_c; mo.Alo[0]=blo_c; mo.Whi[0]=bhi_w+3*DM*DM; mo.Wlo[0]=blo_w+3*DM*DM; mo.bias[0]=bo; mo.C[0]=out; mo.Chi[0]=nullptr; mo.Clo[0]=nullptr; mo.alpha[0]=1.0f;
    mo.Ahi[1]=mo.Ahi[0]; mo.Alo[1]=mo.Alo[0]; mo.Whi[1]=mo.Whi[0]; mo.Wlo[1]=mo.Wlo[0]; mo.bias[1]=bo; mo.C[1]=out; mo.Chi[1]=nullptr; mo.Clo[1]=nullptr; mo.alpha[1]=1.0f;
    mo.Ahi[2]=mo.Ahi[0]; mo.Alo[2]=mo.Alo[0]; mo.Whi[2]=mo.Whi[0]; mo.Wlo[2]=mo.Wlo[0]; mo.bias[2]=bo; mo.C[2]=out; mo.Chi[2]=nullptr; mo.Clo[2]=nullptr; mo.alpha[2]=1.0f;
    hmma_gemm<<<dim3(DM/128, L/64, 1), 256, HG_SMEM>>>(mo, 0);
}

// round 14
// speedup vs baseline: 1.0362x; 1.0025x over previous
#include <cuda_runtime.h>
#include <cuda_bf16.h>
#include <math.h>
#include <stdint.h>

#define L 2048
#define DM 512
#define NH 8
#define DH 64
#define MF 128
#define CHK 64
#define NC (L/CHK)   // 32

#define SCALE_QK 0.2102241038134287f
#define NC_COEF  0.08838834764831845f
#define KEPS 1e-4f
#define DEPS 1e-6f

// ---------------- device scratch ----------------
__device__ float g_hk[NH*L];
__device__ unsigned g_kstab;
__device__ float g_S[NH*NC*MF*DH];
__device__ float g_z[NH*NC*MF];

__device__ __nv_bfloat16 g_bhi_in[3][L*DM];
__device__ __nv_bfloat16 g_blo_in[3][L*DM];
__device__ __nv_bfloat16 g_bhi_w[4][DM*DM];
__device__ __nv_bfloat16 g_blo_w[4][DM*DM];
__device__ __nv_bfloat16 g_bhi_ctx[L*DM];
__device__ __nv_bfloat16 g_blo_ctx[L*DM];
__device__ __nv_bfloat16 g_qhi[L*DM];
__device__ __nv_bfloat16 g_qlo[L*DM];
__device__ __nv_bfloat16 g_khi[L*DM];
__device__ __nv_bfloat16 g_klo[L*DM];
__device__ __nv_bfloat16 g_rfthi[MF*DH];
__device__ __nv_bfloat16 g_rftlo[MF*DH];
__device__ __nv_bfloat16 g_pqhi[NH*L*MF];
__device__ __nv_bfloat16 g_pqlo[NH*L*MF];
__device__ __nv_bfloat16 g_pkhi[NH*L*MF];
__device__ __nv_bfloat16 g_pklo[NH*L*MF];
__device__ __nv_bfloat16 g_vhi[L*DM];
__device__ __nv_bfloat16 g_vlo[L*DM];
__device__ __nv_bfloat16 g_Shi[NH*NC*MF*DH];
__device__ __nv_bfloat16 g_Slo[NH*NC*MF*DH];

__device__ __forceinline__ unsigned enc_f(float f){
    unsigned u = __float_as_uint(f);
    return (u & 0x80000000u) ? ~u : (u | 0x80000000u);
}
__device__ __forceinline__ float dec_f(unsigned k){
    unsigned u = (k & 0x80000000u) ? (k ^ 0x80000000u) : ~k;
    return __uint_as_float(u);
}

__device__ __forceinline__ uint32_t smem_u32(const void* p) {
    uint32_t a;
    asm("{ .reg .u64 t; cvta.to.shared.u64 t, %1; cvt.u32.u64 %0, t; }" : "=r"(a) : "l"(p));
    return a;
}

#define CP_ASYNC16(sa, gp) asm volatile("cp.async.cg.shared.global [%0], [%1], 16;" :: "r"(sa), "l"(gp))
#define CP_COMMIT()        asm volatile("cp.async.commit_group;")
#define CP_WAIT1()         asm volatile("cp.async.wait_group 1;")
#define CP_WAIT0()         asm volatile("cp.async.wait_group 0;")

#define LDSM4(r0,r1,r2,r3,a) \
    asm volatile("ldmatrix.sync.aligned.m8n8.x4.shared.b16 {%0,%1,%2,%3}, [%4];" \
        : "=r"(r0),"=r"(r1),"=r"(r2),"=r"(r3) : "r"(a))
#define LDSM4T(r0,r1,r2,r3,a) \
    asm volatile("ldmatrix.sync.aligned.m8n8.x4.trans.shared.b16 {%0,%1,%2,%3}, [%4];" \
        : "=r"(r0),"=r"(r1),"=r"(r2),"=r"(r3) : "r"(a))

#define MMA16816(d,a,b0,b1) \
    asm volatile("mma.sync.aligned.m16n8k16.row.col.f32.bf16.bf16.f32 " \
        "{%0,%1,%2,%3},{%4,%5,%6,%7},{%8,%9},{%0,%1,%2,%3};" \
        : "+f"((d)[0]),"+f"((d)[1]),"+f"((d)[2]),"+f"((d)[3]) \
        : "r"((a)[0]),"r"((a)[1]),"r"((a)[2]),"r"((a)[3]),"r"(b0),"r"(b1))

__device__ __forceinline__ void split2(float x, float y, __nv_bfloat162& hv, __nv_bfloat162& lv){
    __nv_bfloat16 hx = __float2bfloat16(x);
    __nv_bfloat16 hy = __float2bfloat16(y);
    hv.x = hx; hv.y = hy;
    lv.x = __float2bfloat16(x - __bfloat162float(hx));
    lv.y = __float2bfloat16(y - __bfloat162float(hy));
}

// ---------------- fp32 -> (bf16 hi, bf16 lo) converter (+rf transpose, +kstab reset) ----------------
struct CV { const float* src[8]; __nv_bfloat16* hi[8]; __nv_bfloat16* lo[8]; int n[8]; int cnt; };
__global__ void convert_split(CV cv, const float* __restrict__ rf){
    int t = blockIdx.y;
    if (t == cv.cnt) {
        if (blockIdx.x == 0 && threadIdx.x == 0) g_kstab = 0u;
        int i0 = blockIdx.x * 1024 + threadIdx.x;
#pragma unroll
        for (int j = 0; j < 4; j++) {
            int i = i0 + j * 256;
            if (i < MF * DH) {
                int m = i >> 6, d = i & 63;
                float x = rf[(size_t)d * MF + m];
                __nv_bfloat16 h = __float2bfloat16(x);
                g_rfthi[(size_t)m * DH + d] = h;
                g_rftlo[(size_t)m * DH + d] = __float2bfloat16(x - __bfloat162float(h));
            }
        }
        return;
    }
    int n = cv.n[t];
    const float* s = cv.src[t];
    __nv_bfloat16* ph = cv.hi[t];
    __nv_bfloat16* pl = cv.lo[t];
    int i0 = blockIdx.x * 1024 + threadIdx.x;
#pragma unroll
    for (int j = 0; j < 4; j++) {
        int i = i0 + j * 256;
        if (i < n) {
            float x = s[i];
            __nv_bfloat16 h = __float2bfloat16(x);
            ph[i] = h;
            pl[i] = __float2bfloat16(x - __bfloat162float(h));
        }
    }
}

// ---------------- split-bf16 HMMA GEMM, templated M-tile (MB*32 rows x 128 cols, BK=64, 2-stage) ----------------
#define PITCH_B 144
#define B_TILE (128*PITCH_B)         // 18432
#define NKC 8

struct MMArgs {
    const __nv_bfloat16* Ahi[3]; const __nv_bfloat16* Alo[3];
    const __nv_bfloat16* Whi[3]; const __nv_bfloat16* Wlo[3];
    const float* bias[3]; float* C[3];
    __nv_bfloat16* Chi[3]; __nv_bfloat16* Clo[3];
    float alpha[3];
};

template<int MB>
__global__ __launch_bounds__(256, 2) void hmma_gemm(MMArgs ga, int do_hk)
{
    constexpr int RT = MB * 32;                 // rows per tile
    constexpr int A_T = RT * PITCH_B;
    constexpr int STB = 2*A_T + 2*B_TILE;
    constexpr int ACH = 2 * MB * 256;           // total A 16B-chunks per stage

    extern __shared__ char smem[];
    uint32_t sb = smem_u32(smem);
    int tid = threadIdx.x;
    int lane = tid & 31, wid = tid >> 5;
    int warp_m = wid & 1, warp_n = wid >> 1;    // 2M x 4N
    int z = blockIdx.z;
    int m0 = blockIdx.y * RT, n0 = blockIdx.x * 128;

    const __nv_bfloat16* Ahi = ga.Ahi[z] + (size_t)m0 * DM;
    const __nv_bfloat16* Alo = ga.Alo[z] + (size_t)m0 * DM;
    const __nv_bfloat16* Whi = ga.Whi[z] + (size_t)n0 * DM;
    const __nv_bfloat16* Wlo = ga.Wlo[z] + (size_t)n0 * DM;
    const float* bias = ga.bias[z];
    float alpha = ga.alpha[z];

    uint32_t a_off = (uint32_t)(warp_m*(16*MB) + (lane & 15)) * PITCH_B + (lane >> 4) * 16;
    uint32_t b_off = (uint32_t)(warp_n*32 + (lane & 7) + (lane >> 4) * 8) * PITCH_B + ((lane >> 3) & 1) * 16;

    float acc[MB][4][4];
#pragma unroll
    for (int i = 0; i < MB; i++)
#pragma unroll
        for (int j = 0; j < 4; j++)
#pragma unroll
            for (int r = 0; r < 4; r++) acc[i][j][r] = 0.f;

    constexpr int J = MB*2 + 8;   // 16B chunks per thread per stage
    {
#pragma unroll
        for (int j = 0; j < J; j++) {
            int idx = tid + j * 256;
            const __nv_bfloat16* gp;
            uint32_t sp;
            if (idx < ACH) {
                int t2 = idx / (MB*256);
                int w = idx - t2 * (MB*256);
                int r = w >> 3, cc = w & 7;
                gp = (t2 ? Alo : Ahi) + (size_t)r * DM + cc*8;
                sp = sb + t2*A_T + (uint32_t)r * PITCH_B + cc*16;
            } else {
                int w = idx - ACH;
                int t2 = w >> 10;
                w &= 1023;
                int r = w >> 3, cc = w & 7;
                gp = (t2 ? Wlo : Whi) + (size_t)r * DM + cc*8;
                sp = sb + 2*A_T + t2*B_TILE + (uint32_t)r * PITCH_B + cc*16;
            }
            CP_ASYNC16(sp, gp);
        }
        CP_COMMIT();
    }

    for (int kc = 0; kc < NKC; kc++) {
        if (kc + 1 < NKC) {
            int k0 = (kc + 1) * 64;
            uint32_t stb = sb + ((kc + 1) & 1) * STB;
#pragma unroll
            for (int j = 0; j < J; j++) {
                int idx = tid + j * 256;
                const __nv_bfloat16* gp;
                uint32_t sp;
                if (idx < ACH) {
                    int t2 = idx / (MB*256);
                    int w = idx - t2 * (MB*256);
                    int r = w >> 3, cc = w & 7;
                    gp = (t2 ? Alo : Ahi) + (size_t)r * DM + k0 + cc*8;
                    sp = stb + t2*A_T + (uint32_t)r * PITCH_B + cc*16;
                } else {
                    int w = idx - ACH;
                    int t2 = w >> 10;
                    w &= 1023;
                    int r = w >> 3, cc = w & 7;
                    gp = (t2 ? Wlo : Whi) + (size_t)r * DM + k0 + cc*8;
                    sp = stb + 2*A_T + t2*B_TILE + (uint32_t)r * PITCH_B + cc*16;
                }
                CP_ASYNC16(sp, gp);
            }
            CP_COMMIT();
            CP_WAIT1();
        } else {
            CP_WAIT0();
        }
        __syncthreads();

        uint32_t st = sb + (kc & 1) * STB;
        uint32_t sAhi = st + a_off;
        uint32_t sAlo = st + A_T + a_off;
        uint32_t sBhi = st + 2*A_T + b_off;
        uint32_t sBlo = st + 2*A_T + B_TILE + b_off;

#pragma unroll
        for (int ks = 0; ks < 4; ks++) {
            uint32_t ah[MB][4], al[MB][4], bh[2][4], bl[2][4];
#pragma unroll
            for (int mi = 0; mi < MB; mi++) {
                LDSM4(ah[mi][0], ah[mi][1], ah[mi][2], ah[mi][3], sAhi + mi*16*PITCH_B + ks*32);
                LDSM4(al[mi][0], al[mi][1], al[mi][2], al[mi][3], sAlo + mi*16*PITCH_B + ks*32);
            }
#pragma unroll
            for (int nb = 0; nb < 2; nb++) {
                LDSM4(bh[nb][0], bh[nb][1], bh[nb][2], bh[nb][3], sBhi + nb*16*PITCH_B + ks*32);
                LDSM4(bl[nb][0], bl[nb][1], bl[nb][2], bl[nb][3], sBlo + nb*16*PITCH_B + ks*32);
            }
#pragma unroll
            for (int mi = 0; mi < MB; mi++)
#pragma unroll
                for (int nb = 0; nb < 2; nb++) {
                    MMA16816(acc[mi][nb*2+0], ah[mi], bh[nb][0], bh[nb][1]);
                    MMA16816(acc[mi][nb*2+1], ah[mi], bh[nb][2], bh[nb][3]);
                    MMA16816(acc[mi][nb*2+0], ah[mi], bl[nb][0], bl[nb][1]);
                    MMA16816(acc[mi][nb*2+1], ah[mi], bl[nb][2], bl[nb][3]);
                    MMA16816(acc[mi][nb*2+0], al[mi], bh[nb][0], bh[nb][1]);
                    MMA16816(acc[mi][nb*2+1], al[mi], bh[nb][2], bh[nb][3]);
                }
        }
        __syncthreads();
    }

    int g = lane >> 2, t = lane & 3;
    __nv_bfloat16* Chi = ga.Chi[z];
    float* C = ga.C[z];
    bool hk = (do_hk && z == 1);
    float* pr = (float*)smem;
    float* red = (float*)smem + 256;

#pragma unroll
    for (int mi = 0; mi < MB; mi++) {
#pragma unroll
        for (int half = 0; half < 2; half++) {
            int lrow = warp_m*(16*MB) + mi*16 + g + half*8;
            int row = m0 + lrow;
            float ss = 0.f;
#pragma unroll
            for (int nj = 0; nj < 4; nj++) {
                int col = n0 + warp_n*32 + nj*8 + t*2;
                float2 bb = *(const float2*)(bias + col);
                float ox = alpha * (acc[mi][nj][half*2+0] + bb.x);
                float oy = alpha * (acc[mi][nj][half*2+1] + bb.y);
                ss += ox*ox + oy*oy;
                if (C) *(float2*)(C + (size_t)row * DM + col) = make_float2(ox, oy);
                if (Chi) {
                    __nv_bfloat162 hv, lv;
                    split2(ox, oy, hv, lv);
                    *(__nv_bfloat162*)(Chi + (size_t)row * DM + col) = hv;
                    *(__nv_bfloat162*)(ga.Clo[z] + (size_t)row * DM + col) = lv;
                }
            }
            if (MB == 2 && hk) {
                ss += __shfl_xor_sync(0xffffffffu, ss, 1);
                ss += __shfl_xor_sync(0xffffffffu, ss, 2);
                if (t == 0) pr[lrow*4 + warp_n] = ss;
            }
        }
    }
    if (MB == 2 && hk) {
        __syncthreads();
        float hmax = -1e30f;
        if (tid < 128) {
            int row = tid >> 1, hd2 = tid & 1;
            float ss = pr[row*4 + hd2*2] + pr[row*4 + hd2*2 + 1];
            float hv = -0.5f * ss;
            g_hk[(size_t)((n0 >> 6) + hd2) * L + m0 + row] = hv;
            hmax = hv;
        }
#pragma unroll
        for (int o = 16; o; o >>= 1) hmax = fmaxf(hmax, __shfl_xor_sync(0xffffffffu, hmax, o));
        if (lane == 0) red[wid] = hmax;
        __syncthreads();
        if (tid == 0) {
            float mx = red[0];
#pragma unroll
            for (int i = 1; i < 8; i++) mx = fmaxf(mx, red[i]);
            atomicMax(&g_kstab, enc_f(mx));
        }
    }
}

#define HG_SMEM2 (2*(2*(64*PITCH_B) + 2*B_TILE))   // MB=2: 110592
#define HG_SMEM1 (2*(2*(32*PITCH_B) + 2*B_TILE))   // MB=1: 92160

// ---------------- rf projection + featurize (HMMA split-bf16) ----------------
#define PITCH2 144
#define TILE2 (128*PITCH2)
#define RF_SMEM (4*TILE2)

__global__ __launch_bounds__(256) void rf_proj_hmma()
{
    extern __shared__ char smem[];
    uint32_t sb = smem_u32(smem);
    int tid = threadIdx.x;
    int lane = tid & 31, wid = tid >> 5;
    int warp_m = wid & 1, warp_n = wid >> 1;
    int z = blockIdx.z;
    int h = z & 7;
    bool isq = z < 8;
    int m0 = blockIdx.y * 128;

    const __nv_bfloat16* Ahi = (isq ? g_qhi : g_khi) + (size_t)m0 * DM + h * DH;
    const __nv_bfloat16* Alo = (isq ? g_qlo : g_klo) + (size_t)m0 * DM + h * DH;

#pragma unroll
    for (int j = 0; j < 16; j++) {
        int idx = tid + j * 256;
        int tile = idx >> 10;
        int w = idx & 1023;
        int r = w >> 3, c = w & 7;
        const __nv_bfloat16* gp =
            (tile == 0) ? (Ahi + (size_t)r * DM + c*8) :
            (tile == 1) ? (Alo + (size_t)r * DM + c*8) :
            (tile == 2) ? (g_rfthi + (size_t)r * DH + c*8) :
                          (g_rftlo + (size_t)r * DH + c*8);
        uint32_t sp = sb + tile * TILE2 + (uint32_t)r * PITCH2 + c * 16;
        CP_ASYNC16(sp, gp);
    }
    CP_COMMIT();
    CP_WAIT0();
    __syncthreads();

    uint32_t a_off = (uint32_t)(warp_m*64 + (lane & 15)) * PITCH2 + (lane >> 4) * 16;
    uint32_t b_off = (uint32_t)(warp_n*32 + (lane & 7) + (lane >> 4) * 8) * PITCH2 + ((lane >> 3) & 1) * 16;
    uint32_t sAhi = sb + a_off;
    uint32_t sAlo = sb + TILE2 + a_off;
    uint32_t sBhi = sb + 2*TILE2 + b_off;
    uint32_t sBlo = sb + 3*TILE2 + b_off;

    float acc[4][4][4];
#pragma unroll
    for (int i = 0; i < 4; i++)
#pragma unroll
        for (int j = 0; j < 4; j++)
#pragma unroll
            for (int r = 0; r < 4; r++) acc[i][j][r] = 0.f;

#pragma unroll
    for (int ks = 0; ks < 4; ks++) {
        uint32_t ah[4][4], al[4][4], bh[2][4], bl[2][4];
#pragma unroll
        for (int mi = 0; mi < 4; mi++) {
            LDSM4(ah[mi][0], ah[mi][1], ah[mi][2], ah[mi][3], sAhi + mi*16*PITCH2 + ks*32);
            LDSM4(al[mi][0], al[mi][1], al[mi][2], al[mi][3], sAlo + mi*16*PITCH2 + ks*32);
        }
#pragma unroll
        for (int nb = 0; nb < 2; nb++) {
            LDSM4(bh[nb][0], bh[nb][1], bh[nb][2], bh[nb][3], sBhi + nb*16*PITCH2 + ks*32);
            LDSM4(bl[nb][0], bl[nb][1], bl[nb][2], bl[nb][3], sBlo + nb*16*PITCH2 + ks*32);
        }
#pragma unroll
        for (int mi = 0; mi < 4; mi++)
#pragma unroll
            for (int nb = 0; nb < 2; nb++) {
                MMA16816(acc[mi][nb*2+0], ah[mi], bh[nb][0], bh[nb][1]);
                MMA16816(acc[mi][nb*2+1], ah[mi], bh[nb][2], bh[nb][3]);
                MMA16816(acc[mi][nb*2+0], ah[mi], bl[nb][0], bl[nb][1]);
                MMA16816(acc[mi][nb*2+1], ah[mi], bl[nb][2], bl[nb][3]);
                MMA16816(acc[mi][nb*2+0], al[mi], bh[nb][0], bh[nb][1]);
                MMA16816(acc[mi][nb*2+1], al[mi], bh[nb][2], bh[nb][3]);
            }
    }

    float kst = isq ? 0.f : dec_f(g_kstab);
    int g = lane >> 2, t = lane & 3;
    __nv_bfloat16* Ph = (isq ? g_pqhi : g_pkhi) + (size_t)h * L * MF;
    __nv_bfloat16* Pl = (isq ? g_pqlo : g_pklo) + (size_t)h * L * MF;
#pragma unroll
    for (int mi = 0; mi < 4; mi++) {
#pragma unroll
        for (int half = 0; half < 2; half++) {
            int row = m0 + warp_m*64 + mi*16 + g + half*8;
            float off = isq ? 0.f : (g_hk[(size_t)h * L + row] - kst);
#pragma unroll
            for (int nj = 0; nj < 4; nj++) {
                int col = warp_n*32 + nj*8 + t*2;
                float ox = NC_COEF * (__expf(acc[mi][nj][half*2+0] + off) + KEPS);
                float oy = NC_COEF * (__expf(acc[mi][nj][half*2+1] + off) + KEPS);
                __nv_bfloat162 hv, lv;
                split2(ox, oy, hv, lv);
                *(__nv_bfloat162*)(Ph + (size_t)row * MF + col) = hv;
                *(__nv_bfloat162*)(Pl + (size_t)row * MF + col) = lv;
            }
        }
    }
}

// ---------------- chunk_state via HMMA ----------------
#define CSP_K 272
#define CSP_V 208
#define CS_KH 0
#define CS_KL (CS_KH + 64*CSP_K)
#define CS_VH (CS_KL + 64*CSP_K)
#define CS_VL (CS_VH + 64*CSP_V)
#define CS_TOTAL (CS_VL + 64*CSP_V)

__global__ __launch_bounds__(256) void chunk_state_hmma(){
    extern __shared__ char smc[];
    uint32_t sb = smem_u32(smc);
    int c = blockIdx.x, h = blockIdx.y;
    int tid = threadIdx.x, lane = tid & 31, wid = tid >> 5;
    int warp_m = wid >> 1, warp_n = wid & 1;
    int l0 = c * CHK;

    const __nv_bfloat16* kh = g_pkhi + ((size_t)h * L + l0) * MF;
    const __nv_bfloat16* kl = g_pklo + ((size_t)h * L + l0) * MF;
    for (int i = tid; i < 1024; i += 256) {
        int r = i >> 4, cc = i & 15;
        CP_ASYNC16(sb + CS_KH + (uint32_t)r*CSP_K + cc*16, kh + (size_t)r*MF + cc*8);
        CP_ASYNC16(sb + CS_KL + (uint32_t)r*CSP_K + cc*16, kl + (size_t)r*MF + cc*8);
    }
    for (int i = tid; i < 512; i += 256) {
        int r = i >> 3, cc = i & 7;
        CP_ASYNC16(sb + CS_VH + (uint32_t)r*CSP_V + cc*16, g_vhi + (size_t)(l0+r)*DM + h*DH + cc*8);
        CP_ASYNC16(sb + CS_VL + (uint32_t)r*CSP_V + cc*16, g_vlo + (size_t)(l0+r)*DM + h*DH + cc*8);
    }
    if (tid < 64) {
        uint4 zz = make_uint4(0u,0u,0u,0u);
#pragma unroll
        for (int q = 0; q < 4; q++) {
            *(uint4*)(smc + CS_VH + tid*CSP_V + 128 + q*16) = zz;
            *(uint4*)(smc + CS_VL + tid*CSP_V + 128 + q*16) = zz;
        }
        *((__nv_bfloat16*)(smc + CS_VH + tid*CSP_V) + 64) = __float2bfloat16(1.0f);
    }
    CP_COMMIT(); CP_WAIT0();
    __syncthreads();

    float acc[2][6][4];
#pragma unroll
    for (int i = 0; i < 2; i++)
#pragma unroll
        for (int j = 0; j < 6; j++)
#pragma unroll
            for (int r = 0; r < 4; r++) acc[i][j][r] = 0.f;

#pragma unroll
    for (int ks = 0; ks < 4; ks++) {
        uint32_t ah[2][4], al[2][4], bh[3][4], bl[3][4];
#pragma unroll
        for (int mi = 0; mi < 2; mi++) {
            uint32_t aoff = (uint32_t)(ks*16 + ((lane >> 4) & 1)*8 + (lane & 7)) * CSP_K
                          + (uint32_t)(warp_m*32 + mi*16 + ((lane >> 3) & 1)*8) * 2;
            LDSM4T(ah[mi][0], ah[mi][1], ah[mi][2], ah[mi][3], sb + CS_KH + aoff);
            LDSM4T(al[mi][0], al[mi][1], al[mi][2], al[mi][3], sb + CS_KL + aoff);
        }
#pragma unroll
        for (int nb = 0; nb < 3; nb++) {
            uint32_t boff = (uint32_t)(ks*16 + (lane & 15)) * CSP_V
                          + (uint32_t)(warp_n*48 + nb*16 + (lane >> 4)*8) * 2;
            LDSM4T(bh[nb][0], bh[nb][1], bh[nb][2], bh[nb][3], sb + CS_VH + boff);
            LDSM4T(bl[nb][0], bl[nb][1], bl[nb][2], bl[nb][3], sb + CS_VL + boff);
        }
#pragma unroll
        for (int mi = 0; mi < 2; mi++)
#pragma unroll
            for (int nb = 0; nb < 3; nb++) {
                MMA16816(acc[mi][nb*2+0], ah[mi], bh[nb][0], bh[nb][1]);
                MMA16816(acc[mi][nb*2+1], ah[mi], bh[nb][2], bh[nb][3]);
                MMA16816(acc[mi][nb*2+0], ah[mi], bl[nb][0], bl[nb][1]);
                MMA16816(acc[mi][nb*2+1], ah[mi], bl[nb][2], bl[nb][3]);
                MMA16816(acc[mi][nb*2+0], al[mi], bh[nb][0], bh[nb][1]);
                MMA16816(acc[mi][nb*2+1], al[mi], bh[nb][2], bh[nb][3]);
            }
    }

    int g = lane >> 2, t = lane & 3;
    float* Sdst = g_S + (size_t)(h*NC + c) * MF * DH;
    float* zdst = g_z + (size_t)(h*NC + c) * MF;
#pragma unroll
    for (int mi = 0; mi < 2; mi++) {
#pragma unroll
        for (int half = 0; half < 2; half++) {
            int m = warp_m*32 + mi*16 + g + half*8;
#pragma unroll
            for (int nj = 0; nj < 6; nj++) {
                int col = warp_n*48 + nj*8 + t*2;
                float x = acc[mi][nj][half*2+0];
                float y = acc[mi][nj][half*2+1];
                if (col < 64) {
                    *(float2*)(Sdst + (size_t)m * DH + col) = make_float2(x, y);
                } else if (col == 64) {
                    zdst[m] = x;
                }
            }
        }
    }
}

// ---------------- exclusive prefix over chunks (batched loads, MLP=32) ----------------
__global__ void prefix_scan(){
    int h = blockIdx.y;
    int idx = blockIdx.x * 256 + threadIdx.x;
    if (idx < MF * DH) {
        const float* p = g_S + (size_t)h * NC * MF * DH + idx;
        float v[NC];
#pragma unroll
        for (int c = 0; c < NC; c++) v[c] = p[(size_t)c * MF * DH];
        __nv_bfloat16* ph = g_Shi + (size_t)h * NC * MF * DH + idx;
        __nv_bfloat16* pl = g_Slo + (size_t)h * NC * MF * DH + idx;
        float prev = 0.f;
#pragma unroll
        for (int c = 0; c < NC; c++) {
            __nv_bfloat16 hh = __float2bfloat16(prev);
            ph[(size_t)c * MF * DH] = hh;
            pl[(size_t)c * MF * DH] = __float2bfloat16(prev - __bfloat162float(hh));
            prev += v[c];
        }
    } else if (idx < MF * DH + MF) {
        int m = idx - MF * DH;
        float* p = g_z + (size_t)h * NC * MF + m;
        float v[NC];
#pragma unroll
        for (int c = 0; c < NC; c++) v[c] = p[c * MF];
        float prev = 0.f;
#pragma unroll
        for (int c = 0; c < NC; c++) {
            p[c * MF] = prev;
            prev += v[c];
        }
    }
}

// ---------------- chunk_out via HMMA (split commit groups) ----------------
#define PQ 272
#define PV 144
#define CO_QH 0
#define CO_QL (CO_QH + 64*PQ)
#define CO_KH (CO_QL + 64*PQ)
#define CO_KL (CO_KH + 64*PQ)
#define CO_VH (CO_KL + 64*PQ)
#define CO_VL (CO_VH + 64*PV)
#define CO_SH (CO_VL + 64*PV)
#define CO_SL (CO_SH + 128*PV)
#define CO_AH (CO_SL + 128*PV)
#define CO_AL (CO_AH + 64*PV)
#define CO_ZB (CO_AL + 64*PV)
#define CO_PR (CO_ZB + 512)
#define CO_RS (CO_PR + 64*4*4)
#define CO_TOTAL (CO_RS + 256)

__global__ __launch_bounds__(256) void chunk_out_hmma(){
    extern __shared__ char smc[];
    uint32_t sb = smem_u32(smc);
    int c = blockIdx.x, h = blockIdx.y;
    int tid = threadIdx.x, lane = tid & 31, wid = tid >> 5;
    int warp_m = wid & 1, warp_n = wid >> 1;
    int l0 = c * CHK;

    {
        const __nv_bfloat16* pqh = g_pqhi + ((size_t)h * L + l0) * MF;
        const __nv_bfloat16* pql = g_pqlo + ((size_t)h * L + l0) * MF;
        const __nv_bfloat16* pkh = g_pkhi + ((size_t)h * L + l0) * MF;
        const __nv_bfloat16* pkl = g_pklo + ((size_t)h * L + l0) * MF;
        for (int i = tid; i < 1024; i += 256) {
            int r = i >> 4, cc = i & 15;
            CP_ASYNC16(sb + CO_QH + r*PQ + cc*16, pqh + (size_t)r*MF + cc*8);
            CP_ASYNC16(sb + CO_QL + r*PQ + cc*16, pql + (size_t)r*MF + cc*8);
            CP_ASYNC16(sb + CO_KH + r*PQ + cc*16, pkh + (size_t)r*MF + cc*8);
            CP_ASYNC16(sb + CO_KL + r*PQ + cc*16, pkl + (size_t)r*MF + cc*8);
        }
        CP_COMMIT();
        for (int i = tid; i < 512; i += 256) {
            int r = i >> 3, cc = i & 7;
            CP_ASYNC16(sb + CO_VH + r*PV + cc*16, g_vhi + (size_t)(l0 + r)*DM + h*DH + cc*8);
            CP_ASYNC16(sb + CO_VL + r*PV + cc*16, g_vlo + (size_t)(l0 + r)*DM + h*DH + cc*8);
        }
        const __nv_bfloat16* sh = g_Shi + (size_t)(h*NC + c)*MF*DH;
        const __nv_bfloat16* sl = g_Slo + (size_t)(h*NC + c)*MF*DH;
        for (int i = tid; i < 1024; i += 256) {
            int r = i >> 3, cc = i & 7;
            CP_ASYNC16(sb + CO_SH + r*PV + cc*16, sh + (size_t)r*DH + cc*8);
            CP_ASYNC16(sb + CO_SL + r*PV + cc*16, sl + (size_t)r*DH + cc*8);
        }
        if (tid < 32) CP_ASYNC16(sb + CO_ZB + tid*16, g_z + (size_t)(h*NC + c)*MF + tid*4);
        CP_COMMIT();
        CP_WAIT1();
    }
    __syncthreads();

    uint32_t a_off = (uint32_t)(warp_m*32 + (lane & 15)) * PQ + (lane >> 4) * 16;
    uint32_t b_off = (uint32_t)(warp_n*16 + (lane & 7) + (lane >> 4) * 8) * PQ + ((lane >> 3) & 1) * 16;

    float acc[2][2][4];
#pragma unroll
    for (int i = 0; i < 2; i++)
#pragma unroll
        for (int j = 0; j < 2; j++)
#pragma unroll
            for (int r = 0; r < 4; r++) acc[i][j][r] = 0.f;

#pragma unroll
    for (int ks = 0; ks < 8; ks++) {
        uint32_t ah[2][4], al[2][4], bh[4], bl[4];
#pragma unroll
        for (int mi = 0; mi < 2; mi++) {
            LDSM4(ah[mi][0], ah[mi][1], ah[mi][2], ah[mi][3], sb + CO_QH + a_off + mi*16*PQ + ks*32);
            LDSM4(al[mi][0], al[mi][1], al[mi][2], al[mi][3], sb + CO_QL + a_off + mi*16*PQ + ks*32);
        }
        LDSM4(bh[0], bh[1], bh[2], bh[3], sb + CO_KH + b_off + ks*32);
        LDSM4(bl[0], bl[1], bl[2], bl[3], sb + CO_KL + b_off + ks*32);
#pragma unroll
        for (int mi = 0; mi < 2; mi++) {
            MMA16816(acc[mi][0], ah[mi], bh[0], bh[1]);
            MMA16816(acc[mi][1], ah[mi], bh[2], bh[3]);
            MMA16816(acc[mi][0], ah[mi], bl[0], bl[1]);
            MMA16816(acc[mi][1], ah[mi], bl[2], bl[3]);
            MMA16816(acc[mi][0], al[mi], bh[0], bh[1]);
            MMA16816(acc[mi][1], al[mi], bh[2], bh[3]);
        }
    }
    CP_WAIT0();

    int g = lane >> 2, t = lane & 3;
    float* pr = (float*)(smc + CO_PR);
#pragma unroll
    for (int mi = 0; mi < 2; mi++) {
#pragma unroll
        for (int half = 0; half < 2; half++) {
            int row = warp_m*32 + mi*16 + g + half*8;
            float rsum = 0.f;
#pragma unroll
            for (int nj = 0; nj < 2; nj++) {
                int col = warp_n*16 + nj*8 + t*2;
                float x = (col     <= row) ? acc[mi][nj][half*2+0] : 0.f;
                float y = (col + 1 <= row) ? acc[mi][nj][half*2+1] : 0.f;
                rsum += x + y;
                __nv_bfloat162 hv, lv;
                split2(x, y, hv, lv);
                *(__nv_bfloat162*)(smc + CO_AH + row*PV + col*2) = hv;
                *(__nv_bfloat162*)(smc + CO_AL + row*PV + col*2) = lv;
            }
            rsum += __shfl_xor_sync(0xffffffffu, rsum, 1);
            rsum += __shfl_xor_sync(0xffffffffu, rsum, 2);
            if (t == 0) pr[row*4 + warp_n] = rsum;
        }
    }
    __syncthreads();

    if (tid < 64) {
        float s = pr[tid*4+0] + pr[tid*4+1] + pr[tid*4+2] + pr[tid*4+3];
        const float* zf = (const float*)(smc + CO_ZB);
#pragma unroll 8
        for (int m2 = 0; m2 < 64; m2++) {
            __nv_bfloat162 qh2 = *(const __nv_bfloat162*)(smc + CO_QH + tid*PQ + m2*4);
            __nv_bfloat162 ql2 = *(const __nv_bfloat162*)(smc + CO_QL + tid*PQ + m2*4);
            float2 z2 = *(const float2*)(zf + m2*2);
            s += (__bfloat162float(qh2.x) + __bfloat162float(ql2.x)) * z2.x
               + (__bfloat162float(qh2.y) + __bfloat162float(ql2.y)) * z2.y;
        }
        ((float*)(smc + CO_RS))[tid] = s + DEPS;
    }

    float o[2][2][4];
#pragma unroll
    for (int i = 0; i < 2; i++)
#pragma unroll
        for (int j = 0; j < 2; j++)
#pragma unroll
            for (int r = 0; r < 4; r++) o[i][j][r] = 0.f;

    uint32_t a2_off = (uint32_t)(warp_m*32 + (lane & 15)) * PV + (lane >> 4) * 16;
    uint32_t bt_off = (uint32_t)(lane & 15) * PV + (warp_n*16 + (lane >> 4) * 8) * 2;

#pragma unroll
    for (int ks = 0; ks < 4; ks++) {
        uint32_t ah[2][4], al[2][4], bh[4], bl[4];
#pragma unroll
        for (int mi = 0; mi < 2; mi++) {
            LDSM4(ah[mi][0], ah[mi][1], ah[mi][2], ah[mi][3], sb + CO_AH + a2_off + mi*16*PV + ks*32);
            LDSM4(al[mi][0], al[mi][1], al[mi][2], al[mi][3], sb + CO_AL + a2_off + mi*16*PV + ks*32);
        }
        LDSM4T(bh[0], bh[1], bh[2], bh[3], sb + CO_VH + bt_off + ks*16*PV);
        LDSM4T(bl[0], bl[1], bl[2], bl[3], sb + CO_VL + bt_off + ks*16*PV);
#pragma unroll
        for (int mi = 0; mi < 2; mi++) {
            MMA16816(o[mi][0], ah[mi], bh[0], bh[1]);
            MMA16816(o[mi][1], ah[mi], bh[2], bh[3]);
            MMA16816(o[mi][0], ah[mi], bl[0], bl[1]);
            MMA16816(o[mi][1], ah[mi], bl[2], bl[3]);
            MMA16816(o[mi][0], al[mi], bh[0], bh[1]);
            MMA16816(o[mi][1], al[mi], bh[2], bh[3]);
        }
    }
#pragma unroll
    for (int ks = 0; ks < 8; ks++) {
        uint32_t ah[2][4], al[2][4], bh[4], bl[4];
#pragma unroll
        for (int mi = 0; mi < 2; mi++) {
            LDSM4(ah[mi][0], ah[mi][1], ah[mi][2], ah[mi][3], sb + CO_QH + a_off + mi*16*PQ + ks*32);
            LDSM4(al[mi][0], al[mi][1], al[mi][2], al[mi][3], sb + CO_QL + a_off + mi*16*PQ + ks*32);
        }
        LDSM4T(bh[0], bh[1], bh[2], bh[3], sb + CO_SH + bt_off + ks*16*PV);
        LDSM4T(bl[0], bl[1], bl[2], bl[3], sb + CO_SL + bt_off + ks*16*PV);
#pragma unroll
        for (int mi = 0; mi < 2; mi++) {
            MMA16816(o[mi][0], ah[mi], bh[0], bh[1]);
            MMA16816(o[mi][1], ah[mi], bh[2], bh[3]);
            MMA16816(o[mi][0], ah[mi], bl[0], bl[1]);
            MMA16816(o[mi][1], ah[mi], bl[2], bl[3]);
            MMA16816(o[mi][0], al[mi], bh[0], bh[1]);
            MMA16816(o[mi][1], al[mi], bh[2], bh[3]);
        }
    }
    __syncthreads();

    const float* rs = (const float*)(smc + CO_RS);
#pragma unroll
    for (int mi = 0; mi < 2; mi++) {
#pragma unroll
        for (int half = 0; half < 2; half++) {
            int row = warp_m*32 + mi*16 + g + half*8;
            float inv = 1.0f / rs[row];
#pragma unroll
            for (int nj = 0; nj < 2; nj++) {
                int col = warp_n*16 + nj*8 + t*2;
                float ox = o[mi][nj][half*2+0] * inv;
                float oy = o[mi][nj][half*2+1] * inv;
                __nv_bfloat162 hv, lv;
                split2(ox, oy, hv, lv);
                size_t off = (size_t)(l0 + row) * DM + h*DH + col;
                *(__nv_bfloat162*)(g_bhi_ctx + off) = hv;
                *(__nv_bfloat162*)(g_blo_ctx + off) = lv;
            }
        }
    }
}

// ---------------- launcher ----------------
extern "C" void kernel_launch(void* const* d_in, const int* in_sizes, int n_in,
                              void* d_out, int out_size)
{
    const float* query = (const float*)d_in[0];
    const float* key_i = (const float*)d_in[1];
    const float* value = (const float*)d_in[2];
    const float* Wq = (const float*)d_in[3];
    const float* bq = (const float*)d_in[4];
    const float* Wk = (const float*)d_in[5];
    const float* bk = (const float*)d_in[6];
    const float* Wv = (const float*)d_in[7];
    const float* bv = (const float*)d_in[8];
    const float* Wo = (const float*)d_in[9];
    const float* bo = (const float*)d_in[10];
    const float* rf = (const float*)d_in[11];
    float* out = (float*)d_out;

    void* p;
    cudaGetSymbolAddress(&p, g_bhi_in);  __nv_bfloat16* bhi_in = (__nv_bfloat16*)p;
    cudaGetSymbolAddress(&p, g_blo_in);  __nv_bfloat16* blo_in = (__nv_bfloat16*)p;
    cudaGetSymbolAddress(&p, g_bhi_w);   __nv_bfloat16* bhi_w  = (__nv_bfloat16*)p;
    cudaGetSymbolAddress(&p, g_blo_w);   __nv_bfloat16* blo_w  = (__nv_bfloat16*)p;
    cudaGetSymbolAddress(&p, g_bhi_ctx); __nv_bfloat16* bhi_c  = (__nv_bfloat16*)p;
    cudaGetSymbolAddress(&p, g_blo_ctx); __nv_bfloat16* blo_c  = (__nv_bfloat16*)p;
    cudaGetSymbolAddress(&p, g_qhi);     __nv_bfloat16* qhi    = (__nv_bfloat16*)p;
    cudaGetSymbolAddress(&p, g_qlo);     __nv_bfloat16* qlo    = (__nv_bfloat16*)p;
    cudaGetSymbolAddress(&p, g_khi);     __nv_bfloat16* khi    = (__nv_bfloat16*)p;
    cudaGetSymbolAddress(&p, g_klo);     __nv_bfloat16* klo    = (__nv_bfloat16*)p;
    cudaGetSymbolAddress(&p, g_vhi);     __nv_bfloat16* vhi    = (__nv_bfloat16*)p;
    cudaGetSymbolAddress(&p, g_vlo);     __nv_bfloat16* vlo    = (__nv_bfloat16*)p;

    CV cv;
    cv.src[0]=query; cv.hi[0]=bhi_in;          cv.lo[0]=blo_in;          cv.n[0]=L*DM;
    cv.src[1]=key_i; cv.hi[1]=bhi_in+L*DM;     cv.lo[1]=blo_in+L*DM;     cv.n[1]=L*DM;
    cv.src[2]=value; cv.hi[2]=bhi_in+2*L*DM;   cv.lo[2]=blo_in+2*L*DM;   cv.n[2]=L*DM;
    cv.src[3]=Wq;    cv.hi[3]=bhi_w;           cv.lo[3]=blo_w;           cv.n[3]=DM*DM;
    cv.src[4]=Wk;    cv.hi[4]=bhi_w+DM*DM;     cv.lo[4]=blo_w+DM*DM;     cv.n[4]=DM*DM;
    cv.src[5]=Wv;    cv.hi[5]=bhi_w+2*DM*DM;   cv.lo[5]=blo_w+2*DM*DM;   cv.n[5]=DM*DM;
    cv.src[6]=Wo;    cv.hi[6]=bhi_w+3*DM*DM;   cv.lo[6]=blo_w+3*DM*DM;   cv.n[6]=DM*DM;
    cv.cnt = 7;
    convert_split<<<dim3((L*DM)/1024, 8), 256>>>(cv, rf);

    cudaFuncSetAttribute(hmma_gemm<2>, cudaFuncAttributeMaxDynamicSharedMemorySize, HG_SMEM2);
    cudaFuncSetAttribute(hmma_gemm<1>, cudaFuncAttributeMaxDynamicSharedMemorySize, HG_SMEM1);
    cudaFuncSetAttribute(rf_proj_hmma, cudaFuncAttributeMaxDynamicSharedMemorySize, RF_SMEM);
    cudaFuncSetAttribute(chunk_state_hmma, cudaFuncAttributeMaxDynamicSharedMemorySize, CS_TOTAL);
    cudaFuncSetAttribute(chunk_out_hmma, cudaFuncAttributeMaxDynamicSharedMemorySize, CO_TOTAL);

    // QKV projections (MB=2, hk fused into z==1 epilogue)
    MMArgs mq;
    mq.Ahi[0]=bhi_in;        mq.Alo[0]=blo_in;        mq.Whi[0]=bhi_w;        mq.Wlo[0]=blo_w;        mq.bias[0]=bq; mq.C[0]=nullptr; mq.Chi[0]=qhi; mq.Clo[0]=qlo; mq.alpha[0]=SCALE_QK;
    mq.Ahi[1]=bhi_in+L*DM;   mq.Alo[1]=blo_in+L*DM;   mq.Whi[1]=bhi_w+DM*DM;  mq.Wlo[1]=blo_w+DM*DM;  mq.bias[1]=bk; mq.C[1]=nullptr; mq.Chi[1]=khi; mq.Clo[1]=klo; mq.alpha[1]=SCALE_QK;
    mq.Ahi[2]=bhi_in+2*L*DM; mq.Alo[2]=blo_in+2*L*DM; mq.Whi[2]=bhi_w+2*DM*DM;mq.Wlo[2]=blo_w+2*DM*DM;mq.bias[2]=bv; mq.C[2]=nullptr; mq.Chi[2]=vhi; mq.Clo[2]=vlo; mq.alpha[2]=1.0f;
    hmma_gemm<2><<<dim3(DM/128, L/64, 3), 256, HG_SMEM2>>>(mq, 1);

    rf_proj_hmma<<<dim3(1, L/128, 16), 256, RF_SMEM>>>();

    chunk_state_hmma<<<dim3(NC, NH), 256, CS_TOTAL>>>();
    prefix_scan<<<dim3((MF*DH + MF + 255)/256, NH), 256>>>();
    chunk_out_hmma<<<dim3(NC, NH), 256, CO_TOTAL>>>();

    // output projection (MB=1: 256 CTAs, 1.7 waves)
    MMArgs mo;
    mo.Ahi[0]=bhi_c; mo.Alo[0]=blo_c; mo.Whi[0]=bhi_w+3*DM*DM; mo.Wlo[0]=blo_w+3*DM*DM; mo.bias[0]=bo; mo.C[0]=out; mo.Chi[0]=nullptr; mo.Clo[0]=nullptr; mo.alpha[0]=1.0f;
    mo.Ahi[1]=mo.Ahi[0]; mo.Alo[1]=mo.Alo[0]; mo.Whi[1]=mo.Whi[0]; mo.Wlo[1]=mo.Wlo[0]; mo.bias[1]=bo; mo.C[1]=out; mo.Chi[1]=nullptr; mo.Clo[1]=nullptr; mo.alpha[1]=1.0f;
    mo.Ahi[2]=mo.Ahi[0]; mo.Alo[2]=mo.Alo[0]; mo.Whi[2]=mo.Whi[0]; mo.Wlo[2]=mo.Wlo[0]; mo.bias[2]=bo; mo.C[2]=out; mo.Chi[2]=nullptr; mo.Clo[2]=nullptr; mo.alpha[2]=1.0f;
    hmma_gemm<1><<<dim3(DM/128, L/32, 1), 256, HG_SMEM1>>>(mo, 0);
}

// round 15
// speedup vs baseline: 1.0880x; 1.0500x over previous
#include <cuda_runtime.h>
#include <cuda_bf16.h>
#include <math.h>
#include <stdint.h>

#define L 2048
#define DM 512
#define NH 8
#define DH 64
#define MF 128
#define CHK 64
#define NC (L/CHK)   // 32

#define SCALE_QK 0.2102241038134287f
#define NC_COEF  0.08838834764831845f
#define KEPS 1e-4f
#define DEPS 1e-6f

// ---------------- device scratch ----------------
__device__ float g_hk[NH*L];
__device__ unsigned g_kstab;
__device__ float g_S[NH*NC*MF*DH];
__device__ float g_z[NH*NC*MF];

__device__ __nv_bfloat16 g_bhi_w[4][DM*DM];
__device__ __nv_bfloat16 g_blo_w[4][DM*DM];
__device__ __nv_bfloat16 g_bhi_ctx[L*DM];
__device__ __nv_bfloat16 g_blo_ctx[L*DM];
__device__ __nv_bfloat16 g_qhi[L*DM];
__device__ __nv_bfloat16 g_qlo[L*DM];
__device__ __nv_bfloat16 g_khi[L*DM];
__device__ __nv_bfloat16 g_klo[L*DM];
__device__ __nv_bfloat16 g_rfthi[MF*DH];
__device__ __nv_bfloat16 g_rftlo[MF*DH];
__device__ __nv_bfloat16 g_pqhi[NH*L*MF];
__device__ __nv_bfloat16 g_pqlo[NH*L*MF];
__device__ __nv_bfloat16 g_pkhi[NH*L*MF];
__device__ __nv_bfloat16 g_pklo[NH*L*MF];
__device__ __nv_bfloat16 g_vhi[L*DM];
__device__ __nv_bfloat16 g_vlo[L*DM];
__device__ __nv_bfloat16 g_Shi[NH*NC*MF*DH];
__device__ __nv_bfloat16 g_Slo[NH*NC*MF*DH];

__device__ __forceinline__ unsigned enc_f(float f){
    unsigned u = __float_as_uint(f);
    return (u & 0x80000000u) ? ~u : (u | 0x80000000u);
}
__device__ __forceinline__ float dec_f(unsigned k){
    unsigned u = (k & 0x80000000u) ? (k ^ 0x80000000u) : ~k;
    return __uint_as_float(u);
}

__device__ __forceinline__ uint32_t smem_u32(const void* p) {
    uint32_t a;
    asm("{ .reg .u64 t; cvta.to.shared.u64 t, %1; cvt.u32.u64 %0, t; }" : "=r"(a) : "l"(p));
    return a;
}

#define CP_ASYNC16(sa, gp) asm volatile("cp.async.cg.shared.global [%0], [%1], 16;" :: "r"(sa), "l"(gp))
#define CP_COMMIT()        asm volatile("cp.async.commit_group;")
#define CP_WAIT1()         asm volatile("cp.async.wait_group 1;")
#define CP_WAIT0()         asm volatile("cp.async.wait_group 0;")

#define LDSM4(r0,r1,r2,r3,a) \
    asm volatile("ldmatrix.sync.aligned.m8n8.x4.shared.b16 {%0,%1,%2,%3}, [%4];" \
        : "=r"(r0),"=r"(r1),"=r"(r2),"=r"(r3) : "r"(a))
#define LDSM4T(r0,r1,r2,r3,a) \
    asm volatile("ldmatrix.sync.aligned.m8n8.x4.trans.shared.b16 {%0,%1,%2,%3}, [%4];" \
        : "=r"(r0),"=r"(r1),"=r"(r2),"=r"(r3) : "r"(a))

#define MMA16816(d,a,b0,b1) \
    asm volatile("mma.sync.aligned.m16n8k16.row.col.f32.bf16.bf16.f32 " \
        "{%0,%1,%2,%3},{%4,%5,%6,%7},{%8,%9},{%0,%1,%2,%3};" \
        : "+f"((d)[0]),"+f"((d)[1]),"+f"((d)[2]),"+f"((d)[3]) \
        : "r"((a)[0]),"r"((a)[1]),"r"((a)[2]),"r"((a)[3]),"r"(b0),"r"(b1))

__device__ __forceinline__ void split2(float x, float y, __nv_bfloat162& hv, __nv_bfloat162& lv){
    __nv_bfloat16 hx = __float2bfloat16(x);
    __nv_bfloat16 hy = __float2bfloat16(y);
    hv.x = hx; hv.y = hy;
    lv.x = __float2bfloat16(x - __bfloat162float(hx));
    lv.y = __float2bfloat16(y - __bfloat162float(hy));
}

// ---------------- fp32 -> (bf16 hi, bf16 lo) converter (weights + rf + kstab) ----------------
struct CV { const float* src[8]; __nv_bfloat16* hi[8]; __nv_bfloat16* lo[8]; int n[8]; int cnt; };
__global__ void convert_split(CV cv, const float* __restrict__ rf){
    int t = blockIdx.y;
    if (t == cv.cnt) {
        if (blockIdx.x == 0 && threadIdx.x == 0) g_kstab = 0u;
        int i0 = blockIdx.x * 1024 + threadIdx.x;
#pragma unroll
        for (int j = 0; j < 4; j++) {
            int i = i0 + j * 256;
            if (i < MF * DH) {
                int m = i >> 6, d = i & 63;
                float x = rf[(size_t)d * MF + m];
                __nv_bfloat16 h = __float2bfloat16(x);
                g_rfthi[(size_t)m * DH + d] = h;
                g_rftlo[(size_t)m * DH + d] = __float2bfloat16(x - __bfloat162float(h));
            }
        }
        return;
    }
    int n = cv.n[t];
    const float* s = cv.src[t];
    __nv_bfloat16* ph = cv.hi[t];
    __nv_bfloat16* pl = cv.lo[t];
    int i0 = blockIdx.x * 1024 + threadIdx.x;
#pragma unroll
    for (int j = 0; j < 4; j++) {
        int i = i0 + j * 256;
        if (i < n) {
            float x = s[i];
            __nv_bfloat16 h = __float2bfloat16(x);
            ph[i] = h;
            pl[i] = __float2bfloat16(x - __bfloat162float(h));
        }
    }
}

// ---------------- split-bf16 HMMA GEMM, templated M-tile; A from fp32 or bf16 ----------------
#define PITCH_B 144
#define B_TILE (128*PITCH_B)         // 18432
#define NKC 8

struct MMArgs {
    const float* Af[3];                            // fp32 A source (if non-null)
    const __nv_bfloat16* Ahi[3]; const __nv_bfloat16* Alo[3];   // bf16 A source otherwise
    const __nv_bfloat16* Whi[3]; const __nv_bfloat16* Wlo[3];
    const float* bias[3]; float* C[3];
    __nv_bfloat16* Chi[3]; __nv_bfloat16* Clo[3];
    float alpha[3];
};

template<int MB, bool AF32>
__global__ __launch_bounds__(256, 2) void hmma_gemm(MMArgs ga, int do_hk)
{
    constexpr int RT = MB * 32;
    constexpr int A_T = RT * PITCH_B;
    constexpr int STB = 2*A_T + 2*B_TILE;
    constexpr int ACH = 2 * MB * 256;

    extern __shared__ char smem[];
    uint32_t sb = smem_u32(smem);
    int tid = threadIdx.x;
    int lane = tid & 31, wid = tid >> 5;
    int warp_m = wid & 1, warp_n = wid >> 1;
    int z = blockIdx.z;
    int m0 = blockIdx.y * RT, n0 = blockIdx.x * 128;

    const float* Af = AF32 ? (ga.Af[z] + (size_t)m0 * DM) : nullptr;
    const __nv_bfloat16* Ahi = AF32 ? nullptr : (ga.Ahi[z] + (size_t)m0 * DM);
    const __nv_bfloat16* Alo = AF32 ? nullptr : (ga.Alo[z] + (size_t)m0 * DM);
    const __nv_bfloat16* Whi = ga.Whi[z] + (size_t)n0 * DM;
    const __nv_bfloat16* Wlo = ga.Wlo[z] + (size_t)n0 * DM;
    const float* bias = ga.bias[z];
    float alpha = ga.alpha[z];

    uint32_t a_off = (uint32_t)(warp_m*(16*MB) + (lane & 15)) * PITCH_B + (lane >> 4) * 16;
    uint32_t b_off = (uint32_t)(warp_n*32 + (lane & 7) + (lane >> 4) * 8) * PITCH_B + ((lane >> 3) & 1) * 16;

    float acc[MB][4][4];
#pragma unroll
    for (int i = 0; i < MB; i++)
#pragma unroll
        for (int j = 0; j < 4; j++)
#pragma unroll
            for (int r = 0; r < 4; r++) acc[i][j][r] = 0.f;

    // ---- per-stage loaders ----
    auto load_stage = [&](int k0, uint32_t so){
        if (AF32) {
            // A: fp32 -> split -> STS (MB*2 float4 per thread)
#pragma unroll
            for (int j = 0; j < MB*2; j++) {
                int idx = tid + j * 256;             // [0, MB*512)
                int r = idx >> 4, c4 = idx & 15;
                float4 v = *(const float4*)(Af + (size_t)r * DM + k0 + c4*4);
                __nv_bfloat162 h0, l0, h1, l1;
                split2(v.x, v.y, h0, l0);
                split2(v.z, v.w, h1, l1);
                uint2 hu, lu;
                hu.x = *(uint32_t*)&h0; hu.y = *(uint32_t*)&h1;
                lu.x = *(uint32_t*)&l0; lu.y = *(uint32_t*)&l1;
                size_t doff = so + (size_t)r * PITCH_B + c4*8;
                *(uint2*)(smem + doff) = hu;
                *(uint2*)(smem + doff + A_T) = lu;
            }
        } else {
#pragma unroll
            for (int j = 0; j < MB*2; j++) {
                int idx = tid + j * 256;
                int t2 = idx / (MB*256);
                int w = idx - t2 * (MB*256);
                int r = w >> 3, cc = w & 7;
                const __nv_bfloat16* gp = (t2 ? Alo : Ahi) + (size_t)r * DM + k0 + cc*8;
                CP_ASYNC16(sb + (uint32_t)so + t2*A_T + (uint32_t)r * PITCH_B + cc*16, gp);
            }
        }
        // B: cp.async (8 chunks per thread)
#pragma unroll
        for (int j = 0; j < 8; j++) {
            int idx = tid + j * 256;                 // [0, 2048)
            int t2 = idx >> 10;
            int w = idx & 1023;
            int r = w >> 3, cc = w & 7;
            const __nv_bfloat16* gp = (t2 ? Wlo : Whi) + (size_t)r * DM + k0 + cc*8;
            CP_ASYNC16(sb + (uint32_t)so + 2*A_T + t2*B_TILE + (uint32_t)r * PITCH_B + cc*16, gp);
        }
        CP_COMMIT();
    };

    load_stage(0, 0);

    for (int kc = 0; kc < NKC; kc++) {
        if (kc + 1 < NKC) {
            load_stage((kc + 1) * 64, ((kc + 1) & 1) * STB);
            CP_WAIT1();
        } else {
            CP_WAIT0();
        }
        __syncthreads();

        uint32_t st = sb + (kc & 1) * STB;
        uint32_t sAhi = st + a_off;
        uint32_t sAlo = st + A_T + a_off;
        uint32_t sBhi = st + 2*A_T + b_off;
        uint32_t sBlo = st + 2*A_T + B_TILE + b_off;

#pragma unroll
        for (int ks = 0; ks < 4; ks++) {
            uint32_t ah[MB][4], al[MB][4], bh[2][4], bl[2][4];
#pragma unroll
            for (int mi = 0; mi < MB; mi++) {
                LDSM4(ah[mi][0], ah[mi][1], ah[mi][2], ah[mi][3], sAhi + mi*16*PITCH_B + ks*32);
                LDSM4(al[mi][0], al[mi][1], al[mi][2], al[mi][3], sAlo + mi*16*PITCH_B + ks*32);
            }
#pragma unroll
            for (int nb = 0; nb < 2; nb++) {
                LDSM4(bh[nb][0], bh[nb][1], bh[nb][2], bh[nb][3], sBhi + nb*16*PITCH_B + ks*32);
                LDSM4(bl[nb][0], bl[nb][1], bl[nb][2], bl[nb][3], sBlo + nb*16*PITCH_B + ks*32);
            }
#pragma unroll
            for (int mi = 0; mi < MB; mi++)
#pragma unroll
                for (int nb = 0; nb < 2; nb++) {
                    MMA16816(acc[mi][nb*2+0], ah[mi], bh[nb][0], bh[nb][1]);
                    MMA16816(acc[mi][nb*2+1], ah[mi], bh[nb][2], bh[nb][3]);
                    MMA16816(acc[mi][nb*2+0], ah[mi], bl[nb][0], bl[nb][1]);
                    MMA16816(acc[mi][nb*2+1], ah[mi], bl[nb][2], bl[nb][3]);
                    MMA16816(acc[mi][nb*2+0], al[mi], bh[nb][0], bh[nb][1]);
                    MMA16816(acc[mi][nb*2+1], al[mi], bh[nb][2], bh[nb][3]);
                }
        }
        __syncthreads();
    }

    int g = lane >> 2, t = lane & 3;
    __nv_bfloat16* Chi = ga.Chi[z];
    float* C = ga.C[z];
    bool hk = (do_hk && z == 1);
    float* pr = (float*)smem;
    float* red = (float*)smem + 256;

#pragma unroll
    for (int mi = 0; mi < MB; mi++) {
#pragma unroll
        for (int half = 0; half < 2; half++) {
            int lrow = warp_m*(16*MB) + mi*16 + g + half*8;
            int row = m0 + lrow;
            float ss = 0.f;
#pragma unroll
            for (int nj = 0; nj < 4; nj++) {
                int col = n0 + warp_n*32 + nj*8 + t*2;
                float2 bb = *(const float2*)(bias + col);
                float ox = alpha * (acc[mi][nj][half*2+0] + bb.x);
                float oy = alpha * (acc[mi][nj][half*2+1] + bb.y);
                ss += ox*ox + oy*oy;
                if (C) *(float2*)(C + (size_t)row * DM + col) = make_float2(ox, oy);
                if (Chi) {
                    __nv_bfloat162 hv, lv;
                    split2(ox, oy, hv, lv);
                    *(__nv_bfloat162*)(Chi + (size_t)row * DM + col) = hv;
                    *(__nv_bfloat162*)(ga.Clo[z] + (size_t)row * DM + col) = lv;
                }
            }
            if (MB == 2 && hk) {
                ss += __shfl_xor_sync(0xffffffffu, ss, 1);
                ss += __shfl_xor_sync(0xffffffffu, ss, 2);
                if (t == 0) pr[lrow*4 + warp_n] = ss;
            }
        }
    }
    if (MB == 2 && hk) {
        __syncthreads();
        float hmax = -1e30f;
        if (tid < 128) {
            int row = tid >> 1, hd2 = tid & 1;
            float ss = pr[row*4 + hd2*2] + pr[row*4 + hd2*2 + 1];
            float hv = -0.5f * ss;
            g_hk[(size_t)((n0 >> 6) + hd2) * L + m0 + row] = hv;
            hmax = hv;
        }
#pragma unroll
        for (int o = 16; o; o >>= 1) hmax = fmaxf(hmax, __shfl_xor_sync(0xffffffffu, hmax, o));
        if (lane == 0) red[wid] = hmax;
        __syncthreads();
        if (tid == 0) {
            float mx = red[0];
#pragma unroll
            for (int i = 1; i < 8; i++) mx = fmaxf(mx, red[i]);
            atomicMax(&g_kstab, enc_f(mx));
        }
    }
}

#define HG_SMEM2 (2*(2*(64*PITCH_B) + 2*B_TILE))   // MB=2: 110592
#define HG_SMEM1 (2*(2*(32*PITCH_B) + 2*B_TILE))   // MB=1: 92160

// ---------------- rf projection + featurize (HMMA split-bf16) ----------------
#define PITCH2 144
#define TILE2 (128*PITCH2)
#define RF_SMEM (4*TILE2)

__global__ __launch_bounds__(256) void rf_proj_hmma()
{
    extern __shared__ char smem[];
    uint32_t sb = smem_u32(smem);
    int tid = threadIdx.x;
    int lane = tid & 31, wid = tid >> 5;
    int warp_m = wid & 1, warp_n = wid >> 1;
    int z = blockIdx.z;
    int h = z & 7;
    bool isq = z < 8;
    int m0 = blockIdx.y * 128;

    const __nv_bfloat16* Ahi = (isq ? g_qhi : g_khi) + (size_t)m0 * DM + h * DH;
    const __nv_bfloat16* Alo = (isq ? g_qlo : g_klo) + (size_t)m0 * DM + h * DH;

#pragma unroll
    for (int j = 0; j < 16; j++) {
        int idx = tid + j * 256;
        int tile = idx >> 10;
        int w = idx & 1023;
        int r = w >> 3, c = w & 7;
        const __nv_bfloat16* gp =
            (tile == 0) ? (Ahi + (size_t)r * DM + c*8) :
            (tile == 1) ? (Alo + (size_t)r * DM + c*8) :
            (tile == 2) ? (g_rfthi + (size_t)r * DH + c*8) :
                          (g_rftlo + (size_t)r * DH + c*8);
        uint32_t sp = sb + tile * TILE2 + (uint32_t)r * PITCH2 + c * 16;
        CP_ASYNC16(sp, gp);
    }
    CP_COMMIT();
    CP_WAIT0();
    __syncthreads();

    uint32_t a_off = (uint32_t)(warp_m*64 + (lane & 15)) * PITCH2 + (lane >> 4) * 16;
    uint32_t b_off = (uint32_t)(warp_n*32 + (lane & 7) + (lane >> 4) * 8) * PITCH2 + ((lane >> 3) & 1) * 16;
    uint32_t sAhi = sb + a_off;
    uint32_t sAlo = sb + TILE2 + a_off;
    uint32_t sBhi = sb + 2*TILE2 + b_off;
    uint32_t sBlo = sb + 3*TILE2 + b_off;

    float acc[4][4][4];
#pragma unroll
    for (int i = 0; i < 4; i++)
#pragma unroll
        for (int j = 0; j < 4; j++)
#pragma unroll
            for (int r = 0; r < 4; r++) acc[i][j][r] = 0.f;

#pragma unroll
    for (int ks = 0; ks < 4; ks++) {
        uint32_t ah[4][4], al[4][4], bh[2][4], bl[2][4];
#pragma unroll
        for (int mi = 0; mi < 4; mi++) {
            LDSM4(ah[mi][0], ah[mi][1], ah[mi][2], ah[mi][3], sAhi + mi*16*PITCH2 + ks*32);
            LDSM4(al[mi][0], al[mi][1], al[mi][2], al[mi][3], sAlo + mi*16*PITCH2 + ks*32);
        }
#pragma unroll
        for (int nb = 0; nb < 2; nb++) {
            LDSM4(bh[nb][0], bh[nb][1], bh[nb][2], bh[nb][3], sBhi + nb*16*PITCH2 + ks*32);
            LDSM4(bl[nb][0], bl[nb][1], bl[nb][2], bl[nb][3], sBlo + nb*16*PITCH2 + ks*32);
        }
#pragma unroll
        for (int mi = 0; mi < 4; mi++)
#pragma unroll
            for (int nb = 0; nb < 2; nb++) {
                MMA16816(acc[mi][nb*2+0], ah[mi], bh[nb][0], bh[nb][1]);
                MMA16816(acc[mi][nb*2+1], ah[mi], bh[nb][2], bh[nb][3]);
                MMA16816(acc[mi][nb*2+0], ah[mi], bl[nb][0], bl[nb][1]);
                MMA16816(acc[mi][nb*2+1], ah[mi], bl[nb][2], bl[nb][3]);
                MMA16816(acc[mi][nb*2+0], al[mi], bh[nb][0], bh[nb][1]);
                MMA16816(acc[mi][nb*2+1], al[mi], bh[nb][2], bh[nb][3]);
            }
    }

    float kst = isq ? 0.f : dec_f(g_kstab);
    int g = lane >> 2, t = lane & 3;
    __nv_bfloat16* Ph = (isq ? g_pqhi : g_pkhi) + (size_t)h * L * MF;
    __nv_bfloat16* Pl = (isq ? g_pqlo : g_pklo) + (size_t)h * L * MF;
#pragma unroll
    for (int mi = 0; mi < 4; mi++) {
#pragma unroll
        for (int half = 0; half < 2; half++) {
            int row = m0 + warp_m*64 + mi*16 + g + half*8;
            float off = isq ? 0.f : (g_hk[(size_t)h * L + row] - kst);
#pragma unroll
            for (int nj = 0; nj < 4; nj++) {
                int col = warp_n*32 + nj*8 + t*2;
                float ox = NC_COEF * (__expf(acc[mi][nj][half*2+0] + off) + KEPS);
                float oy = NC_COEF * (__expf(acc[mi][nj][half*2+1] + off) + KEPS);
                __nv_bfloat162 hv, lv;
                split2(ox, oy, hv, lv);
                *(__nv_bfloat162*)(Ph + (size_t)row * MF + col) = hv;
                *(__nv_bfloat162*)(Pl + (size_t)row * MF + col) = lv;
            }
        }
    }
}

// ---------------- chunk_state via HMMA ----------------
#define CSP_K 272
#define CSP_V 208
#define CS_KH 0
#define CS_KL (CS_KH + 64*CSP_K)
#define CS_VH (CS_KL + 64*CSP_K)
#define CS_VL (CS_VH + 64*CSP_V)
#define CS_TOTAL (CS_VL + 64*CSP_V)

__global__ __launch_bounds__(256) void chunk_state_hmma(){
    extern __shared__ char smc[];
    uint32_t sb = smem_u32(smc);
    int c = blockIdx.x, h = blockIdx.y;
    int tid = threadIdx.x, lane = tid & 31, wid = tid >> 5;
    int warp_m = wid >> 1, warp_n = wid & 1;
    int l0 = c * CHK;

    const __nv_bfloat16* kh = g_pkhi + ((size_t)h * L + l0) * MF;
    const __nv_bfloat16* kl = g_pklo + ((size_t)h * L + l0) * MF;
    for (int i = tid; i < 1024; i += 256) {
        int r = i >> 4, cc = i & 15;
        CP_ASYNC16(sb + CS_KH + (uint32_t)r*CSP_K + cc*16, kh + (size_t)r*MF + cc*8);
        CP_ASYNC16(sb + CS_KL + (uint32_t)r*CSP_K + cc*16, kl + (size_t)r*MF + cc*8);
    }
    for (int i = tid; i < 512; i += 256) {
        int r = i >> 3, cc = i & 7;
        CP_ASYNC16(sb + CS_VH + (uint32_t)r*CSP_V + cc*16, g_vhi + (size_t)(l0+r)*DM + h*DH + cc*8);
        CP_ASYNC16(sb + CS_VL + (uint32_t)r*CSP_V + cc*16, g_vlo + (size_t)(l0+r)*DM + h*DH + cc*8);
    }
    if (tid < 64) {
        uint4 zz = make_uint4(0u,0u,0u,0u);
#pragma unroll
        for (int q = 0; q < 4; q++) {
            *(uint4*)(smc + CS_VH + tid*CSP_V + 128 + q*16) = zz;
            *(uint4*)(smc + CS_VL + tid*CSP_V + 128 + q*16) = zz;
        }
        *((__nv_bfloat16*)(smc + CS_VH + tid*CSP_V) + 64) = __float2bfloat16(1.0f);
    }
    CP_COMMIT(); CP_WAIT0();
    __syncthreads();

    float acc[2][6][4];
#pragma unroll
    for (int i = 0; i < 2; i++)
#pragma unroll
        for (int j = 0; j < 6; j++)
#pragma unroll
            for (int r = 0; r < 4; r++) acc[i][j][r] = 0.f;

#pragma unroll
    for (int ks = 0; ks < 4; ks++) {
        uint32_t ah[2][4], al[2][4], bh[3][4], bl[3][4];
#pragma unroll
        for (int mi = 0; mi < 2; mi++) {
            uint32_t aoff = (uint32_t)(ks*16 + ((lane >> 4) & 1)*8 + (lane & 7)) * CSP_K
                          + (uint32_t)(warp_m*32 + mi*16 + ((lane >> 3) & 1)*8) * 2;
            LDSM4T(ah[mi][0], ah[mi][1], ah[mi][2], ah[mi][3], sb + CS_KH + aoff);
            LDSM4T(al[mi][0], al[mi][1], al[mi][2], al[mi][3], sb + CS_KL + aoff);
        }
#pragma unroll
        for (int nb = 0; nb < 3; nb++) {
            uint32_t boff = (uint32_t)(ks*16 + (lane & 15)) * CSP_V
                          + (uint32_t)(warp_n*48 + nb*16 + (lane >> 4)*8) * 2;
            LDSM4T(bh[nb][0], bh[nb][1], bh[nb][2], bh[nb][3], sb + CS_VH + boff);
            LDSM4T(bl[nb][0], bl[nb][1], bl[nb][2], bl[nb][3], sb + CS_VL + boff);
        }
#pragma unroll
        for (int mi = 0; mi < 2; mi++)
#pragma unroll
            for (int nb = 0; nb < 3; nb++) {
                MMA16816(acc[mi][nb*2+0], ah[mi], bh[nb][0], bh[nb][1]);
                MMA16816(acc[mi][nb*2+1], ah[mi], bh[nb][2], bh[nb][3]);
                MMA16816(acc[mi][nb*2+0], ah[mi], bl[nb][0], bl[nb][1]);
                MMA16816(acc[mi][nb*2+1], ah[mi], bl[nb][2], bl[nb][3]);
                MMA16816(acc[mi][nb*2+0], al[mi], bh[nb][0], bh[nb][1]);
                MMA16816(acc[mi][nb*2+1], al[mi], bh[nb][2], bh[nb][3]);
            }
    }

    int g = lane >> 2, t = lane & 3;
    float* Sdst = g_S + (size_t)(h*NC + c) * MF * DH;
    float* zdst = g_z + (size_t)(h*NC + c) * MF;
#pragma unroll
    for (int mi = 0; mi < 2; mi++) {
#pragma unroll
        for (int half = 0; half < 2; half++) {
            int m = warp_m*32 + mi*16 + g + half*8;
#pragma unroll
            for (int nj = 0; nj < 6; nj++) {
                int col = warp_n*48 + nj*8 + t*2;
                float x = acc[mi][nj][half*2+0];
                float y = acc[mi][nj][half*2+1];
                if (col < 64) {
                    *(float2*)(Sdst + (size_t)m * DH + col) = make_float2(x, y);
                } else if (col == 64) {
                    zdst[m] = x;
                }
            }
        }
    }
}

// ---------------- exclusive prefix over chunks (batched loads, MLP=32) ----------------
__global__ void prefix_scan(){
    int h = blockIdx.y;
    int idx = blockIdx.x * 256 + threadIdx.x;
    if (idx < MF * DH) {
        const float* p = g_S + (size_t)h * NC * MF * DH + idx;
        float v[NC];
#pragma unroll
        for (int c = 0; c < NC; c++) v[c] = p[(size_t)c * MF * DH];
        __nv_bfloat16* ph = g_Shi + (size_t)h * NC * MF * DH + idx;
        __nv_bfloat16* pl = g_Slo + (size_t)h * NC * MF * DH + idx;
        float prev = 0.f;
#pragma unroll
        for (int c = 0; c < NC; c++) {
            __nv_bfloat16 hh = __float2bfloat16(prev);
            ph[(size_t)c * MF * DH] = hh;
            pl[(size_t)c * MF * DH] = __float2bfloat16(prev - __bfloat162float(hh));
            prev += v[c];
        }
    } else if (idx < MF * DH + MF) {
        int m = idx - MF * DH;
        float* p = g_z + (size_t)h * NC * MF + m;
        float v[NC];
#pragma unroll
        for (int c = 0; c < NC; c++) v[c] = p[c * MF];
        float prev = 0.f;
#pragma unroll
        for (int c = 0; c < NC; c++) {
            p[c * MF] = prev;
            prev += v[c];
        }
    }
}

// ---------------- chunk_out via HMMA (split commit groups) ----------------
#define PQ 272
#define PV 144
#define CO_QH 0
#define CO_QL (CO_QH + 64*PQ)
#define CO_KH (CO_QL + 64*PQ)
#define CO_KL (CO_KH + 64*PQ)
#define CO_VH (CO_KL + 64*PQ)
#define CO_VL (CO_VH + 64*PV)
#define CO_SH (CO_VL + 64*PV)
#define CO_SL (CO_SH + 128*PV)
#define CO_AH (CO_SL + 128*PV)
#define CO_AL (CO_AH + 64*PV)
#define CO_ZB (CO_AL + 64*PV)
#define CO_PR (CO_ZB + 512)
#define CO_RS (CO_PR + 64*4*4)
#define CO_TOTAL (CO_RS + 256)

__global__ __launch_bounds__(256) void chunk_out_hmma(){
    extern __shared__ char smc[];
    uint32_t sb = smem_u32(smc);
    int c = blockIdx.x, h = blockIdx.y;
    int tid = threadIdx.x, lane = tid & 31, wid = tid >> 5;
    int warp_m = wid & 1, warp_n = wid >> 1;
    int l0 = c * CHK;

    {
        const __nv_bfloat16* pqh = g_pqhi + ((size_t)h * L + l0) * MF;
        const __nv_bfloat16* pql = g_pqlo + ((size_t)h * L + l0) * MF;
        const __nv_bfloat16* pkh = g_pkhi + ((size_t)h * L + l0) * MF;
        const __nv_bfloat16* pkl = g_pklo + ((size_t)h * L + l0) * MF;
        for (int i = tid; i < 1024; i += 256) {
            int r = i >> 4, cc = i & 15;
            CP_ASYNC16(sb + CO_QH + r*PQ + cc*16, pqh + (size_t)r*MF + cc*8);
            CP_ASYNC16(sb + CO_QL + r*PQ + cc*16, pql + (size_t)r*MF + cc*8);
            CP_ASYNC16(sb + CO_KH + r*PQ + cc*16, pkh + (size_t)r*MF + cc*8);
            CP_ASYNC16(sb + CO_KL + r*PQ + cc*16, pkl + (size_t)r*MF + cc*8);
        }
        CP_COMMIT();
        for (int i = tid; i < 512; i += 256) {
            int r = i >> 3, cc = i & 7;
            CP_ASYNC16(sb + CO_VH + r*PV + cc*16, g_vhi + (size_t)(l0 + r)*DM + h*DH + cc*8);
            CP_ASYNC16(sb + CO_VL + r*PV + cc*16, g_vlo + (size_t)(l0 + r)*DM + h*DH + cc*8);
        }
        const __nv_bfloat16* sh = g_Shi + (size_t)(h*NC + c)*MF*DH;
        const __nv_bfloat16* sl = g_Slo + (size_t)(h*NC + c)*MF*DH;
        for (int i = tid; i < 1024; i += 256) {
            int r = i >> 3, cc = i & 7;
            CP_ASYNC16(sb + CO_SH + r*PV + cc*16, sh + (size_t)r*DH + cc*8);
            CP_ASYNC16(sb + CO_SL + r*PV + cc*16, sl + (size_t)r*DH + cc*8);
        }
        if (tid < 32) CP_ASYNC16(sb + CO_ZB + tid*16, g_z + (size_t)(h*NC + c)*MF + tid*4);
        CP_COMMIT();
        CP_WAIT1();
    }
    __syncthreads();

    uint32_t a_off = (uint32_t)(warp_m*32 + (lane & 15)) * PQ + (lane >> 4) * 16;
    uint32_t b_off = (uint32_t)(warp_n*16 + (lane & 7) + (lane >> 4) * 8) * PQ + ((lane >> 3) & 1) * 16;

    float acc[2][2][4];
#pragma unroll
    for (int i = 0; i < 2; i++)
#pragma unroll
        for (int j = 0; j < 2; j++)
#pragma unroll
            for (int r = 0; r < 4; r++) acc[i][j][r] = 0.f;

#pragma unroll
    for (int ks = 0; ks < 8; ks++) {
        uint32_t ah[2][4], al[2][4], bh[4], bl[4];
#pragma unroll
        for (int mi = 0; mi < 2; mi++) {
            LDSM4(ah[mi][0], ah[mi][1], ah[mi][2], ah[mi][3], sb + CO_QH + a_off + mi*16*PQ + ks*32);
            LDSM4(al[mi][0], al[mi][1], al[mi][2], al[mi][3], sb + CO_QL + a_off + mi*16*PQ + ks*32);
        }
        LDSM4(bh[0], bh[1], bh[2], bh[3], sb + CO_KH + b_off + ks*32);
        LDSM4(bl[0], bl[1], bl[2], bl[3], sb + CO_KL + b_off + ks*32);
#pragma unroll
        for (int mi = 0; mi < 2; mi++) {
            MMA16816(acc[mi][0], ah[mi], bh[0], bh[1]);
            MMA16816(acc[mi][1], ah[mi], bh[2], bh[3]);
            MMA16816(acc[mi][0], ah[mi], bl[0], bl[1]);
            MMA16816(acc[mi][1], ah[mi], bl[2], bl[3]);
            MMA16816(acc[mi][0], al[mi], bh[0], bh[1]);
            MMA16816(acc[mi][1], al[mi], bh[2], bh[3]);
        }
    }
    CP_WAIT0();

    int g = lane >> 2, t = lane & 3;
    float* pr = (float*)(smc + CO_PR);
#pragma unroll
    for (int mi = 0; mi < 2; mi++) {
#pragma unroll
        for (int half = 0; half < 2; half++) {
            int row = warp_m*32 + mi*16 + g + half*8;
            float rsum = 0.f;
#pragma unroll
            for (int nj = 0; nj < 2; nj++) {
                int col = warp_n*16 + nj*8 + t*2;
                float x = (col     <= row) ? acc[mi][nj][half*2+0] : 0.f;
                float y = (col + 1 <= row) ? acc[mi][nj][half*2+1] : 0.f;
                rsum += x + y;
                __nv_bfloat162 hv, lv;
                split2(x, y, hv, lv);
                *(__nv_bfloat162*)(smc + CO_AH + row*PV + col*2) = hv;
                *(__nv_bfloat162*)(smc + CO_AL + row*PV + col*2) = lv;
            }
            rsum += __shfl_xor_sync(0xffffffffu, rsum, 1);
            rsum += __shfl_xor_sync(0xffffffffu, rsum, 2);
            if (t == 0) pr[row*4 + warp_n] = rsum;
        }
    }
    __syncthreads();

    if (tid < 64) {
        float s = pr[tid*4+0] + pr[tid*4+1] + pr[tid*4+2] + pr[tid*4+3];
        const float* zf = (const float*)(smc + CO_ZB);
#pragma unroll 8
        for (int m2 = 0; m2 < 64; m2++) {
            __nv_bfloat162 qh2 = *(const __nv_bfloat162*)(smc + CO_QH + tid*PQ + m2*4);
            __nv_bfloat162 ql2 = *(const __nv_bfloat162*)(smc + CO_QL + tid*PQ + m2*4);
            float2 z2 = *(const float2*)(zf + m2*2);
            s += (__bfloat162float(qh2.x) + __bfloat162float(ql2.x)) * z2.x
               + (__bfloat162float(qh2.y) + __bfloat162float(ql2.y)) * z2.y;
        }
        ((float*)(smc + CO_RS))[tid] = s + DEPS;
    }

    float o[2][2][4];
#pragma unroll
    for (int i = 0; i < 2; i++)
#pragma unroll
        for (int j = 0; j < 2; j++)
#pragma unroll
            for (int r = 0; r < 4; r++) o[i][j][r] = 0.f;

    uint32_t a2_off = (uint32_t)(warp_m*32 + (lane & 15)) * PV + (lane >> 4) * 16;
    uint32_t bt_off = (uint32_t)(lane & 15) * PV + (warp_n*16 + (lane >> 4) * 8) * 2;

#pragma unroll
    for (int ks = 0; ks < 4; ks++) {
        uint32_t ah[2][4], al[2][4], bh[4], bl[4];
#pragma unroll
        for (int mi = 0; mi < 2; mi++) {
            LDSM4(ah[mi][0], ah[mi][1], ah[mi][2], ah[mi][3], sb + CO_AH + a2_off + mi*16*PV + ks*32);
            LDSM4(al[mi][0], al[mi][1], al[mi][2], al[mi][3], sb + CO_AL + a2_off + mi*16*PV + ks*32);
        }
        LDSM4T(bh[0], bh[1], bh[2], bh[3], sb + CO_VH + bt_off + ks*16*PV);
        LDSM4T(bl[0], bl[1], bl[2], bl[3], sb + CO_VL + bt_off + ks*16*PV);
#pragma unroll
        for (int mi = 0; mi < 2; mi++) {
            MMA16816(o[mi][0], ah[mi], bh[0], bh[1]);
            MMA16816(o[mi][1], ah[mi], bh[2], bh[3]);
            MMA16816(o[mi][0], ah[mi], bl[0], bl[1]);
            MMA16816(o[mi][1], ah[mi], bl[2], bl[3]);
            MMA16816(o[mi][0], al[mi], bh[0], bh[1]);
            MMA16816(o[mi][1], al[mi], bh[2], bh[3]);
        }
    }
#pragma unroll
    for (int ks = 0; ks < 8; ks++) {
        uint32_t ah[2][4], al[2][4], bh[4], bl[4];
#pragma unroll
        for (int mi = 0; mi < 2; mi++) {
            LDSM4(ah[mi][0], ah[mi][1], ah[mi][2], ah[mi][3], sb + CO_QH + a_off + mi*16*PQ + ks*32);
            LDSM4(al[mi][0], al[mi][1], al[mi][2], al[mi][3], sb + CO_QL + a_off + mi*16*PQ + ks*32);
        }
        LDSM4T(bh[0], bh[1], bh[2], bh[3], sb + CO_SH + bt_off + ks*16*PV);
        LDSM4T(bl[0], bl[1], bl[2], bl[3], sb + CO_SL + bt_off + ks*16*PV);
#pragma unroll
        for (int mi = 0; mi < 2; mi++) {
            MMA16816(o[mi][0], ah[mi], bh[0], bh[1]);
            MMA16816(o[mi][1], ah[mi], bh[2], bh[3]);
            MMA16816(o[mi][0], ah[mi], bl[0], bl[1]);
            MMA16816(o[mi][1], ah[mi], bl[2], bl[3]);
            MMA16816(o[mi][0], al[mi], bh[0], bh[1]);
            MMA16816(o[mi][1], al[mi], bh[2], bh[3]);
        }
    }
    __syncthreads();

    const float* rs = (const float*)(smc + CO_RS);
#pragma unroll
    for (int mi = 0; mi < 2; mi++) {
#pragma unroll
        for (int half = 0; half < 2; half++) {
            int row = warp_m*32 + mi*16 + g + half*8;
            float inv = 1.0f / rs[row];
#pragma unroll
            for (int nj = 0; nj < 2; nj++) {
                int col = warp_n*16 + nj*8 + t*2;
                float ox = o[mi][nj][half*2+0] * inv;
                float oy = o[mi][nj][half*2+1] * inv;
                __nv_bfloat162 hv, lv;
                split2(ox, oy, hv, lv);
                size_t off = (size_t)(l0 + row) * DM + h*DH + col;
                *(__nv_bfloat162*)(g_bhi_ctx + off) = hv;
                *(__nv_bfloat162*)(g_blo_ctx + off) = lv;
            }
        }
    }
}

// ---------------- launcher ----------------
extern "C" void kernel_launch(void* const* d_in, const int* in_sizes, int n_in,
                              void* d_out, int out_size)
{
    const float* query = (const float*)d_in[0];
    const float* key_i = (const float*)d_in[1];
    const float* value = (const float*)d_in[2];
    const float* Wq = (const float*)d_in[3];
    const float* bq = (const float*)d_in[4];
    const float* Wk = (const float*)d_in[5];
    const float* bk = (const float*)d_in[6];
    const float* Wv = (const float*)d_in[7];
    const float* bv = (const float*)d_in[8];
    const float* Wo = (const float*)d_in[9];
    const float* bo = (const float*)d_in[10];
    const float* rf = (const float*)d_in[11];
    float* out = (float*)d_out;

    void* p;
    cudaGetSymbolAddress(&p, g_bhi_w);   __nv_bfloat16* bhi_w  = (__nv_bfloat16*)p;
    cudaGetSymbolAddress(&p, g_blo_w);   __nv_bfloat16* blo_w  = (__nv_bfloat16*)p;
    cudaGetSymbolAddress(&p, g_bhi_ctx); __nv_bfloat16* bhi_c  = (__nv_bfloat16*)p;
    cudaGetSymbolAddress(&p, g_blo_ctx); __nv_bfloat16* blo_c  = (__nv_bfloat16*)p;
    cudaGetSymbolAddress(&p, g_qhi);     __nv_bfloat16* qhi    = (__nv_bfloat16*)p;
    cudaGetSymbolAddress(&p, g_qlo);     __nv_bfloat16* qlo    = (__nv_bfloat16*)p;
    cudaGetSymbolAddress(&p, g_khi);     __nv_bfloat16* khi    = (__nv_bfloat16*)p;
    cudaGetSymbolAddress(&p, g_klo);     __nv_bfloat16* klo    = (__nv_bfloat16*)p;
    cudaGetSymbolAddress(&p, g_vhi);     __nv_bfloat16* vhi    = (__nv_bfloat16*)p;
    cudaGetSymbolAddress(&p, g_vlo);     __nv_bfloat16* vlo    = (__nv_bfloat16*)p;

    // convert only weights (+rf/kstab); inputs converted in-GEMM
    CV cv;
    cv.src[0]=Wq; cv.hi[0]=bhi_w;          cv.lo[0]=blo_w;          cv.n[0]=DM*DM;
    cv.src[1]=Wk; cv.hi[1]=bhi_w+DM*DM;    cv.lo[1]=blo_w+DM*DM;    cv.n[1]=DM*DM;
    cv.src[2]=Wv; cv.hi[2]=bhi_w+2*DM*DM;  cv.lo[2]=blo_w+2*DM*DM;  cv.n[2]=DM*DM;
    cv.src[3]=Wo; cv.hi[3]=bhi_w+3*DM*DM;  cv.lo[3]=blo_w+3*DM*DM;  cv.n[3]=DM*DM;
    cv.cnt = 4;
    convert_split<<<dim3((DM*DM)/1024, 5), 256>>>(cv, rf);

    cudaFuncSetAttribute((hmma_gemm<2,true>),  cudaFuncAttributeMaxDynamicSharedMemorySize, HG_SMEM2);
    cudaFuncSetAttribute((hmma_gemm<1,false>), cudaFuncAttributeMaxDynamicSharedMemorySize, HG_SMEM1);
    cudaFuncSetAttribute(rf_proj_hmma, cudaFuncAttributeMaxDynamicSharedMemorySize, RF_SMEM);
    cudaFuncSetAttribute(chunk_state_hmma, cudaFuncAttributeMaxDynamicSharedMemorySize, CS_TOTAL);
    cudaFuncSetAttribute(chunk_out_hmma, cudaFuncAttributeMaxDynamicSharedMemorySize, CO_TOTAL);

    // QKV projections (MB=2, A from fp32 inputs, hk fused into z==1 epilogue)
    MMArgs mq;
    mq.Af[0]=query; mq.Ahi[0]=nullptr; mq.Alo[0]=nullptr; mq.Whi[0]=bhi_w;        mq.Wlo[0]=blo_w;        mq.bias[0]=bq; mq.C[0]=nullptr; mq.Chi[0]=qhi; mq.Clo[0]=qlo; mq.alpha[0]=SCALE_QK;
    mq.Af[1]=key_i; mq.Ahi[1]=nullptr; mq.Alo[1]=nullptr; mq.Whi[1]=bhi_w+DM*DM;  mq.Wlo[1]=blo_w+DM*DM;  mq.bias[1]=bk; mq.C[1]=nullptr; mq.Chi[1]=khi; mq.Clo[1]=klo; mq.alpha[1]=SCALE_QK;
    mq.Af[2]=value; mq.Ahi[2]=nullptr; mq.Alo[2]=nullptr; mq.Whi[2]=bhi_w+2*DM*DM;mq.Wlo[2]=blo_w+2*DM*DM;mq.bias[2]=bv; mq.C[2]=nullptr; mq.Chi[2]=vhi; mq.Clo[2]=vlo; mq.alpha[2]=1.0f;
    hmma_gemm<2,true><<<dim3(DM/128, L/64, 3), 256, HG_SMEM2>>>(mq, 1);

    rf_proj_hmma<<<dim3(1, L/128, 16), 256, RF_SMEM>>>();

    chunk_state_hmma<<<dim3(NC, NH), 256, CS_TOTAL>>>();
    prefix_scan<<<dim3((MF*DH + MF + 255)/256, NH), 256>>>();
    chunk_out_hmma<<<dim3(NC, NH), 256, CO_TOTAL>>>();

    // output projection (MB=1, A from bf16 ctx)
    MMArgs mo;
    mo.Af[0]=nullptr; mo.Ahi[0]=bhi_c; mo.Alo[0]=blo_c; mo.Whi[0]=bhi_w+3*DM*DM; mo.Wlo[0]=blo_w+3*DM*DM; mo.bias[0]=bo; mo.C[0]=out; mo.Chi[0]=nullptr; mo.Clo[0]=nullptr; mo.alpha[0]=1.0f;
    mo.Af[1]=nullptr; mo.Ahi[1]=mo.Ahi[0]; mo.Alo[1]=mo.Alo[0]; mo.Whi[1]=mo.Whi[0]; mo.Wlo[1]=mo.Wlo[0]; mo.bias[1]=bo; mo.C[1]=out; mo.Chi[1]=nullptr; mo.Clo[1]=nullptr; mo.alpha[1]=1.0f;
    mo.Af[2]=nullptr; mo.Ahi[2]=mo.Ahi[0]; mo.Alo[2]=mo.Alo[0]; mo.Whi[2]=mo.Whi[0]; mo.Wlo[2]=mo.Wlo[0]; mo.bias[2]=bo; mo.C[2]=out; mo.Chi[2]=nullptr; mo.Clo[2]=nullptr; mo.alpha[2]=1.0f;
    hmma_gemm<1,false><<<dim3(DM/128, L/32, 1), 256, HG_SMEM1>>>(mo, 0);
}

// round 16
// speedup vs baseline: 1.0967x; 1.0081x over previous
#include <cuda_runtime.h>
#include <cuda_bf16.h>
#include <math.h>
#include <stdint.h>

#define L 2048
#define DM 512
#define NH 8
#define DH 64
#define MF 128
#define CHK 64
#define NC (L/CHK)   // 32

#define SCALE_QK 0.2102241038134287f
#define NC_COEF  0.08838834764831845f
#define KEPS 1e-4f
#define DEPS 1e-6f

// ---------------- device scratch ----------------
__device__ float g_hk[NH*L];
__device__ unsigned g_kstab;
__device__ float g_S[NH*NC*MF*DH];
__device__ float g_z[NH*NC*MF];

__device__ __nv_bfloat16 g_bhi_w[4][DM*DM];
__device__ __nv_bfloat16 g_blo_w[4][DM*DM];
__device__ __nv_bfloat16 g_bhi_ctx[L*DM];
__device__ __nv_bfloat16 g_blo_ctx[L*DM];
__device__ __nv_bfloat16 g_qhi[L*DM];
__device__ __nv_bfloat16 g_qlo[L*DM];
__device__ __nv_bfloat16 g_khi[L*DM];
__device__ __nv_bfloat16 g_klo[L*DM];
__device__ __nv_bfloat16 g_rfthi[MF*DH];
__device__ __nv_bfloat16 g_rftlo[MF*DH];
__device__ __nv_bfloat16 g_pqhi[NH*L*MF];
__device__ __nv_bfloat16 g_pqlo[NH*L*MF];
__device__ __nv_bfloat16 g_pkhi[NH*L*MF];
__device__ __nv_bfloat16 g_pklo[NH*L*MF];
__device__ __nv_bfloat16 g_vhi[L*DM];
__device__ __nv_bfloat16 g_vlo[L*DM];
__device__ __nv_bfloat16 g_Shi[NH*NC*MF*DH];
__device__ __nv_bfloat16 g_Slo[NH*NC*MF*DH];

__device__ __forceinline__ unsigned enc_f(float f){
    unsigned u = __float_as_uint(f);
    return (u & 0x80000000u) ? ~u : (u | 0x80000000u);
}
__device__ __forceinline__ float dec_f(unsigned k){
    unsigned u = (k & 0x80000000u) ? (k ^ 0x80000000u) : ~k;
    return __uint_as_float(u);
}

__device__ __forceinline__ uint32_t smem_u32(const void* p) {
    uint32_t a;
    asm("{ .reg .u64 t; cvta.to.shared.u64 t, %1; cvt.u32.u64 %0, t; }" : "=r"(a) : "l"(p));
    return a;
}

#define CP_ASYNC16(sa, gp) asm volatile("cp.async.cg.shared.global [%0], [%1], 16;" :: "r"(sa), "l"(gp))
#define CP_COMMIT()        asm volatile("cp.async.commit_group;")
#define CP_WAIT1()         asm volatile("cp.async.wait_group 1;")
#define CP_WAIT0()         asm volatile("cp.async.wait_group 0;")

#define LDSM4(r0,r1,r2,r3,a) \
    asm volatile("ldmatrix.sync.aligned.m8n8.x4.shared.b16 {%0,%1,%2,%3}, [%4];" \
        : "=r"(r0),"=r"(r1),"=r"(r2),"=r"(r3) : "r"(a))
#define LDSM4T(r0,r1,r2,r3,a) \
    asm volatile("ldmatrix.sync.aligned.m8n8.x4.trans.shared.b16 {%0,%1,%2,%3}, [%4];" \
        : "=r"(r0),"=r"(r1),"=r"(r2),"=r"(r3) : "r"(a))

#define MMA16816(d,a,b0,b1) \
    asm volatile("mma.sync.aligned.m16n8k16.row.col.f32.bf16.bf16.f32 " \
        "{%0,%1,%2,%3},{%4,%5,%6,%7},{%8,%9},{%0,%1,%2,%3};" \
        : "+f"((d)[0]),"+f"((d)[1]),"+f"((d)[2]),"+f"((d)[3]) \
        : "r"((a)[0]),"r"((a)[1]),"r"((a)[2]),"r"((a)[3]),"r"(b0),"r"(b1))

__device__ __forceinline__ void split2(float x, float y, __nv_bfloat162& hv, __nv_bfloat162& lv){
    __nv_bfloat16 hx = __float2bfloat16(x);
    __nv_bfloat16 hy = __float2bfloat16(y);
    hv.x = hx; hv.y = hy;
    lv.x = __float2bfloat16(x - __bfloat162float(hx));
    lv.y = __float2bfloat16(y - __bfloat162float(hy));
}

// ---------------- fp32 -> (bf16 hi, bf16 lo) converter (weights + rf + kstab) ----------------
struct CV { const float* src[8]; __nv_bfloat16* hi[8]; __nv_bfloat16* lo[8]; int n[8]; int cnt; };
__global__ void convert_split(CV cv, const float* __restrict__ rf){
    int t = blockIdx.y;
    if (t == cv.cnt) {
        if (blockIdx.x == 0 && threadIdx.x == 0) g_kstab = 0u;
        int i0 = blockIdx.x * 1024 + threadIdx.x;
#pragma unroll
        for (int j = 0; j < 4; j++) {
            int i = i0 + j * 256;
            if (i < MF * DH) {
                int m = i >> 6, d = i & 63;
                float x = rf[(size_t)d * MF + m];
                __nv_bfloat16 h = __float2bfloat16(x);
                g_rfthi[(size_t)m * DH + d] = h;
                g_rftlo[(size_t)m * DH + d] = __float2bfloat16(x - __bfloat162float(h));
            }
        }
        return;
    }
    int n = cv.n[t];
    const float* s = cv.src[t];
    __nv_bfloat16* ph = cv.hi[t];
    __nv_bfloat16* pl = cv.lo[t];
    int i0 = blockIdx.x * 1024 + threadIdx.x;
#pragma unroll
    for (int j = 0; j < 4; j++) {
        int i = i0 + j * 256;
        if (i < n) {
            float x = s[i];
            __nv_bfloat16 h = __float2bfloat16(x);
            ph[i] = h;
            pl[i] = __float2bfloat16(x - __bfloat162float(h));
        }
    }
}

// ---------------- split-bf16 HMMA GEMM, templated M-tile; A from fp32 or bf16 ----------------
#define PITCH_B 144
#define B_TILE (128*PITCH_B)         // 18432
#define NKC 8

struct MMArgs {
    const float* Af[3];
    const __nv_bfloat16* Ahi[3]; const __nv_bfloat16* Alo[3];
    const __nv_bfloat16* Whi[3]; const __nv_bfloat16* Wlo[3];
    const float* bias[3]; float* C[3];
    __nv_bfloat16* Chi[3]; __nv_bfloat16* Clo[3];
    float alpha[3];
};

template<int MB, bool AF32>
__global__ __launch_bounds__(256, 2) void hmma_gemm(MMArgs ga, int do_hk)
{
    constexpr int RT = MB * 32;
    constexpr int A_T = RT * PITCH_B;
    constexpr int STB = 2*A_T + 2*B_TILE;
    constexpr int ACH = 2 * MB * 256;

    extern __shared__ char smem[];
    uint32_t sb = smem_u32(smem);
    int tid = threadIdx.x;
    int lane = tid & 31, wid = tid >> 5;
    int warp_m = wid & 1, warp_n = wid >> 1;
    int z = blockIdx.z;
    int m0 = blockIdx.y * RT, n0 = blockIdx.x * 128;

    const float* Af = AF32 ? (ga.Af[z] + (size_t)m0 * DM) : nullptr;
    const __nv_bfloat16* Ahi = AF32 ? nullptr : (ga.Ahi[z] + (size_t)m0 * DM);
    const __nv_bfloat16* Alo = AF32 ? nullptr : (ga.Alo[z] + (size_t)m0 * DM);
    const __nv_bfloat16* Whi = ga.Whi[z] + (size_t)n0 * DM;
    const __nv_bfloat16* Wlo = ga.Wlo[z] + (size_t)n0 * DM;
    const float* bias = ga.bias[z];
    float alpha = ga.alpha[z];

    uint32_t a_off = (uint32_t)(warp_m*(16*MB) + (lane & 15)) * PITCH_B + (lane >> 4) * 16;
    uint32_t b_off = (uint32_t)(warp_n*32 + (lane & 7) + (lane >> 4) * 8) * PITCH_B + ((lane >> 3) & 1) * 16;

    float acc[MB][4][4];
#pragma unroll
    for (int i = 0; i < MB; i++)
#pragma unroll
        for (int j = 0; j < 4; j++)
#pragma unroll
            for (int r = 0; r < 4; r++) acc[i][j][r] = 0.f;

    auto load_stage = [&](int k0, uint32_t so){
        if (AF32) {
#pragma unroll
            for (int j = 0; j < MB*2; j++) {
                int idx = tid + j * 256;
                int r = idx >> 4, c4 = idx & 15;
                float4 v = *(const float4*)(Af + (size_t)r * DM + k0 + c4*4);
                __nv_bfloat162 h0, l0, h1, l1;
                split2(v.x, v.y, h0, l0);
                split2(v.z, v.w, h1, l1);
                uint2 hu, lu;
                hu.x = *(uint32_t*)&h0; hu.y = *(uint32_t*)&h1;
                lu.x = *(uint32_t*)&l0; lu.y = *(uint32_t*)&l1;
                size_t doff = so + (size_t)r * PITCH_B + c4*8;
                *(uint2*)(smem + doff) = hu;
                *(uint2*)(smem + doff + A_T) = lu;
            }
        } else {
#pragma unroll
            for (int j = 0; j < MB*2; j++) {
                int idx = tid + j * 256;
                int t2 = idx / (MB*256);
                int w = idx - t2 * (MB*256);
                int r = w >> 3, cc = w & 7;
                const __nv_bfloat16* gp = (t2 ? Alo : Ahi) + (size_t)r * DM + k0 + cc*8;
                CP_ASYNC16(sb + (uint32_t)so + t2*A_T + (uint32_t)r * PITCH_B + cc*16, gp);
            }
        }
#pragma unroll
        for (int j = 0; j < 8; j++) {
            int idx = tid + j * 256;
            int t2 = idx >> 10;
            int w = idx & 1023;
            int r = w >> 3, cc = w & 7;
            const __nv_bfloat16* gp = (t2 ? Wlo : Whi) + (size_t)r * DM + k0 + cc*8;
            CP_ASYNC16(sb + (uint32_t)so + 2*A_T + t2*B_TILE + (uint32_t)r * PITCH_B + cc*16, gp);
        }
        CP_COMMIT();
    };

    load_stage(0, 0);

    for (int kc = 0; kc < NKC; kc++) {
        if (kc + 1 < NKC) {
            load_stage((kc + 1) * 64, ((kc + 1) & 1) * STB);
            CP_WAIT1();
        } else {
            CP_WAIT0();
        }
        __syncthreads();

        uint32_t st = sb + (kc & 1) * STB;
        uint32_t sAhi = st + a_off;
        uint32_t sAlo = st + A_T + a_off;
        uint32_t sBhi = st + 2*A_T + b_off;
        uint32_t sBlo = st + 2*A_T + B_TILE + b_off;

#pragma unroll
        for (int ks = 0; ks < 4; ks++) {
            uint32_t ah[MB][4], al[MB][4], bh[2][4], bl[2][4];
#pragma unroll
            for (int mi = 0; mi < MB; mi++) {
                LDSM4(ah[mi][0], ah[mi][1], ah[mi][2], ah[mi][3], sAhi + mi*16*PITCH_B + ks*32);
                LDSM4(al[mi][0], al[mi][1], al[mi][2], al[mi][3], sAlo + mi*16*PITCH_B + ks*32);
            }
#pragma unroll
            for (int nb = 0; nb < 2; nb++) {
                LDSM4(bh[nb][0], bh[nb][1], bh[nb][2], bh[nb][3], sBhi + nb*16*PITCH_B + ks*32);
                LDSM4(bl[nb][0], bl[nb][1], bl[nb][2], bl[nb][3], sBlo + nb*16*PITCH_B + ks*32);
            }
#pragma unroll
            for (int mi = 0; mi < MB; mi++)
#pragma unroll
                for (int nb = 0; nb < 2; nb++) {
                    MMA16816(acc[mi][nb*2+0], ah[mi], bh[nb][0], bh[nb][1]);
                    MMA16816(acc[mi][nb*2+1], ah[mi], bh[nb][2], bh[nb][3]);
                    MMA16816(acc[mi][nb*2+0], ah[mi], bl[nb][0], bl[nb][1]);
                    MMA16816(acc[mi][nb*2+1], ah[mi], bl[nb][2], bl[nb][3]);
                    MMA16816(acc[mi][nb*2+0], al[mi], bh[nb][0], bh[nb][1]);
                    MMA16816(acc[mi][nb*2+1], al[mi], bh[nb][2], bh[nb][3]);
                }
        }
        __syncthreads();
    }

    int g = lane >> 2, t = lane & 3;
    __nv_bfloat16* Chi = ga.Chi[z];
    float* C = ga.C[z];
    bool hk = (do_hk && z == 1);
    float* pr = (float*)smem;
    float* red = (float*)smem + 256;

#pragma unroll
    for (int mi = 0; mi < MB; mi++) {
#pragma unroll
        for (int half = 0; half < 2; half++) {
            int lrow = warp_m*(16*MB) + mi*16 + g + half*8;
            int row = m0 + lrow;
            float ss = 0.f;
#pragma unroll
            for (int nj = 0; nj < 4; nj++) {
                int col = n0 + warp_n*32 + nj*8 + t*2;
                float2 bb = *(const float2*)(bias + col);
                float ox = alpha * (acc[mi][nj][half*2+0] + bb.x);
                float oy = alpha * (acc[mi][nj][half*2+1] + bb.y);
                ss += ox*ox + oy*oy;
                if (C) *(float2*)(C + (size_t)row * DM + col) = make_float2(ox, oy);
                if (Chi) {
                    __nv_bfloat162 hv, lv;
                    split2(ox, oy, hv, lv);
                    *(__nv_bfloat162*)(Chi + (size_t)row * DM + col) = hv;
                    *(__nv_bfloat162*)(ga.Clo[z] + (size_t)row * DM + col) = lv;
                }
            }
            if (MB == 2 && hk) {
                ss += __shfl_xor_sync(0xffffffffu, ss, 1);
                ss += __shfl_xor_sync(0xffffffffu, ss, 2);
                if (t == 0) pr[lrow*4 + warp_n] = ss;
            }
        }
    }
    if (MB == 2 && hk) {
        __syncthreads();
        float hmax = -1e30f;
        if (tid < 128) {
            int row = tid >> 1, hd2 = tid & 1;
            float ss = pr[row*4 + hd2*2] + pr[row*4 + hd2*2 + 1];
            float hv = -0.5f * ss;
            g_hk[(size_t)((n0 >> 6) + hd2) * L + m0 + row] = hv;
            hmax = hv;
        }
#pragma unroll
        for (int o = 16; o; o >>= 1) hmax = fmaxf(hmax, __shfl_xor_sync(0xffffffffu, hmax, o));
        if (lane == 0) red[wid] = hmax;
        __syncthreads();
        if (tid == 0) {
            float mx = red[0];
#pragma unroll
            for (int i = 1; i < 8; i++) mx = fmaxf(mx, red[i]);
            atomicMax(&g_kstab, enc_f(mx));
        }
    }
}

#define HG_SMEM2 (2*(2*(64*PITCH_B) + 2*B_TILE))
#define HG_SMEM1 (2*(2*(32*PITCH_B) + 2*B_TILE))

// ---------------- rf projection + featurize (HMMA split-bf16); zbase selects q/k half ----------------
#define PITCH2 144
#define TILE2 (128*PITCH2)
#define RF_SMEM (4*TILE2)

__global__ __launch_bounds__(256) void rf_proj_hmma(int zbase)
{
    extern __shared__ char smem[];
    uint32_t sb = smem_u32(smem);
    int tid = threadIdx.x;
    int lane = tid & 31, wid = tid >> 5;
    int warp_m = wid & 1, warp_n = wid >> 1;
    int z = zbase + blockIdx.z;
    int h = z & 7;
    bool isq = z < 8;
    int m0 = blockIdx.y * 128;

    const __nv_bfloat16* Ahi = (isq ? g_qhi : g_khi) + (size_t)m0 * DM + h * DH;
    const __nv_bfloat16* Alo = (isq ? g_qlo : g_klo) + (size_t)m0 * DM + h * DH;

#pragma unroll
    for (int j = 0; j < 16; j++) {
        int idx = tid + j * 256;
        int tile = idx >> 10;
        int w = idx & 1023;
        int r = w >> 3, c = w & 7;
        const __nv_bfloat16* gp =
            (tile == 0) ? (Ahi + (size_t)r * DM + c*8) :
            (tile == 1) ? (Alo + (size_t)r * DM + c*8) :
            (tile == 2) ? (g_rfthi + (size_t)r * DH + c*8) :
                          (g_rftlo + (size_t)r * DH + c*8);
        uint32_t sp = sb + tile * TILE2 + (uint32_t)r * PITCH2 + c * 16;
        CP_ASYNC16(sp, gp);
    }
    CP_COMMIT();
    CP_WAIT0();
    __syncthreads();

    uint32_t a_off = (uint32_t)(warp_m*64 + (lane & 15)) * PITCH2 + (lane >> 4) * 16;
    uint32_t b_off = (uint32_t)(warp_n*32 + (lane & 7) + (lane >> 4) * 8) * PITCH2 + ((lane >> 3) & 1) * 16;
    uint32_t sAhi = sb + a_off;
    uint32_t sAlo = sb + TILE2 + a_off;
    uint32_t sBhi = sb + 2*TILE2 + b_off;
    uint32_t sBlo = sb + 3*TILE2 + b_off;

    float acc[4][4][4];
#pragma unroll
    for (int i = 0; i < 4; i++)
#pragma unroll
        for (int j = 0; j < 4; j++)
#pragma unroll
            for (int r = 0; r < 4; r++) acc[i][j][r] = 0.f;

#pragma unroll
    for (int ks = 0; ks < 4; ks++) {
        uint32_t ah[4][4], al[4][4], bh[2][4], bl[2][4];
#pragma unroll
        for (int mi = 0; mi < 4; mi++) {
            LDSM4(ah[mi][0], ah[mi][1], ah[mi][2], ah[mi][3], sAhi + mi*16*PITCH2 + ks*32);
            LDSM4(al[mi][0], al[mi][1], al[mi][2], al[mi][3], sAlo + mi*16*PITCH2 + ks*32);
        }
#pragma unroll
        for (int nb = 0; nb < 2; nb++) {
            LDSM4(bh[nb][0], bh[nb][1], bh[nb][2], bh[nb][3], sBhi + nb*16*PITCH2 + ks*32);
            LDSM4(bl[nb][0], bl[nb][1], bl[nb][2], bl[nb][3], sBlo + nb*16*PITCH2 + ks*32);
        }
#pragma unroll
        for (int mi = 0; mi < 4; mi++)
#pragma unroll
            for (int nb = 0; nb < 2; nb++) {
                MMA16816(acc[mi][nb*2+0], ah[mi], bh[nb][0], bh[nb][1]);
                MMA16816(acc[mi][nb*2+1], ah[mi], bh[nb][2], bh[nb][3]);
                MMA16816(acc[mi][nb*2+0], ah[mi], bl[nb][0], bl[nb][1]);
                MMA16816(acc[mi][nb*2+1], ah[mi], bl[nb][2], bl[nb][3]);
                MMA16816(acc[mi][nb*2+0], al[mi], bh[nb][0], bh[nb][1]);
                MMA16816(acc[mi][nb*2+1], al[mi], bh[nb][2], bh[nb][3]);
            }
    }

    float kst = isq ? 0.f : dec_f(g_kstab);
    int g = lane >> 2, t = lane & 3;
    __nv_bfloat16* Ph = (isq ? g_pqhi : g_pkhi) + (size_t)h * L * MF;
    __nv_bfloat16* Pl = (isq ? g_pqlo : g_pklo) + (size_t)h * L * MF;
#pragma unroll
    for (int mi = 0; mi < 4; mi++) {
#pragma unroll
        for (int half = 0; half < 2; half++) {
            int row = m0 + warp_m*64 + mi*16 + g + half*8;
            float off = isq ? 0.f : (g_hk[(size_t)h * L + row] - kst);
#pragma unroll
            for (int nj = 0; nj < 4; nj++) {
                int col = warp_n*32 + nj*8 + t*2;
                float ox = NC_COEF * (__expf(acc[mi][nj][half*2+0] + off) + KEPS);
                float oy = NC_COEF * (__expf(acc[mi][nj][half*2+1] + off) + KEPS);
                __nv_bfloat162 hv, lv;
                split2(ox, oy, hv, lv);
                *(__nv_bfloat162*)(Ph + (size_t)row * MF + col) = hv;
                *(__nv_bfloat162*)(Pl + (size_t)row * MF + col) = lv;
            }
        }
    }
}

// ---------------- chunk_state via HMMA ----------------
#define CSP_K 272
#define CSP_V 208
#define CS_KH 0
#define CS_KL (CS_KH + 64*CSP_K)
#define CS_VH (CS_KL + 64*CSP_K)
#define CS_VL (CS_VH + 64*CSP_V)
#define CS_TOTAL (CS_VL + 64*CSP_V)

__global__ __launch_bounds__(256) void chunk_state_hmma(){
    extern __shared__ char smc[];
    uint32_t sb = smem_u32(smc);
    int c = blockIdx.x, h = blockIdx.y;
    int tid = threadIdx.x, lane = tid & 31, wid = tid >> 5;
    int warp_m = wid >> 1, warp_n = wid & 1;
    int l0 = c * CHK;

    const __nv_bfloat16* kh = g_pkhi + ((size_t)h * L + l0) * MF;
    const __nv_bfloat16* kl = g_pklo + ((size_t)h * L + l0) * MF;
    for (int i = tid; i < 1024; i += 256) {
        int r = i >> 4, cc = i & 15;
        CP_ASYNC16(sb + CS_KH + (uint32_t)r*CSP_K + cc*16, kh + (size_t)r*MF + cc*8);
        CP_ASYNC16(sb + CS_KL + (uint32_t)r*CSP_K + cc*16, kl + (size_t)r*MF + cc*8);
    }
    for (int i = tid; i < 512; i += 256) {
        int r = i >> 3, cc = i & 7;
        CP_ASYNC16(sb + CS_VH + (uint32_t)r*CSP_V + cc*16, g_vhi + (size_t)(l0+r)*DM + h*DH + cc*8);
        CP_ASYNC16(sb + CS_VL + (uint32_t)r*CSP_V + cc*16, g_vlo + (size_t)(l0+r)*DM + h*DH + cc*8);
    }
    if (tid < 64) {
        uint4 zz = make_uint4(0u,0u,0u,0u);
#pragma unroll
        for (int q = 0; q < 4; q++) {
            *(uint4*)(smc + CS_VH + tid*CSP_V + 128 + q*16) = zz;
            *(uint4*)(smc + CS_VL + tid*CSP_V + 128 + q*16) = zz;
        }
        *((__nv_bfloat16*)(smc + CS_VH + tid*CSP_V) + 64) = __float2bfloat16(1.0f);
    }
    CP_COMMIT(); CP_WAIT0();
    __syncthreads();

    float acc[2][6][4];
#pragma unroll
    for (int i = 0; i < 2; i++)
#pragma unroll
        for (int j = 0; j < 6; j++)
#pragma unroll
            for (int r = 0; r < 4; r++) acc[i][j][r] = 0.f;

#pragma unroll
    for (int ks = 0; ks < 4; ks++) {
        uint32_t ah[2][4], al[2][4], bh[3][4], bl[3][4];
#pragma unroll
        for (int mi = 0; mi < 2; mi++) {
            uint32_t aoff = (uint32_t)(ks*16 + ((lane >> 4) & 1)*8 + (lane & 7)) * CSP_K
                          + (uint32_t)(warp_m*32 + mi*16 + ((lane >> 3) & 1)*8) * 2;
            LDSM4T(ah[mi][0], ah[mi][1], ah[mi][2], ah[mi][3], sb + CS_KH + aoff);
            LDSM4T(al[mi][0], al[mi][1], al[mi][2], al[mi][3], sb + CS_KL + aoff);
        }
#pragma unroll
        for (int nb = 0; nb < 3; nb++) {
            uint32_t boff = (uint32_t)(ks*16 + (lane & 15)) * CSP_V
                          + (uint32_t)(warp_n*48 + nb*16 + (lane >> 4)*8) * 2;
            LDSM4T(bh[nb][0], bh[nb][1], bh[nb][2], bh[nb][3], sb + CS_VH + boff);
            LDSM4T(bl[nb][0], bl[nb][1], bl[nb][2], bl[nb][3], sb + CS_VL + boff);
        }
#pragma unroll
        for (int mi = 0; mi < 2; mi++)
#pragma unroll
            for (int nb = 0; nb < 3; nb++) {
                MMA16816(acc[mi][nb*2+0], ah[mi], bh[nb][0], bh[nb][1]);
                MMA16816(acc[mi][nb*2+1], ah[mi], bh[nb][2], bh[nb][3]);
                MMA16816(acc[mi][nb*2+0], ah[mi], bl[nb][0], bl[nb][1]);
                MMA16816(acc[mi][nb*2+1], ah[mi], bl[nb][2], bl[nb][3]);
                MMA16816(acc[mi][nb*2+0], al[mi], bh[nb][0], bh[nb][1]);
                MMA16816(acc[mi][nb*2+1], al[mi], bh[nb][2], bh[nb][3]);
            }
    }

    int g = lane >> 2, t = lane & 3;
    float* Sdst = g_S + (size_t)(h*NC + c) * MF * DH;
    float* zdst = g_z + (size_t)(h*NC + c) * MF;
#pragma unroll
    for (int mi = 0; mi < 2; mi++) {
#pragma unroll
        for (int half = 0; half < 2; half++) {
            int m = warp_m*32 + mi*16 + g + half*8;
#pragma unroll
            for (int nj = 0; nj < 6; nj++) {
                int col = warp_n*48 + nj*8 + t*2;
                float x = acc[mi][nj][half*2+0];
                float y = acc[mi][nj][half*2+1];
                if (col < 64) {
                    *(float2*)(Sdst + (size_t)m * DH + col) = make_float2(x, y);
                } else if (col == 64) {
                    zdst[m] = x;
                }
            }
        }
    }
}

// ---------------- exclusive prefix over chunks (batched loads, MLP=32) ----------------
__global__ void prefix_scan(){
    int h = blockIdx.y;
    int idx = blockIdx.x * 256 + threadIdx.x;
    if (idx < MF * DH) {
        const float* p = g_S + (size_t)h * NC * MF * DH + idx;
        float v[NC];
#pragma unroll
        for (int c = 0; c < NC; c++) v[c] = p[(size_t)c * MF * DH];
        __nv_bfloat16* ph = g_Shi + (size_t)h * NC * MF * DH + idx;
        __nv_bfloat16* pl = g_Slo + (size_t)h * NC * MF * DH + idx;
        float prev = 0.f;
#pragma unroll
        for (int c = 0; c < NC; c++) {
            __nv_bfloat16 hh = __float2bfloat16(prev);
            ph[(size_t)c * MF * DH] = hh;
            pl[(size_t)c * MF * DH] = __float2bfloat16(prev - __bfloat162float(hh));
            prev += v[c];
        }
    } else if (idx < MF * DH + MF) {
        int m = idx - MF * DH;
        float* p = g_z + (size_t)h * NC * MF + m;
        float v[NC];
#pragma unroll
        for (int c = 0; c < NC; c++) v[c] = p[c * MF];
        float prev = 0.f;
#pragma unroll
        for (int c = 0; c < NC; c++) {
            p[c * MF] = prev;
            prev += v[c];
        }
    }
}

// ---------------- chunk_out via HMMA (split commit groups) ----------------
#define PQ 272
#define PV 144
#define CO_QH 0
#define CO_QL (CO_QH + 64*PQ)
#define CO_KH (CO_QL + 64*PQ)
#define CO_KL (CO_KH + 64*PQ)
#define CO_VH (CO_KL + 64*PQ)
#define CO_VL (CO_VH + 64*PV)
#define CO_SH (CO_VL + 64*PV)
#define CO_SL (CO_SH + 128*PV)
#define CO_AH (CO_SL + 128*PV)
#define CO_AL (CO_AH + 64*PV)
#define CO_ZB (CO_AL + 64*PV)
#define CO_PR (CO_ZB + 512)
#define CO_RS (CO_PR + 64*4*4)
#define CO_TOTAL (CO_RS + 256)

__global__ __launch_bounds__(256) void chunk_out_hmma(){
    extern __shared__ char smc[];
    uint32_t sb = smem_u32(smc);
    int c = blockIdx.x, h = blockIdx.y;
    int tid = threadIdx.x, lane = tid & 31, wid = tid >> 5;
    int warp_m = wid & 1, warp_n = wid >> 1;
    int l0 = c * CHK;

    {
        const __nv_bfloat16* pqh = g_pqhi + ((size_t)h * L + l0) * MF;
        const __nv_bfloat16* pql = g_pqlo + ((size_t)h * L + l0) * MF;
        const __nv_bfloat16* pkh = g_pkhi + ((size_t)h * L + l0) * MF;
        const __nv_bfloat16* pkl = g_pklo + ((size_t)h * L + l0) * MF;
        for (int i = tid; i < 1024; i += 256) {
            int r = i >> 4, cc = i & 15;
            CP_ASYNC16(sb + CO_QH + r*PQ + cc*16, pqh + (size_t)r*MF + cc*8);
            CP_ASYNC16(sb + CO_QL + r*PQ + cc*16, pql + (size_t)r*MF + cc*8);
            CP_ASYNC16(sb + CO_KH + r*PQ + cc*16, pkh + (size_t)r*MF + cc*8);
            CP_ASYNC16(sb + CO_KL + r*PQ + cc*16, pkl + (size_t)r*MF + cc*8);
        }
        CP_COMMIT();
        for (int i = tid; i < 512; i += 256) {
            int r = i >> 3, cc = i & 7;
            CP_ASYNC16(sb + CO_VH + r*PV + cc*16, g_vhi + (size_t)(l0 + r)*DM + h*DH + cc*8);
            CP_ASYNC16(sb + CO_VL + r*PV + cc*16, g_vlo + (size_t)(l0 + r)*DM + h*DH + cc*8);
        }
        const __nv_bfloat16* sh = g_Shi + (size_t)(h*NC + c)*MF*DH;
        const __nv_bfloat16* sl = g_Slo + (size_t)(h*NC + c)*MF*DH;
        for (int i = tid; i < 1024; i += 256) {
            int r = i >> 3, cc = i & 7;
            CP_ASYNC16(sb + CO_SH + r*PV + cc*16, sh + (size_t)r*DH + cc*8);
            CP_ASYNC16(sb + CO_SL + r*PV + cc*16, sl + (size_t)r*DH + cc*8);
        }
        if (tid < 32) CP_ASYNC16(sb + CO_ZB + tid*16, g_z + (size_t)(h*NC + c)*MF + tid*4);
        CP_COMMIT();
        CP_WAIT1();
    }
    __syncthreads();

    uint32_t a_off = (uint32_t)(warp_m*32 + (lane & 15)) * PQ + (lane >> 4) * 16;
    uint32_t b_off = (uint32_t)(warp_n*16 + (lane & 7) + (lane >> 4) * 8) * PQ + ((lane >> 3) & 1) * 16;

    float acc[2][2][4];
#pragma unroll
    for (int i = 0; i < 2; i++)
#pragma unroll
        for (int j = 0; j < 2; j++)
#pragma unroll
            for (int r = 0; r < 4; r++) acc[i][j][r] = 0.f;

#pragma unroll
    for (int ks = 0; ks < 8; ks++) {
        uint32_t ah[2][4], al[2][4], bh[4], bl[4];
#pragma unroll
        for (int mi = 0; mi < 2; mi++) {
            LDSM4(ah[mi][0], ah[mi][1], ah[mi][2], ah[mi][3], sb + CO_QH + a_off + mi*16*PQ + ks*32);
            LDSM4(al[mi][0], al[mi][1], al[mi][2], al[mi][3], sb + CO_QL + a_off + mi*16*PQ + ks*32);
        }
        LDSM4(bh[0], bh[1], bh[2], bh[3], sb + CO_KH + b_off + ks*32);
        LDSM4(bl[0], bl[1], bl[2], bl[3], sb + CO_KL + b_off + ks*32);
#pragma unroll
        for (int mi = 0; mi < 2; mi++) {
            MMA16816(acc[mi][0], ah[mi], bh[0], bh[1]);
            MMA16816(acc[mi][1], ah[mi], bh[2], bh[3]);
            MMA16816(acc[mi][0], ah[mi], bl[0], bl[1]);
            MMA16816(acc[mi][1], ah[mi], bl[2], bl[3]);
            MMA16816(acc[mi][0], al[mi], bh[0], bh[1]);
            MMA16816(acc[mi][1], al[mi], bh[2], bh[3]);
        }
    }
    CP_WAIT0();

    int g = lane >> 2, t = lane & 3;
    float* pr = (float*)(smc + CO_PR);
#pragma unroll
    for (int mi = 0; mi < 2; mi++) {
#pragma unroll
        for (int half = 0; half < 2; half++) {
            int row = warp_m*32 + mi*16 + g + half*8;
            float rsum = 0.f;
#pragma unroll
            for (int nj = 0; nj < 2; nj++) {
                int col = warp_n*16 + nj*8 + t*2;
                float x = (col     <= row) ? acc[mi][nj][half*2+0] : 0.f;
                float y = (col + 1 <= row) ? acc[mi][nj][half*2+1] : 0.f;
                rsum += x + y;
                __nv_bfloat162 hv, lv;
                split2(x, y, hv, lv);
                *(__nv_bfloat162*)(smc + CO_AH + row*PV + col*2) = hv;
                *(__nv_bfloat162*)(smc + CO_AL + row*PV + col*2) = lv;
            }
            rsum += __shfl_xor_sync(0xffffffffu, rsum, 1);
            rsum += __shfl_xor_sync(0xffffffffu, rsum, 2);
            if (t == 0) pr[row*4 + warp_n] = rsum;
        }
    }
    __syncthreads();

    if (tid < 64) {
        float s = pr[tid*4+0] + pr[tid*4+1] + pr[tid*4+2] + pr[tid*4+3];
        const float* zf = (const float*)(smc + CO_ZB);
#pragma unroll 8
        for (int m2 = 0; m2 < 64; m2++) {
            __nv_bfloat162 qh2 = *(const __nv_bfloat162*)(smc + CO_QH + tid*PQ + m2*4);
            __nv_bfloat162 ql2 = *(const __nv_bfloat162*)(smc + CO_QL + tid*PQ + m2*4);
            float2 z2 = *(const float2*)(zf + m2*2);
            s += (__bfloat162float(qh2.x) + __bfloat162float(ql2.x)) * z2.x
               + (__bfloat162float(qh2.y) + __bfloat162float(ql2.y)) * z2.y;
        }
        ((float*)(smc + CO_RS))[tid] = s + DEPS;
    }

    float o[2][2][4];
#pragma unroll
    for (int i = 0; i < 2; i++)
#pragma unroll
        for (int j = 0; j < 2; j++)
#pragma unroll
            for (int r = 0; r < 4; r++) o[i][j][r] = 0.f;

    uint32_t a2_off = (uint32_t)(warp_m*32 + (lane & 15)) * PV + (lane >> 4) * 16;
    uint32_t bt_off = (uint32_t)(lane & 15) * PV + (warp_n*16 + (lane >> 4) * 8) * 2;

#pragma unroll
    for (int ks = 0; ks < 4; ks++) {
        uint32_t ah[2][4], al[2][4], bh[4], bl[4];
#pragma unroll
        for (int mi = 0; mi < 2; mi++) {
            LDSM4(ah[mi][0], ah[mi][1], ah[mi][2], ah[mi][3], sb + CO_AH + a2_off + mi*16*PV + ks*32);
            LDSM4(al[mi][0], al[mi][1], al[mi][2], al[mi][3], sb + CO_AL + a2_off + mi*16*PV + ks*32);
        }
        LDSM4T(bh[0], bh[1], bh[2], bh[3], sb + CO_VH + bt_off + ks*16*PV);
        LDSM4T(bl[0], bl[1], bl[2], bl[3], sb + CO_VL + bt_off + ks*16*PV);
#pragma unroll
        for (int mi = 0; mi < 2; mi++) {
            MMA16816(o[mi][0], ah[mi], bh[0], bh[1]);
            MMA16816(o[mi][1], ah[mi], bh[2], bh[3]);
            MMA16816(o[mi][0], ah[mi], bl[0], bl[1]);
            MMA16816(o[mi][1], ah[mi], bl[2], bl[3]);
            MMA16816(o[mi][0], al[mi], bh[0], bh[1]);
            MMA16816(o[mi][1], al[mi], bh[2], bh[3]);
        }
    }
#pragma unroll
    for (int ks = 0; ks < 8; ks++) {
        uint32_t ah[2][4], al[2][4], bh[4], bl[4];
#pragma unroll
        for (int mi = 0; mi < 2; mi++) {
            LDSM4(ah[mi][0], ah[mi][1], ah[mi][2], ah[mi][3], sb + CO_QH + a_off + mi*16*PQ + ks*32);
            LDSM4(al[mi][0], al[mi][1], al[mi][2], al[mi][3], sb + CO_QL + a_off + mi*16*PQ + ks*32);
        }
        LDSM4T(bh[0], bh[1], bh[2], bh[3], sb + CO_SH + bt_off + ks*16*PV);
        LDSM4T(bl[0], bl[1], bl[2], bl[3], sb + CO_SL + bt_off + ks*16*PV);
#pragma unroll
        for (int mi = 0; mi < 2; mi++) {
            MMA16816(o[mi][0], ah[mi], bh[0], bh[1]);
            MMA16816(o[mi][1], ah[mi], bh[2], bh[3]);
            MMA16816(o[mi][0], ah[mi], bl[0], bl[1]);
            MMA16816(o[mi][1], ah[mi], bl[2], bl[3]);
            MMA16816(o[mi][0], al[mi], bh[0], bh[1]);
            MMA16816(o[mi][1], al[mi], bh[2], bh[3]);
        }
    }
    __syncthreads();

    const float* rs = (const float*)(smc + CO_RS);
#pragma unroll
    for (int mi = 0; mi < 2; mi++) {
#pragma unroll
        for (int half = 0; half < 2; half++) {
            int row = warp_m*32 + mi*16 + g + half*8;
            float inv = 1.0f / rs[row];
#pragma unroll
            for (int nj = 0; nj < 2; nj++) {
                int col = warp_n*16 + nj*8 + t*2;
                float ox = o[mi][nj][half*2+0] * inv;
                float oy = o[mi][nj][half*2+1] * inv;
                __nv_bfloat162 hv, lv;
                split2(ox, oy, hv, lv);
                size_t off = (size_t)(l0 + row) * DM + h*DH + col;
                *(__nv_bfloat162*)(g_bhi_ctx + off) = hv;
                *(__nv_bfloat162*)(g_blo_ctx + off) = lv;
            }
        }
    }
}

// ---------------- launcher ----------------
extern "C" void kernel_launch(void* const* d_in, const int* in_sizes, int n_in,
                              void* d_out, int out_size)
{
    const float* query = (const float*)d_in[0];
    const float* key_i = (const float*)d_in[1];
    const float* value = (const float*)d_in[2];
    const float* Wq = (const float*)d_in[3];
    const float* bq = (const float*)d_in[4];
    const float* Wk = (const float*)d_in[5];
    const float* bk = (const float*)d_in[6];
    const float* Wv = (const float*)d_in[7];
    const float* bv = (const float*)d_in[8];
    const float* Wo = (const float*)d_in[9];
    const float* bo = (const float*)d_in[10];
    const float* rf = (const float*)d_in[11];
    float* out = (float*)d_out;

    void* p;
    cudaGetSymbolAddress(&p, g_bhi_w);   __nv_bfloat16* bhi_w  = (__nv_bfloat16*)p;
    cudaGetSymbolAddress(&p, g_blo_w);   __nv_bfloat16* blo_w  = (__nv_bfloat16*)p;
    cudaGetSymbolAddress(&p, g_bhi_ctx); __nv_bfloat16* bhi_c  = (__nv_bfloat16*)p;
    cudaGetSymbolAddress(&p, g_blo_ctx); __nv_bfloat16* blo_c  = (__nv_bfloat16*)p;
    cudaGetSymbolAddress(&p, g_qhi);     __nv_bfloat16* qhi    = (__nv_bfloat16*)p;
    cudaGetSymbolAddress(&p, g_qlo);     __nv_bfloat16* qlo    = (__nv_bfloat16*)p;
    cudaGetSymbolAddress(&p, g_khi);     __nv_bfloat16* khi    = (__nv_bfloat16*)p;
    cudaGetSymbolAddress(&p, g_klo);     __nv_bfloat16* klo    = (__nv_bfloat16*)p;
    cudaGetSymbolAddress(&p, g_vhi);     __nv_bfloat16* vhi    = (__nv_bfloat16*)p;
    cudaGetSymbolAddress(&p, g_vlo);     __nv_bfloat16* vlo    = (__nv_bfloat16*)p;

    // one-time side stream + events (created on the first, non-captured call)
    static cudaStream_t s1 = nullptr;
    static cudaEvent_t ev_fork = nullptr, ev_join = nullptr;
    if (!s1) {
        cudaStreamCreateWithFlags(&s1, cudaStreamNonBlocking);
        cudaEventCreateWithFlags(&ev_fork, cudaEventDisableTiming);
        cudaEventCreateWithFlags(&ev_join, cudaEventDisableTiming);
    }

    CV cv;
    cv.src[0]=Wq; cv.hi[0]=bhi_w;          cv.lo[0]=blo_w;          cv.n[0]=DM*DM;
    cv.src[1]=Wk; cv.hi[1]=bhi_w+DM*DM;    cv.lo[1]=blo_w+DM*DM;    cv.n[1]=DM*DM;
    cv.src[2]=Wv; cv.hi[2]=bhi_w+2*DM*DM;  cv.lo[2]=blo_w+2*DM*DM;  cv.n[2]=DM*DM;
    cv.src[3]=Wo; cv.hi[3]=bhi_w+3*DM*DM;  cv.lo[3]=blo_w+3*DM*DM;  cv.n[3]=DM*DM;
    cv.cnt = 4;
    convert_split<<<dim3((DM*DM)/1024, 5), 256>>>(cv, rf);

    cudaFuncSetAttribute((hmma_gemm<2,true>),  cudaFuncAttributeMaxDynamicSharedMemorySize, HG_SMEM2);
    cudaFuncSetAttribute((hmma_gemm<1,false>), cudaFuncAttributeMaxDynamicSharedMemorySize, HG_SMEM1);
    cudaFuncSetAttribute(rf_proj_hmma, cudaFuncAttributeMaxDynamicSharedMemorySize, RF_SMEM);
    cudaFuncSetAttribute(chunk_state_hmma, cudaFuncAttributeMaxDynamicSharedMemorySize, CS_TOTAL);
    cudaFuncSetAttribute(chunk_out_hmma, cudaFuncAttributeMaxDynamicSharedMemorySize, CO_TOTAL);

    // QKV projections (MB=2, A from fp32 inputs, hk fused into z==1 epilogue)
    MMArgs mq;
    mq.Af[0]=query; mq.Ahi[0]=nullptr; mq.Alo[0]=nullptr; mq.Whi[0]=bhi_w;        mq.Wlo[0]=blo_w;        mq.bias[0]=bq; mq.C[0]=nullptr; mq.Chi[0]=qhi; mq.Clo[0]=qlo; mq.alpha[0]=SCALE_QK;
    mq.Af[1]=key_i; mq.Ahi[1]=nullptr; mq.Alo[1]=nullptr; mq.Whi[1]=bhi_w+DM*DM;  mq.Wlo[1]=blo_w+DM*DM;  mq.bias[1]=bk; mq.C[1]=nullptr; mq.Chi[1]=khi; mq.Clo[1]=klo; mq.alpha[1]=SCALE_QK;
    mq.Af[2]=value; mq.Ahi[2]=nullptr; mq.Alo[2]=nullptr; mq.Whi[2]=bhi_w+2*DM*DM;mq.Wlo[2]=blo_w+2*DM*DM;mq.bias[2]=bv; mq.C[2]=nullptr; mq.Chi[2]=vhi; mq.Clo[2]=vlo; mq.alpha[2]=1.0f;
    hmma_gemm<2,true><<<dim3(DM/128, L/64, 3), 256, HG_SMEM2>>>(mq, 1);

    // fork: q-half of rf_proj on side stream (only consumed by chunk_out)
    cudaEventRecord(ev_fork, 0);
    cudaStreamWaitEvent(s1, ev_fork, 0);
    rf_proj_hmma<<<dim3(1, L/128, 8), 256, RF_SMEM, s1>>>(0);
    cudaEventRecord(ev_join, s1);

    // main stream: k-half -> chunk_state -> prefix
    rf_proj_hmma<<<dim3(1, L/128, 8), 256, RF_SMEM>>>(8);
    chunk_state_hmma<<<dim3(NC, NH), 256, CS_TOTAL>>>();
    prefix_scan<<<dim3((MF*DH + MF + 255)/256, NH), 256>>>();

    // join before chunk_out (needs q')
    cudaStreamWaitEvent(0, ev_join, 0);
    chunk_out_hmma<<<dim3(NC, NH), 256, CO_TOTAL>>>();

    // output projection (MB=1, A from bf16 ctx)
    MMArgs mo;
    mo.Af[0]=nullptr; mo.Ahi[0]=bhi_c; mo.Alo[0]=blo_c; mo.Whi[0]=bhi_w+3*DM*DM; mo.Wlo[0]=blo_w+3*DM*DM; mo.bias[0]=bo; mo.C[0]=out; mo.Chi[0]=nullptr; mo.Clo[0]=nullptr; mo.alpha[0]=1.0f;
    mo.Af[1]=nullptr; mo.Ahi[1]=mo.Ahi[0]; mo.Alo[1]=mo.Alo[0]; mo.Whi[1]=mo.Whi[0]; mo.Wlo[1]=mo.Wlo[0]; mo.bias[1]=bo; mo.C[1]=out; mo.Chi[1]=nullptr; mo.Clo[1]=nullptr; mo.alpha[1]=1.0f;
    mo.Af[2]=nullptr; mo.Ahi[2]=mo.Ahi[0]; mo.Alo[2]=mo.Alo[0]; mo.Whi[2]=mo.Whi[0]; mo.Wlo[2]=mo.Wlo[0]; mo.bias[2]=bo; mo.C[2]=out; mo.Chi[2]=nullptr; mo.Clo[2]=nullptr; mo.alpha[2]=1.0f;
    hmma_gemm<1,false><<<dim3(DM/128, L/32, 1), 256, HG_SMEM1>>>(mo, 0);
}